// round 1
// baseline (speedup 1.0000x reference)
#include <cuda_runtime.h>
#include <math.h>

#define BATCH 2
#define SEQ   2048
#define MODEL 2048
#define NH    32
#define NKV   8
#define HD    64
#define ROWS  (BATCH*SEQ)   // 4096

// ---------------- scratch (static device arrays; no allocation allowed) ----
__device__ float g_Q[(size_t)ROWS * NH  * HD];   // 32 MB
__device__ float g_K[(size_t)ROWS * NKV * HD];   // 8 MB
__device__ float g_V[(size_t)ROWS * NKV * HD];   // 8 MB
__device__ float g_Y[(size_t)ROWS * NH  * HD];   // 32 MB

// ---------------------------------------------------------------------------
// SGEMM: C[M,N] = A[M,K] @ B[K,N], row-major. M%128==0, N%128==0, K%8==0.
// 128x128 block tile, BK=8, 256 threads, 8x8 micro-tile as 2x2 chunks of 4x4.
// ---------------------------------------------------------------------------
__global__ __launch_bounds__(256)
void sgemm128(const float* __restrict__ A, const float* __restrict__ B,
              float* __restrict__ C, int M, int N, int K) {
    __shared__ float As[8][132];   // [k][m], stride 132 -> conflict-free STS/LDS
    __shared__ float Bs[8][128];   // [k][n]

    const int tid = threadIdx.x;
    const int tx  = tid & 15;      // N micro index
    const int ty  = tid >> 4;      // M micro index
    const int bm  = blockIdx.y * 128;
    const int bn  = blockIdx.x * 128;

    float acc[2][2][4][4];
    #pragma unroll
    for (int a = 0; a < 2; a++)
        #pragma unroll
        for (int b = 0; b < 2; b++)
            #pragma unroll
            for (int i = 0; i < 4; i++)
                #pragma unroll
                for (int j = 0; j < 4; j++) acc[a][b][i][j] = 0.f;

    const int arow = tid >> 1;          // 0..127
    const int acol = (tid & 1) * 4;     // 0 / 4
    const int brow = tid >> 5;          // 0..7
    const int bcol = (tid & 31) * 4;    // 0..124

    const float* Ap = A + (size_t)(bm + arow) * K + acol;
    const float* Bp = B + (size_t)brow * N + bn + bcol;

    float4 av = *(const float4*)Ap;
    float4 bv = *(const float4*)Bp;

    const int ntiles = K >> 3;
    for (int t = 0; t < ntiles; t++) {
        As[acol + 0][arow] = av.x;
        As[acol + 1][arow] = av.y;
        As[acol + 2][arow] = av.z;
        As[acol + 3][arow] = av.w;
        *(float4*)&Bs[brow][bcol] = bv;
        __syncthreads();

        if (t + 1 < ntiles) {           // prefetch next tile under compute
            Ap += 8;
            Bp += (size_t)8 * N;
            av = *(const float4*)Ap;
            bv = *(const float4*)Bp;
        }

        #pragma unroll
        for (int kk = 0; kk < 8; kk++) {
            float a0[4], a1[4], b0[4], b1[4];
            *(float4*)a0 = *(const float4*)&As[kk][ty * 4];
            *(float4*)a1 = *(const float4*)&As[kk][64 + ty * 4];
            *(float4*)b0 = *(const float4*)&Bs[kk][tx * 4];
            *(float4*)b1 = *(const float4*)&Bs[kk][64 + tx * 4];
            #pragma unroll
            for (int i = 0; i < 4; i++)
                #pragma unroll
                for (int j = 0; j < 4; j++) {
                    acc[0][0][i][j] += a0[i] * b0[j];
                    acc[0][1][i][j] += a0[i] * b1[j];
                    acc[1][0][i][j] += a1[i] * b0[j];
                    acc[1][1][i][j] += a1[i] * b1[j];
                }
        }
        __syncthreads();
    }

    #pragma unroll
    for (int ri = 0; ri < 2; ri++)
        #pragma unroll
        for (int i = 0; i < 4; i++) {
            int row = bm + ri * 64 + ty * 4 + i;
            #pragma unroll
            for (int ci = 0; ci < 2; ci++) {
                float4 v = make_float4(acc[ri][ci][i][0], acc[ri][ci][i][1],
                                       acc[ri][ci][i][2], acc[ri][ci][i][3]);
                *(float4*)&C[(size_t)row * N + bn + ci * 64 + tx * 4] = v;
            }
        }
}

// ---------------------------------------------------------------------------
// RoPE in-place on [ROWS, nheads*64]. One thread per (row, head, d<32) pair.
// Angle computed in double so our error << reference's own fp32 rounding.
// ---------------------------------------------------------------------------
__global__ __launch_bounds__(256)
void rope_kernel(float* __restrict__ T, int nheads, int total) {
    int i = blockIdx.x * blockDim.x + threadIdx.x;
    if (i >= total) return;
    int d   = i & 31;
    int h   = (i >> 5) % nheads;
    int row = i / (32 * nheads);
    int s   = row % SEQ;

    // inv_freq = 10000^(-2d/64) = 2^(-d * log2(10000) / 32)
    double inv = exp2(-(double)d * (13.287712379549448882 / 32.0));
    double ang = (double)s * inv;
    double sd, cd;
    sincos(ang, &sd, &cd);
    float c  = (float)cd;
    float sn = (float)sd;

    float* p = T + (size_t)row * (nheads * 64) + h * 64 + d;
    float q0 = p[0];
    float q1 = p[32];
    p[0]  = q0 * c - q1 * sn;
    p[32] = q1 * c + q0 * sn;
}

// ---------------------------------------------------------------------------
// Flash attention, fp32. Q-tile 128 rows, KV-tile 64, head_dim 64, causal.
// 256 threads: thread (tx,ty) owns S rows {ty*4+i, 64+ty*4+i}, cols tx*4+j,
// and O rows same, O cols tx*4+j. Row reductions live inside 16-lane groups.
// ---------------------------------------------------------------------------
__global__ __launch_bounds__(256)
void flashattn(const float* __restrict__ Q, const float* __restrict__ K,
               const float* __restrict__ V, float* __restrict__ Y) {
    extern __shared__ float sm[];
    float* Qt = sm;                  // [64][132]  d-major: Qt[d*132 + r], r<128
    float* Kt = Qt + 64 * 132;       // [64][68]   d-major: Kt[d*68  + c], c<64
    float* Vs = Kt + 64 * 68;        // [64][68]   c-major: Vs[c*68  + d]
    float* Ps = Vs + 64 * 68;        // [128][68]  r-major: Ps[r*68  + c]

    const int tid = threadIdx.x;
    const int tx  = tid & 15;
    const int ty  = tid >> 4;
    const int qt  = blockIdx.x;
    const int h   = blockIdx.y;
    const int b   = blockIdx.z;
    const int kvh = h >> 2;          // 4 Q-heads per KV head
    const float scale = 0.125f;      // 1/sqrt(64)

    // load Q tile once (scale folded in)
    {
        const float* Qg = Q + ((size_t)(b * SEQ + qt * 128)) * (NH * HD) + h * HD;
        for (int t = tid; t < 128 * 16; t += 256) {
            int r  = t >> 4;
            int d4 = (t & 15) * 4;
            float4 v = *(const float4*)(Qg + (size_t)r * (NH * HD) + d4);
            Qt[(d4 + 0) * 132 + r] = v.x * scale;
            Qt[(d4 + 1) * 132 + r] = v.y * scale;
            Qt[(d4 + 2) * 132 + r] = v.z * scale;
            Qt[(d4 + 3) * 132 + r] = v.w * scale;
        }
    }

    float m[2][4], l[2][4], o[2][4][4];
    #pragma unroll
    for (int ri = 0; ri < 2; ri++)
        #pragma unroll
        for (int i = 0; i < 4; i++) {
            m[ri][i] = -INFINITY;
            l[ri][i] = 0.f;
            #pragma unroll
            for (int j = 0; j < 4; j++) o[ri][i][j] = 0.f;
        }

    const int njt = 2 * qt + 2;      // tiles 0 .. 2qt+1 (causal skip)
    for (int jt = 0; jt < njt; jt++) {
        __syncthreads();             // prior P@V reads done before K/V/Ps rewrite

        // load K (transposed) and V tiles
        const float* Kg = K + ((size_t)(b * SEQ + jt * 64)) * (NKV * HD) + kvh * HD;
        const float* Vg = V + ((size_t)(b * SEQ + jt * 64)) * (NKV * HD) + kvh * HD;
        for (int t = tid; t < 64 * 16; t += 256) {
            int c  = t >> 4;
            int d4 = (t & 15) * 4;
            float4 kv = *(const float4*)(Kg + (size_t)c * (NKV * HD) + d4);
            Kt[(d4 + 0) * 68 + c] = kv.x;
            Kt[(d4 + 1) * 68 + c] = kv.y;
            Kt[(d4 + 2) * 68 + c] = kv.z;
            Kt[(d4 + 3) * 68 + c] = kv.w;
            float4 vv = *(const float4*)(Vg + (size_t)c * (NKV * HD) + d4);
            *(float4*)&Vs[c * 68 + d4] = vv;
        }
        __syncthreads();

        // S = (Q*scale) @ K^T   (128 x 64 tile)
        float s[2][4][4];
        #pragma unroll
        for (int ri = 0; ri < 2; ri++)
            #pragma unroll
            for (int i = 0; i < 4; i++)
                #pragma unroll
                for (int j = 0; j < 4; j++) s[ri][i][j] = 0.f;

        #pragma unroll 8
        for (int d = 0; d < 64; d++) {
            float a0[4], a1[4], bb[4];
            *(float4*)a0 = *(const float4*)&Qt[d * 132 + ty * 4];
            *(float4*)a1 = *(const float4*)&Qt[d * 132 + 64 + ty * 4];
            *(float4*)bb = *(const float4*)&Kt[d * 68 + tx * 4];
            #pragma unroll
            for (int i = 0; i < 4; i++)
                #pragma unroll
                for (int j = 0; j < 4; j++) {
                    s[0][i][j] += a0[i] * bb[j];
                    s[1][i][j] += a1[i] * bb[j];
                }
        }

        // causal mask (only the last two tiles can straddle the diagonal)
        if (jt * 64 + 63 > qt * 128) {
            #pragma unroll
            for (int ri = 0; ri < 2; ri++)
                #pragma unroll
                for (int i = 0; i < 4; i++) {
                    int qr = qt * 128 + ri * 64 + ty * 4 + i;
                    #pragma unroll
                    for (int j = 0; j < 4; j++) {
                        int qc = jt * 64 + tx * 4 + j;
                        if (qc > qr) s[ri][i][j] = -INFINITY;
                    }
                }
        }

        // online softmax update + stash P in smem
        #pragma unroll
        for (int ri = 0; ri < 2; ri++)
            #pragma unroll
            for (int i = 0; i < 4; i++) {
                float rm = fmaxf(fmaxf(s[ri][i][0], s[ri][i][1]),
                                 fmaxf(s[ri][i][2], s[ri][i][3]));
                rm = fmaxf(rm, __shfl_xor_sync(0xffffffffu, rm, 1));
                rm = fmaxf(rm, __shfl_xor_sync(0xffffffffu, rm, 2));
                rm = fmaxf(rm, __shfl_xor_sync(0xffffffffu, rm, 4));
                rm = fmaxf(rm, __shfl_xor_sync(0xffffffffu, rm, 8));

                float mo = m[ri][i];
                float mn = fmaxf(mo, rm);
                float f  = __expf(mo - mn);        // first tile: exp(-inf)=0
                float rs = 0.f;
                #pragma unroll
                for (int j = 0; j < 4; j++) {
                    float p = __expf(s[ri][i][j] - mn);
                    s[ri][i][j] = p;
                    rs += p;
                }
                rs += __shfl_xor_sync(0xffffffffu, rs, 1);
                rs += __shfl_xor_sync(0xffffffffu, rs, 2);
                rs += __shfl_xor_sync(0xffffffffu, rs, 4);
                rs += __shfl_xor_sync(0xffffffffu, rs, 8);

                l[ri][i] = l[ri][i] * f + rs;
                m[ri][i] = mn;
                #pragma unroll
                for (int j = 0; j < 4; j++) o[ri][i][j] *= f;

                *(float4*)&Ps[(ri * 64 + ty * 4 + i) * 68 + tx * 4] =
                    make_float4(s[ri][i][0], s[ri][i][1], s[ri][i][2], s[ri][i][3]);
            }
        __syncthreads();

        // O += P @ V
        #pragma unroll 8
        for (int c = 0; c < 64; c++) {
            float bb[4];
            *(float4*)bb = *(const float4*)&Vs[c * 68 + tx * 4];
            #pragma unroll
            for (int ri = 0; ri < 2; ri++)
                #pragma unroll
                for (int i = 0; i < 4; i++) {
                    float p = Ps[(ri * 64 + ty * 4 + i) * 68 + c];
                    #pragma unroll
                    for (int j = 0; j < 4; j++) o[ri][i][j] += p * bb[j];
                }
        }
    }

    // epilogue: normalize and write Y[b, s, h*64 + d]
    #pragma unroll
    for (int ri = 0; ri < 2; ri++)
        #pragma unroll
        for (int i = 0; i < 4; i++) {
            float inv = 1.f / l[ri][i];
            int row = b * SEQ + qt * 128 + ri * 64 + ty * 4 + i;
            float4 out = make_float4(o[ri][i][0] * inv, o[ri][i][1] * inv,
                                     o[ri][i][2] * inv, o[ri][i][3] * inv);
            *(float4*)&Y[(size_t)row * (NH * HD) + h * HD + tx * 4] = out;
        }
}

// ---------------------------------------------------------------------------
extern "C" void kernel_launch(void* const* d_in, const int* in_sizes, int n_in,
                              void* d_out, int out_size) {
    const float* x  = (const float*)d_in[0];
    const float* Wq = (const float*)d_in[1];
    const float* Wk = (const float*)d_in[2];
    const float* Wv = (const float*)d_in[3];
    const float* Wo = (const float*)d_in[4];
    float* out = (float*)d_out;

    float *Qp, *Kp, *Vp, *Yp;
    cudaGetSymbolAddress((void**)&Qp, g_Q);
    cudaGetSymbolAddress((void**)&Kp, g_K);
    cudaGetSymbolAddress((void**)&Vp, g_V);
    cudaGetSymbolAddress((void**)&Yp, g_Y);

    dim3 blk(256);

    // QKV projections
    sgemm128<<<dim3((NH * HD) / 128, ROWS / 128), blk>>>(x, Wq, Qp, ROWS, NH * HD, MODEL);
    sgemm128<<<dim3((NKV * HD) / 128, ROWS / 128), blk>>>(x, Wk, Kp, ROWS, NKV * HD, MODEL);
    sgemm128<<<dim3((NKV * HD) / 128, ROWS / 128), blk>>>(x, Wv, Vp, ROWS, NKV * HD, MODEL);

    // RoPE on Q and K
    int totq = ROWS * NH * 32;
    int totk = ROWS * NKV * 32;
    rope_kernel<<<(totq + 255) / 256, blk>>>(Qp, NH, totq);
    rope_kernel<<<(totk + 255) / 256, blk>>>(Kp, NKV, totk);

    // flash attention
    const int SMEM = (64 * 132 + 64 * 68 + 64 * 68 + 128 * 68) * 4;  // 103424 B
    cudaFuncSetAttribute(flashattn, cudaFuncAttributeMaxDynamicSharedMemorySize, SMEM);
    flashattn<<<dim3(SEQ / 128, NH, BATCH), blk, SMEM>>>(Qp, Kp, Vp, Yp);

    // output projection
    sgemm128<<<dim3(MODEL / 128, ROWS / 128), blk>>>(Yp, Wo, out, ROWS, MODEL, MODEL);
}

// round 2
// speedup vs baseline: 1.1503x; 1.1503x over previous
#include <cuda_runtime.h>
#include <math.h>

#define BATCH 2
#define SEQ   2048
#define MODEL 2048
#define NH    32
#define NKV   8
#define HD    64
#define ROWS  (BATCH*SEQ)   // 4096

typedef unsigned long long u64;

// ---------------- packed fp32x2 helpers (Blackwell FFMA2 path) -------------
__device__ __forceinline__ u64 pk2(float lo, float hi) {
    u64 r; asm("mov.b64 %0, {%1, %2};" : "=l"(r) : "f"(lo), "f"(hi)); return r;
}
__device__ __forceinline__ float2 upk2(u64 v) {
    float2 r; asm("mov.b64 {%0, %1}, %2;" : "=f"(r.x), "=f"(r.y) : "l"(v)); return r;
}
__device__ __forceinline__ void fma2(u64& d, u64 a, u64 b) {
    asm("fma.rn.f32x2 %0, %1, %2, %0;" : "+l"(d) : "l"(a), "l"(b));
}
__device__ __forceinline__ void mul2(u64& d, u64 a) {
    asm("mul.rn.f32x2 %0, %0, %1;" : "+l"(d) : "l"(a));
}

// ---------------- scratch (static device arrays; no allocation allowed) ----
__device__ float g_Q[(size_t)ROWS * NH  * HD];   // 32 MB
__device__ float g_K[(size_t)ROWS * NKV * HD];   // 8 MB
__device__ float g_V[(size_t)ROWS * NKV * HD];   // 8 MB
__device__ float g_Y[(size_t)ROWS * NH  * HD];   // 32 MB
__device__ float g_cs[(size_t)SEQ * 32 * 2];     // 512 KB cos/sin table

// ---------------------------------------------------------------------------
// RoPE table: 65536 threads do the fp64 trig ONCE (was 4.2M double sincos).
// ---------------------------------------------------------------------------
__global__ __launch_bounds__(256)
void rope_table() {
    int i = blockIdx.x * 256 + threadIdx.x;
    if (i >= SEQ * 32) return;
    int d = i & 31;
    int s = i >> 5;
    // inv_freq = 10000^(-d/32) = 2^(-d * log2(10000) / 32)
    double inv = exp2(-(double)d * (13.287712379549448882 / 32.0));
    double ang = (double)s * inv;
    double sd, cd;
    sincos(ang, &sd, &cd);
    g_cs[2 * i + 0] = (float)cd;
    g_cs[2 * i + 1] = (float)sd;
}

// ---------------------------------------------------------------------------
// RoPE in-place on [ROWS, nheads*64], reading the (cos,sin) table.
// ---------------------------------------------------------------------------
__global__ __launch_bounds__(256)
void rope_kernel(float* __restrict__ T, int nheads, int total) {
    int i = blockIdx.x * blockDim.x + threadIdx.x;
    if (i >= total) return;
    int d   = i & 31;
    int h   = (i >> 5) % nheads;
    int row = i / (32 * nheads);
    int s   = row % SEQ;

    float2 cs = *(const float2*)&g_cs[2 * (s * 32 + d)];

    float* p = T + (size_t)row * (nheads * 64) + h * 64 + d;
    float q0 = p[0];
    float q1 = p[32];
    p[0]  = q0 * cs.x - q1 * cs.y;
    p[32] = q1 * cs.x + q0 * cs.y;
}

// ---------------------------------------------------------------------------
// SGEMM: C[M,N] = A[M,K] @ B[K,N], row-major. 128x128 tile, BK=8, 256 thr,
// 8x8 micro-tile, accumulators packed as fp32x2 pairs (FFMA2).
// ---------------------------------------------------------------------------
__global__ __launch_bounds__(256)
void sgemm128(const float* __restrict__ A, const float* __restrict__ B,
              float* __restrict__ C, int M, int N, int K) {
    __shared__ float As[8][132];   // [k][m]
    __shared__ float Bs[8][128];   // [k][n]

    const int tid = threadIdx.x;
    const int tx  = tid & 15;
    const int ty  = tid >> 4;
    const int bm  = blockIdx.y * 128;
    const int bn  = blockIdx.x * 128;

    u64 acc[2][2][4][2];           // [mhalf][nhalf][i][jpair]
    #pragma unroll
    for (int a = 0; a < 2; a++)
        #pragma unroll
        for (int b = 0; b < 2; b++)
            #pragma unroll
            for (int i = 0; i < 4; i++) {
                acc[a][b][i][0] = 0ull; acc[a][b][i][1] = 0ull;
            }

    const int arow = tid >> 1;
    const int acol = (tid & 1) * 4;
    const int brow = tid >> 5;
    const int bcol = (tid & 31) * 4;

    const float* Ap = A + (size_t)(bm + arow) * K + acol;
    const float* Bp = B + (size_t)brow * N + bn + bcol;

    float4 av = *(const float4*)Ap;
    float4 bv = *(const float4*)Bp;

    const int ntiles = K >> 3;
    for (int t = 0; t < ntiles; t++) {
        As[acol + 0][arow] = av.x;
        As[acol + 1][arow] = av.y;
        As[acol + 2][arow] = av.z;
        As[acol + 3][arow] = av.w;
        *(float4*)&Bs[brow][bcol] = bv;
        __syncthreads();

        if (t + 1 < ntiles) {
            Ap += 8;
            Bp += (size_t)8 * N;
            av = *(const float4*)Ap;
            bv = *(const float4*)Bp;
        }

        #pragma unroll
        for (int kk = 0; kk < 8; kk++) {
            float a0[4], a1[4];
            *(float4*)a0 = *(const float4*)&As[kk][ty * 4];
            *(float4*)a1 = *(const float4*)&As[kk][64 + ty * 4];
            const u64* b0p = (const u64*)&Bs[kk][tx * 4];
            const u64* b1p = (const u64*)&Bs[kk][64 + tx * 4];
            u64 B00 = b0p[0], B01 = b0p[1];
            u64 B10 = b1p[0], B11 = b1p[1];
            #pragma unroll
            for (int i = 0; i < 4; i++) {
                u64 A0 = pk2(a0[i], a0[i]);
                u64 A1 = pk2(a1[i], a1[i]);
                fma2(acc[0][0][i][0], A0, B00);
                fma2(acc[0][0][i][1], A0, B01);
                fma2(acc[0][1][i][0], A0, B10);
                fma2(acc[0][1][i][1], A0, B11);
                fma2(acc[1][0][i][0], A1, B00);
                fma2(acc[1][0][i][1], A1, B01);
                fma2(acc[1][1][i][0], A1, B10);
                fma2(acc[1][1][i][1], A1, B11);
            }
        }
        __syncthreads();
    }

    #pragma unroll
    for (int ri = 0; ri < 2; ri++)
        #pragma unroll
        for (int i = 0; i < 4; i++) {
            int row = bm + ri * 64 + ty * 4 + i;
            #pragma unroll
            for (int ci = 0; ci < 2; ci++) {
                float2 p0 = upk2(acc[ri][ci][i][0]);
                float2 p1 = upk2(acc[ri][ci][i][1]);
                float4 v = make_float4(p0.x, p0.y, p1.x, p1.y);
                *(float4*)&C[(size_t)row * N + bn + ci * 64 + tx * 4] = v;
            }
        }
}

// ---------------------------------------------------------------------------
// Flash attention, fp32 with FFMA2-packed GEMM loops. Q-tile 128, KV-tile 64.
// ---------------------------------------------------------------------------
__global__ __launch_bounds__(256)
void flashattn(const float* __restrict__ Q, const float* __restrict__ K,
               const float* __restrict__ V, float* __restrict__ Y) {
    extern __shared__ float sm[];
    float* Qt = sm;                  // [64][132]  Qt[d*132 + r]
    float* Kt = Qt + 64 * 132;       // [64][68]   Kt[d*68  + c]
    float* Vs = Kt + 64 * 68;        // [64][68]   Vs[c*68  + d]
    float* Ps = Vs + 64 * 68;        // [128][68]  Ps[r*68  + c]

    const int tid = threadIdx.x;
    const int tx  = tid & 15;
    const int ty  = tid >> 4;
    const int qt  = blockIdx.x;
    const int h   = blockIdx.y;
    const int b   = blockIdx.z;
    const int kvh = h >> 2;
    const float scale = 0.125f;

    {
        const float* Qg = Q + ((size_t)(b * SEQ + qt * 128)) * (NH * HD) + h * HD;
        for (int t = tid; t < 128 * 16; t += 256) {
            int r  = t >> 4;
            int d4 = (t & 15) * 4;
            float4 v = *(const float4*)(Qg + (size_t)r * (NH * HD) + d4);
            Qt[(d4 + 0) * 132 + r] = v.x * scale;
            Qt[(d4 + 1) * 132 + r] = v.y * scale;
            Qt[(d4 + 2) * 132 + r] = v.z * scale;
            Qt[(d4 + 3) * 132 + r] = v.w * scale;
        }
    }

    float m[2][4], l[2][4];
    u64 o2[2][4][2];                 // O accumulators, j-paired fp32x2
    #pragma unroll
    for (int ri = 0; ri < 2; ri++)
        #pragma unroll
        for (int i = 0; i < 4; i++) {
            m[ri][i] = -INFINITY;
            l[ri][i] = 0.f;
            o2[ri][i][0] = 0ull; o2[ri][i][1] = 0ull;
        }

    const int njt = 2 * qt + 2;
    for (int jt = 0; jt < njt; jt++) {
        __syncthreads();

        const float* Kg = K + ((size_t)(b * SEQ + jt * 64)) * (NKV * HD) + kvh * HD;
        const float* Vg = V + ((size_t)(b * SEQ + jt * 64)) * (NKV * HD) + kvh * HD;
        for (int t = tid; t < 64 * 16; t += 256) {
            int c  = t >> 4;
            int d4 = (t & 15) * 4;
            float4 kv = *(const float4*)(Kg + (size_t)c * (NKV * HD) + d4);
            Kt[(d4 + 0) * 68 + c] = kv.x;
            Kt[(d4 + 1) * 68 + c] = kv.y;
            Kt[(d4 + 2) * 68 + c] = kv.z;
            Kt[(d4 + 3) * 68 + c] = kv.w;
            float4 vv = *(const float4*)(Vg + (size_t)c * (NKV * HD) + d4);
            *(float4*)&Vs[c * 68 + d4] = vv;
        }
        __syncthreads();

        // S = (Q*scale) @ K^T, packed
        u64 s2[2][4][2];
        #pragma unroll
        for (int ri = 0; ri < 2; ri++)
            #pragma unroll
            for (int i = 0; i < 4; i++) { s2[ri][i][0] = 0ull; s2[ri][i][1] = 0ull; }

        #pragma unroll 4
        for (int d = 0; d < 64; d++) {
            float a0[4], a1[4];
            *(float4*)a0 = *(const float4*)&Qt[d * 132 + ty * 4];
            *(float4*)a1 = *(const float4*)&Qt[d * 132 + 64 + ty * 4];
            const u64* bp = (const u64*)&Kt[d * 68 + tx * 4];
            u64 B0 = bp[0], B1 = bp[1];
            #pragma unroll
            for (int i = 0; i < 4; i++) {
                u64 A0 = pk2(a0[i], a0[i]);
                u64 A1 = pk2(a1[i], a1[i]);
                fma2(s2[0][i][0], A0, B0);
                fma2(s2[0][i][1], A0, B1);
                fma2(s2[1][i][0], A1, B0);
                fma2(s2[1][i][1], A1, B1);
            }
        }

        // unpack, mask, online softmax, stash P
        #pragma unroll
        for (int ri = 0; ri < 2; ri++)
            #pragma unroll
            for (int i = 0; i < 4; i++) {
                float2 u0 = upk2(s2[ri][i][0]);
                float2 u1 = upk2(s2[ri][i][1]);
                float s0 = u0.x, s1 = u0.y, s2v = u1.x, s3 = u1.y;

                if (jt * 64 + 63 > qt * 128) {
                    int qr = qt * 128 + ri * 64 + ty * 4 + i;
                    int qc = jt * 64 + tx * 4;
                    if (qc + 0 > qr) s0  = -INFINITY;
                    if (qc + 1 > qr) s1  = -INFINITY;
                    if (qc + 2 > qr) s2v = -INFINITY;
                    if (qc + 3 > qr) s3  = -INFINITY;
                }

                float rm = fmaxf(fmaxf(s0, s1), fmaxf(s2v, s3));
                rm = fmaxf(rm, __shfl_xor_sync(0xffffffffu, rm, 1));
                rm = fmaxf(rm, __shfl_xor_sync(0xffffffffu, rm, 2));
                rm = fmaxf(rm, __shfl_xor_sync(0xffffffffu, rm, 4));
                rm = fmaxf(rm, __shfl_xor_sync(0xffffffffu, rm, 8));

                float mo = m[ri][i];
                float mn = fmaxf(mo, rm);
                float f  = __expf(mo - mn);
                float p0 = __expf(s0 - mn);
                float p1 = __expf(s1 - mn);
                float p2 = __expf(s2v - mn);
                float p3 = __expf(s3 - mn);
                float rs = (p0 + p1) + (p2 + p3);
                rs += __shfl_xor_sync(0xffffffffu, rs, 1);
                rs += __shfl_xor_sync(0xffffffffu, rs, 2);
                rs += __shfl_xor_sync(0xffffffffu, rs, 4);
                rs += __shfl_xor_sync(0xffffffffu, rs, 8);

                l[ri][i] = l[ri][i] * f + rs;
                m[ri][i] = mn;
                u64 fp = pk2(f, f);
                mul2(o2[ri][i][0], fp);
                mul2(o2[ri][i][1], fp);

                *(float4*)&Ps[(ri * 64 + ty * 4 + i) * 68 + tx * 4] =
                    make_float4(p0, p1, p2, p3);
            }
        __syncthreads();

        // O += P @ V, packed
        #pragma unroll 4
        for (int c = 0; c < 64; c++) {
            const u64* bp = (const u64*)&Vs[c * 68 + tx * 4];
            u64 B0 = bp[0], B1 = bp[1];
            #pragma unroll
            for (int ri = 0; ri < 2; ri++)
                #pragma unroll
                for (int i = 0; i < 4; i++) {
                    float p = Ps[(ri * 64 + ty * 4 + i) * 68 + c];
                    u64 pp = pk2(p, p);
                    fma2(o2[ri][i][0], pp, B0);
                    fma2(o2[ri][i][1], pp, B1);
                }
        }
    }

    #pragma unroll
    for (int ri = 0; ri < 2; ri++)
        #pragma unroll
        for (int i = 0; i < 4; i++) {
            float inv = 1.f / l[ri][i];
            int row = b * SEQ + qt * 128 + ri * 64 + ty * 4 + i;
            float2 u0 = upk2(o2[ri][i][0]);
            float2 u1 = upk2(o2[ri][i][1]);
            float4 out = make_float4(u0.x * inv, u0.y * inv, u1.x * inv, u1.y * inv);
            *(float4*)&Y[(size_t)row * (NH * HD) + h * HD + tx * 4] = out;
        }
}

// ---------------------------------------------------------------------------
extern "C" void kernel_launch(void* const* d_in, const int* in_sizes, int n_in,
                              void* d_out, int out_size) {
    const float* x  = (const float*)d_in[0];
    const float* Wq = (const float*)d_in[1];
    const float* Wk = (const float*)d_in[2];
    const float* Wv = (const float*)d_in[3];
    const float* Wo = (const float*)d_in[4];
    float* out = (float*)d_out;

    float *Qp, *Kp, *Vp, *Yp;
    cudaGetSymbolAddress((void**)&Qp, g_Q);
    cudaGetSymbolAddress((void**)&Kp, g_K);
    cudaGetSymbolAddress((void**)&Vp, g_V);
    cudaGetSymbolAddress((void**)&Yp, g_Y);

    dim3 blk(256);

    // RoPE table (fp64 trig once) — overlaps nothing but is ~10us
    rope_table<<<(SEQ * 32 + 255) / 256, blk>>>();

    // QKV projections
    sgemm128<<<dim3((NH * HD) / 128, ROWS / 128), blk>>>(x, Wq, Qp, ROWS, NH * HD, MODEL);
    sgemm128<<<dim3((NKV * HD) / 128, ROWS / 128), blk>>>(x, Wk, Kp, ROWS, NKV * HD, MODEL);
    sgemm128<<<dim3((NKV * HD) / 128, ROWS / 128), blk>>>(x, Wv, Vp, ROWS, NKV * HD, MODEL);

    // RoPE on Q and K
    int totq = ROWS * NH * 32;
    int totk = ROWS * NKV * 32;
    rope_kernel<<<(totq + 255) / 256, blk>>>(Qp, NH, totq);
    rope_kernel<<<(totk + 255) / 256, blk>>>(Kp, NKV, totk);

    // flash attention
    const int SMEM = (64 * 132 + 64 * 68 + 64 * 68 + 128 * 68) * 4;  // 103424 B
    cudaFuncSetAttribute(flashattn, cudaFuncAttributeMaxDynamicSharedMemorySize, SMEM);
    flashattn<<<dim3(SEQ / 128, NH, BATCH), blk, SMEM>>>(Qp, Kp, Vp, Yp);

    // output projection
    sgemm128<<<dim3(MODEL / 128, ROWS / 128), blk>>>(Yp, Wo, out, ROWS, MODEL, MODEL);
}

// round 3
// speedup vs baseline: 1.2002x; 1.0434x over previous
#include <cuda_runtime.h>
#include <math.h>

#define BATCH 2
#define SEQ   2048
#define MODEL 2048
#define NH    32
#define NKV   8
#define HD    64
#define ROWS  (BATCH*SEQ)   // 4096

typedef unsigned long long u64;

// ---------------- packed fp32x2 helpers (Blackwell FFMA2 path) -------------
__device__ __forceinline__ u64 pk2(float lo, float hi) {
    u64 r; asm("mov.b64 %0, {%1, %2};" : "=l"(r) : "f"(lo), "f"(hi)); return r;
}
__device__ __forceinline__ float2 upk2(u64 v) {
    float2 r; asm("mov.b64 {%0, %1}, %2;" : "=f"(r.x), "=f"(r.y) : "l"(v)); return r;
}
__device__ __forceinline__ void fma2(u64& d, u64 a, u64 b) {
    asm("fma.rn.f32x2 %0, %1, %2, %0;" : "+l"(d) : "l"(a), "l"(b));
}
__device__ __forceinline__ void mul2(u64& d, u64 a) {
    asm("mul.rn.f32x2 %0, %0, %1;" : "+l"(d) : "l"(a));
}

// ---------------- scratch (static device arrays; no allocation allowed) ----
__device__ float g_Q[(size_t)ROWS * NH  * HD];   // 32 MB
__device__ float g_K[(size_t)ROWS * NKV * HD];   // 8 MB
__device__ float g_V[(size_t)ROWS * NKV * HD];   // 8 MB
__device__ float g_Y[(size_t)ROWS * NH  * HD];   // 32 MB
__device__ float g_cs[(size_t)SEQ * 32 * 2];     // 512 KB cos/sin table

// ---------------------------------------------------------------------------
// RoPE table: fp64 trig once for 65536 (s,d) pairs.
// ---------------------------------------------------------------------------
__global__ __launch_bounds__(256)
void rope_table() {
    int i = blockIdx.x * 256 + threadIdx.x;
    if (i >= SEQ * 32) return;
    int d = i & 31;
    int s = i >> 5;
    double inv = exp2(-(double)d * (13.287712379549448882 / 32.0));
    double ang = (double)s * inv;
    double sd, cd;
    sincos(ang, &sd, &cd);
    g_cs[2 * i + 0] = (float)cd;
    g_cs[2 * i + 1] = (float)sd;
}

__global__ __launch_bounds__(256)
void rope_kernel(float* __restrict__ T, int nheads, int total) {
    int i = blockIdx.x * blockDim.x + threadIdx.x;
    if (i >= total) return;
    int d   = i & 31;
    int h   = (i >> 5) % nheads;
    int row = i / (32 * nheads);
    int s   = row % SEQ;

    float2 cs = *(const float2*)&g_cs[2 * (s * 32 + d)];

    float* p = T + (size_t)row * (nheads * 64) + h * 64 + d;
    float q0 = p[0];
    float q1 = p[32];
    p[0]  = q0 * cs.x - q1 * cs.y;
    p[32] = q1 * cs.x + q0 * cs.y;
}

// ---------------------------------------------------------------------------
// SGEMM core: 128x128 tile, BK=8, 256 threads, 8x8 micro-tile, FFMA2 pairs.
// ---------------------------------------------------------------------------
__device__ __forceinline__
void gemm_core(const float* __restrict__ A, const float* __restrict__ B,
               float* __restrict__ C, int N, int K) {
    __shared__ float As[8][132];
    __shared__ float Bs[8][128];

    const int tid = threadIdx.x;
    const int tx  = tid & 15;
    const int ty  = tid >> 4;
    const int bm  = blockIdx.y * 128;
    const int bn  = blockIdx.x * 128;

    u64 acc[2][2][4][2];
    #pragma unroll
    for (int a = 0; a < 2; a++)
        #pragma unroll
        for (int b = 0; b < 2; b++)
            #pragma unroll
            for (int i = 0; i < 4; i++) {
                acc[a][b][i][0] = 0ull; acc[a][b][i][1] = 0ull;
            }

    const int arow = tid >> 1;
    const int acol = (tid & 1) * 4;
    const int brow = tid >> 5;
    const int bcol = (tid & 31) * 4;

    const float* Ap = A + (size_t)(bm + arow) * K + acol;
    const float* Bp = B + (size_t)brow * N + bn + bcol;

    float4 av = *(const float4*)Ap;
    float4 bv = *(const float4*)Bp;

    const int ntiles = K >> 3;
    for (int t = 0; t < ntiles; t++) {
        As[acol + 0][arow] = av.x;
        As[acol + 1][arow] = av.y;
        As[acol + 2][arow] = av.z;
        As[acol + 3][arow] = av.w;
        *(float4*)&Bs[brow][bcol] = bv;
        __syncthreads();

        if (t + 1 < ntiles) {
            Ap += 8;
            Bp += (size_t)8 * N;
            av = *(const float4*)Ap;
            bv = *(const float4*)Bp;
        }

        #pragma unroll
        for (int kk = 0; kk < 8; kk++) {
            float a0[4], a1[4];
            *(float4*)a0 = *(const float4*)&As[kk][ty * 4];
            *(float4*)a1 = *(const float4*)&As[kk][64 + ty * 4];
            const u64* b0p = (const u64*)&Bs[kk][tx * 4];
            const u64* b1p = (const u64*)&Bs[kk][64 + tx * 4];
            u64 B00 = b0p[0], B01 = b0p[1];
            u64 B10 = b1p[0], B11 = b1p[1];
            #pragma unroll
            for (int i = 0; i < 4; i++) {
                u64 A0 = pk2(a0[i], a0[i]);
                u64 A1 = pk2(a1[i], a1[i]);
                fma2(acc[0][0][i][0], A0, B00);
                fma2(acc[0][0][i][1], A0, B01);
                fma2(acc[0][1][i][0], A0, B10);
                fma2(acc[0][1][i][1], A0, B11);
                fma2(acc[1][0][i][0], A1, B00);
                fma2(acc[1][0][i][1], A1, B01);
                fma2(acc[1][1][i][0], A1, B10);
                fma2(acc[1][1][i][1], A1, B11);
            }
        }
        __syncthreads();
    }

    #pragma unroll
    for (int ri = 0; ri < 2; ri++)
        #pragma unroll
        for (int i = 0; i < 4; i++) {
            int row = bm + ri * 64 + ty * 4 + i;
            #pragma unroll
            for (int ci = 0; ci < 2; ci++) {
                float2 p0 = upk2(acc[ri][ci][i][0]);
                float2 p1 = upk2(acc[ri][ci][i][1]);
                float4 v = make_float4(p0.x, p0.y, p1.x, p1.y);
                *(float4*)&C[(size_t)row * N + bn + ci * 64 + tx * 4] = v;
            }
        }
}

__global__ __launch_bounds__(256, 2)
void sgemm128(const float* __restrict__ A, const float* __restrict__ B,
              float* __restrict__ C, int N, int K) {
    gemm_core(A, B, C, N, K);
}

// fused K+V projection: blockIdx.z picks (B, C) pair -> one full wave
__global__ __launch_bounds__(256, 2)
void sgemm128_kv(const float* __restrict__ A,
                 const float* __restrict__ Bk, const float* __restrict__ Bv,
                 float* __restrict__ Ck, float* __restrict__ Cv,
                 int N, int K) {
    const float* B = blockIdx.z ? Bv : Bk;
    float*       C = blockIdx.z ? Cv : Ck;
    gemm_core(A, B, C, N, K);
}

// ---------------------------------------------------------------------------
// Flash attention, fp32, FFMA2-packed. Q-tile 128, KV-tile 64.
// ---------------------------------------------------------------------------
__global__ __launch_bounds__(256, 2)
void flashattn(const float* __restrict__ Q, const float* __restrict__ K,
               const float* __restrict__ V, float* __restrict__ Y) {
    extern __shared__ float sm[];
    float* Qt = sm;                  // [64][132]  Qt[d*132 + r]
    float* Kt = Qt + 64 * 132;       // [64][68]   Kt[d*68  + c]
    float* Vs = Kt + 64 * 68;        // [64][68]   Vs[c*68  + d]
    float* Ps = Vs + 64 * 68;        // [128][68]  Ps[r*68  + c]

    const int tid = threadIdx.x;
    const int tx  = tid & 15;
    const int ty  = tid >> 4;
    const int qt  = gridDim.x - 1 - blockIdx.x;   // heavy tiles first
    const int h   = blockIdx.y;
    const int b   = blockIdx.z;
    const int kvh = h >> 2;
    const float scale = 0.125f;

    {
        const float* Qg = Q + ((size_t)(b * SEQ + qt * 128)) * (NH * HD) + h * HD;
        for (int t = tid; t < 128 * 16; t += 256) {
            int r  = t >> 4;
            int d4 = (t & 15) * 4;
            float4 v = *(const float4*)(Qg + (size_t)r * (NH * HD) + d4);
            Qt[(d4 + 0) * 132 + r] = v.x * scale;
            Qt[(d4 + 1) * 132 + r] = v.y * scale;
            Qt[(d4 + 2) * 132 + r] = v.z * scale;
            Qt[(d4 + 3) * 132 + r] = v.w * scale;
        }
    }

    float m[2][4], l[2][4];
    u64 o2[2][4][2];
    #pragma unroll
    for (int ri = 0; ri < 2; ri++)
        #pragma unroll
        for (int i = 0; i < 4; i++) {
            m[ri][i] = -INFINITY;
            l[ri][i] = 0.f;
            o2[ri][i][0] = 0ull; o2[ri][i][1] = 0ull;
        }

    const int njt = 2 * qt + 2;
    for (int jt = 0; jt < njt; jt++) {
        __syncthreads();

        const float* Kg = K + ((size_t)(b * SEQ + jt * 64)) * (NKV * HD) + kvh * HD;
        const float* Vg = V + ((size_t)(b * SEQ + jt * 64)) * (NKV * HD) + kvh * HD;
        for (int t = tid; t < 64 * 16; t += 256) {
            int c  = t >> 4;
            int d4 = (t & 15) * 4;
            float4 kv = *(const float4*)(Kg + (size_t)c * (NKV * HD) + d4);
            Kt[(d4 + 0) * 68 + c] = kv.x;
            Kt[(d4 + 1) * 68 + c] = kv.y;
            Kt[(d4 + 2) * 68 + c] = kv.z;
            Kt[(d4 + 3) * 68 + c] = kv.w;
            float4 vv = *(const float4*)(Vg + (size_t)c * (NKV * HD) + d4);
            *(float4*)&Vs[c * 68 + d4] = vv;
        }
        __syncthreads();

        // S = (Q*scale) @ K^T
        u64 s2[2][4][2];
        #pragma unroll
        for (int ri = 0; ri < 2; ri++)
            #pragma unroll
            for (int i = 0; i < 4; i++) { s2[ri][i][0] = 0ull; s2[ri][i][1] = 0ull; }

        #pragma unroll 4
        for (int d = 0; d < 64; d++) {
            float a0[4], a1[4];
            *(float4*)a0 = *(const float4*)&Qt[d * 132 + ty * 4];
            *(float4*)a1 = *(const float4*)&Qt[d * 132 + 64 + ty * 4];
            const u64* bp = (const u64*)&Kt[d * 68 + tx * 4];
            u64 B0 = bp[0], B1 = bp[1];
            #pragma unroll
            for (int i = 0; i < 4; i++) {
                u64 A0 = pk2(a0[i], a0[i]);
                u64 A1 = pk2(a1[i], a1[i]);
                fma2(s2[0][i][0], A0, B0);
                fma2(s2[0][i][1], A0, B1);
                fma2(s2[1][i][0], A1, B0);
                fma2(s2[1][i][1], A1, B1);
            }
        }

        // mask + online softmax + stash P
        #pragma unroll
        for (int ri = 0; ri < 2; ri++)
            #pragma unroll
            for (int i = 0; i < 4; i++) {
                float2 u0 = upk2(s2[ri][i][0]);
                float2 u1 = upk2(s2[ri][i][1]);
                float s0 = u0.x, s1 = u0.y, s2v = u1.x, s3 = u1.y;

                if (jt * 64 + 63 > qt * 128) {
                    int qr = qt * 128 + ri * 64 + ty * 4 + i;
                    int qc = jt * 64 + tx * 4;
                    if (qc + 0 > qr) s0  = -INFINITY;
                    if (qc + 1 > qr) s1  = -INFINITY;
                    if (qc + 2 > qr) s2v = -INFINITY;
                    if (qc + 3 > qr) s3  = -INFINITY;
                }

                float rm = fmaxf(fmaxf(s0, s1), fmaxf(s2v, s3));
                rm = fmaxf(rm, __shfl_xor_sync(0xffffffffu, rm, 1));
                rm = fmaxf(rm, __shfl_xor_sync(0xffffffffu, rm, 2));
                rm = fmaxf(rm, __shfl_xor_sync(0xffffffffu, rm, 4));
                rm = fmaxf(rm, __shfl_xor_sync(0xffffffffu, rm, 8));

                float mo = m[ri][i];
                float mn = fmaxf(mo, rm);
                float f  = __expf(mo - mn);
                float p0 = __expf(s0 - mn);
                float p1 = __expf(s1 - mn);
                float p2 = __expf(s2v - mn);
                float p3 = __expf(s3 - mn);
                float rs = (p0 + p1) + (p2 + p3);
                rs += __shfl_xor_sync(0xffffffffu, rs, 1);
                rs += __shfl_xor_sync(0xffffffffu, rs, 2);
                rs += __shfl_xor_sync(0xffffffffu, rs, 4);
                rs += __shfl_xor_sync(0xffffffffu, rs, 8);

                l[ri][i] = l[ri][i] * f + rs;
                m[ri][i] = mn;
                u64 fp = pk2(f, f);
                mul2(o2[ri][i][0], fp);
                mul2(o2[ri][i][1], fp);

                *(float4*)&Ps[(ri * 64 + ty * 4 + i) * 68 + tx * 4] =
                    make_float4(p0, p1, p2, p3);
            }
        __syncthreads();

        // O += P @ V : float4 P loads (8 LDS.128 per 4 cols, not 32 scalar LDS)
        #pragma unroll 4
        for (int c4 = 0; c4 < 64; c4 += 4) {
            float4 pv[2][4];
            #pragma unroll
            for (int ri = 0; ri < 2; ri++)
                #pragma unroll
                for (int i = 0; i < 4; i++)
                    pv[ri][i] = *(const float4*)&Ps[(ri * 64 + ty * 4 + i) * 68 + c4];
            #pragma unroll
            for (int cc = 0; cc < 4; cc++) {
                const u64* bp = (const u64*)&Vs[(c4 + cc) * 68 + tx * 4];
                u64 B0 = bp[0], B1 = bp[1];
                #pragma unroll
                for (int ri = 0; ri < 2; ri++)
                    #pragma unroll
                    for (int i = 0; i < 4; i++) {
                        float p = cc == 0 ? pv[ri][i].x : cc == 1 ? pv[ri][i].y
                                : cc == 2 ? pv[ri][i].z : pv[ri][i].w;
                        u64 pp = pk2(p, p);
                        fma2(o2[ri][i][0], pp, B0);
                        fma2(o2[ri][i][1], pp, B1);
                    }
            }
        }
    }

    #pragma unroll
    for (int ri = 0; ri < 2; ri++)
        #pragma unroll
        for (int i = 0; i < 4; i++) {
            float inv = 1.f / l[ri][i];
            int row = b * SEQ + qt * 128 + ri * 64 + ty * 4 + i;
            float2 u0 = upk2(o2[ri][i][0]);
            float2 u1 = upk2(o2[ri][i][1]);
            float4 out = make_float4(u0.x * inv, u0.y * inv, u1.x * inv, u1.y * inv);
            *(float4*)&Y[(size_t)row * (NH * HD) + h * HD + tx * 4] = out;
        }
}

// ---------------------------------------------------------------------------
extern "C" void kernel_launch(void* const* d_in, const int* in_sizes, int n_in,
                              void* d_out, int out_size) {
    const float* x  = (const float*)d_in[0];
    const float* Wq = (const float*)d_in[1];
    const float* Wk = (const float*)d_in[2];
    const float* Wv = (const float*)d_in[3];
    const float* Wo = (const float*)d_in[4];
    float* out = (float*)d_out;

    float *Qp, *Kp, *Vp, *Yp;
    cudaGetSymbolAddress((void**)&Qp, g_Q);
    cudaGetSymbolAddress((void**)&Kp, g_K);
    cudaGetSymbolAddress((void**)&Vp, g_V);
    cudaGetSymbolAddress((void**)&Yp, g_Y);

    dim3 blk(256);

    rope_table<<<(SEQ * 32 + 255) / 256, blk>>>();

    // Q projection (512 CTAs) + fused K/V projection (256 CTAs)
    sgemm128<<<dim3((NH * HD) / 128, ROWS / 128), blk>>>(x, Wq, Qp, NH * HD, MODEL);
    sgemm128_kv<<<dim3((NKV * HD) / 128, ROWS / 128, 2), blk>>>(
        x, Wk, Wv, Kp, Vp, NKV * HD, MODEL);

    // RoPE on Q and K
    int totq = ROWS * NH * 32;
    int totk = ROWS * NKV * 32;
    rope_kernel<<<(totq + 255) / 256, blk>>>(Qp, NH, totq);
    rope_kernel<<<(totk + 255) / 256, blk>>>(Kp, NKV, totk);

    // flash attention
    const int SMEM = (64 * 132 + 64 * 68 + 64 * 68 + 128 * 68) * 4;  // 103424 B
    cudaFuncSetAttribute(flashattn, cudaFuncAttributeMaxDynamicSharedMemorySize, SMEM);
    flashattn<<<dim3(SEQ / 128, NH, BATCH), blk, SMEM>>>(Qp, Kp, Vp, Yp);

    // output projection
    sgemm128<<<dim3(MODEL / 128, ROWS / 128), blk>>>(Yp, Wo, out, MODEL, MODEL);
}

// round 5
// speedup vs baseline: 1.9032x; 1.5857x over previous
#include <cuda_runtime.h>
#include <cuda_bf16.h>
#include <math.h>
#include <stdint.h>

#define BATCH 2
#define SEQ   2048
#define MODEL 2048
#define NH    32
#define NKV   8
#define HD    64
#define ROWS  (BATCH*SEQ)   // 4096

typedef unsigned long long u64;
typedef __nv_bfloat16 bf16;

// ---------------- packed fp32x2 helpers (flash attention path) -------------
__device__ __forceinline__ u64 pk2(float lo, float hi) {
    u64 r; asm("mov.b64 %0, {%1, %2};" : "=l"(r) : "f"(lo), "f"(hi)); return r;
}
__device__ __forceinline__ float2 upk2(u64 v) {
    float2 r; asm("mov.b64 {%0, %1}, %2;" : "=f"(r.x), "=f"(r.y) : "l"(v)); return r;
}
__device__ __forceinline__ void fma2(u64& d, u64 a, u64 b) {
    asm("fma.rn.f32x2 %0, %1, %2, %0;" : "+l"(d) : "l"(a), "l"(b));
}
__device__ __forceinline__ void mul2(u64& d, u64 a) {
    asm("mul.rn.f32x2 %0, %0, %1;" : "+l"(d) : "l"(a));
}

// ---------------- mma.sync helpers (baseline compute_103 features) ---------
__device__ __forceinline__ uint32_t smem_u32(const void* p) {
    uint32_t a;
    asm("{ .reg .u64 t; cvta.to.shared.u64 t, %1; cvt.u32.u64 %0, t; }" : "=r"(a) : "l"(p));
    return a;
}
__device__ __forceinline__ void ldsm4(uint32_t* r, uint32_t addr) {
    asm volatile("ldmatrix.sync.aligned.m8n8.x4.shared.b16 {%0,%1,%2,%3}, [%4];"
                 : "=r"(r[0]), "=r"(r[1]), "=r"(r[2]), "=r"(r[3]) : "r"(addr));
}
__device__ __forceinline__ void mma_bf16(float* d, const uint32_t* a, const uint32_t* b) {
    asm volatile("mma.sync.aligned.m16n8k16.row.col.f32.bf16.bf16.f32 "
                 "{%0,%1,%2,%3}, {%4,%5,%6,%7}, {%8,%9}, {%0,%1,%2,%3};"
                 : "+f"(d[0]), "+f"(d[1]), "+f"(d[2]), "+f"(d[3])
                 : "r"(a[0]), "r"(a[1]), "r"(a[2]), "r"(a[3]), "r"(b[0]), "r"(b[1]));
}
__device__ __forceinline__ void cp16(uint32_t dst, const void* src) {
    asm volatile("cp.async.cg.shared.global [%0], [%1], 16;" :: "r"(dst), "l"(src));
}
#define CP_COMMIT() asm volatile("cp.async.commit_group;" ::: "memory")
#define CP_WAIT1()  asm volatile("cp.async.wait_group 1;" ::: "memory")

// ---------------- scratch --------------------------------------------------
__device__ float g_Q[(size_t)ROWS * NH  * HD];
__device__ float g_K[(size_t)ROWS * NKV * HD];
__device__ float g_V[(size_t)ROWS * NKV * HD];
__device__ float g_Y[(size_t)ROWS * NH  * HD];
__device__ float g_cs[(size_t)SEQ * 32 * 2];

__device__ bf16 g_xh[(size_t)ROWS * MODEL];
__device__ bf16 g_xl[(size_t)ROWS * MODEL];
__device__ bf16 g_Yh[(size_t)ROWS * NH * HD];
__device__ bf16 g_Yl[(size_t)ROWS * NH * HD];
__device__ bf16 g_Wqt_h[(size_t)(NH  * HD) * MODEL];
__device__ bf16 g_Wqt_l[(size_t)(NH  * HD) * MODEL];
__device__ bf16 g_Wkt_h[(size_t)(NKV * HD) * MODEL];
__device__ bf16 g_Wkt_l[(size_t)(NKV * HD) * MODEL];
__device__ bf16 g_Wvt_h[(size_t)(NKV * HD) * MODEL];
__device__ bf16 g_Wvt_l[(size_t)(NKV * HD) * MODEL];
__device__ bf16 g_Wot_h[(size_t)MODEL * (NH * HD)];
__device__ bf16 g_Wot_l[(size_t)MODEL * (NH * HD)];

// ---------------------------------------------------------------------------
// RoPE table + apply
// ---------------------------------------------------------------------------
__global__ __launch_bounds__(256)
void rope_table() {
    int i = blockIdx.x * 256 + threadIdx.x;
    if (i >= SEQ * 32) return;
    int d = i & 31;
    int s = i >> 5;
    double inv = exp2(-(double)d * (13.287712379549448882 / 32.0));
    double ang = (double)s * inv;
    double sd, cd;
    sincos(ang, &sd, &cd);
    g_cs[2 * i + 0] = (float)cd;
    g_cs[2 * i + 1] = (float)sd;
}

__global__ __launch_bounds__(256)
void rope_kernel(float* __restrict__ T, int nheads, int total) {
    int i = blockIdx.x * blockDim.x + threadIdx.x;
    if (i >= total) return;
    int d   = i & 31;
    int h   = (i >> 5) % nheads;
    int row = i / (32 * nheads);
    int s   = row % SEQ;
    float2 cs = *(const float2*)&g_cs[2 * (s * 32 + d)];
    float* p = T + (size_t)row * (nheads * 64) + h * 64 + d;
    float q0 = p[0];
    float q1 = p[32];
    p[0]  = q0 * cs.x - q1 * cs.y;
    p[32] = q1 * cs.x + q0 * cs.y;
}

// ---------------------------------------------------------------------------
// split fp32 -> (hi, lo) bf16
// ---------------------------------------------------------------------------
__global__ __launch_bounds__(256)
void split_rows(const float* __restrict__ X, bf16* __restrict__ H,
                bf16* __restrict__ L, int total) {
    int i = blockIdx.x * 256 + threadIdx.x;
    if (i >= total) return;
    float v = X[i];
    bf16 h = __float2bfloat16(v);
    H[i] = h;
    L[i] = __float2bfloat16(v - __bfloat162float(h));
}

// ---------------------------------------------------------------------------
// transpose + split: W[K,N] fp32 -> T[N,K] bf16 hi/lo
// ---------------------------------------------------------------------------
__global__ __launch_bounds__(256)
void transpose_split(const float* __restrict__ W, bf16* __restrict__ Th,
                     bf16* __restrict__ Tl, int Kd, int Nw) {
    __shared__ float tile[32][33];
    int n0 = blockIdx.x * 32, k0 = blockIdx.y * 32;
    int tx = threadIdx.x & 31, ty = threadIdx.x >> 5;
    #pragma unroll
    for (int j = ty; j < 32; j += 8)
        tile[j][tx] = W[(size_t)(k0 + j) * Nw + n0 + tx];
    __syncthreads();
    #pragma unroll
    for (int j = ty; j < 32; j += 8) {
        float v = tile[tx][j];
        bf16 h = __float2bfloat16(v);
        Th[(size_t)(n0 + j) * Kd + k0 + tx] = h;
        Tl[(size_t)(n0 + j) * Kd + k0 + tx] = __float2bfloat16(v - __bfloat162float(h));
    }
}

// ---------------------------------------------------------------------------
// Split-bf16 tensor-core GEMM via mma.sync (HMMA).
// C[M,Nt] = Ah@B^T with cross terms AhBl + AlBh.  A*: [M,K] bf16 K-major.
// B*: [Nt,K] bf16 K-major (pre-transposed weights).
// Tile 128x128, BK=32, 8 warps (4M x 2N), double-buffered cp.async.
// smem row = 128B: [hi 64B | lo 64B], XOR-8 swizzle on 16B chunks.
// ---------------------------------------------------------------------------
#define GSTAGE 32768     // A tile 16KB + B tile 16KB
#define GEMM_SMEM (2 * GSTAGE)

__device__ __forceinline__ void g_load_stage(char* base, uint32_t sbase,
                                             const bf16* Ah, const bf16* Al,
                                             const bf16* Bh, const bf16* Bl,
                                             int bm, int bn, int kb, int K, int tid) {
    // A: 1024 chunks of 16B, B: 1024 chunks
    #pragma unroll
    for (int it = 0; it < 4; it++) {
        int idx = tid + it * 256;
        int r = idx >> 3, c = idx & 7;
        uint32_t dst = sbase + r * 128 + ((c ^ (r & 7)) << 4);
        const bf16* src = (c < 4 ? Ah : Al) + (size_t)(bm + r) * K + kb * 32 + (c & 3) * 8;
        cp16(dst, src);
    }
    #pragma unroll
    for (int it = 0; it < 4; it++) {
        int idx = tid + it * 256;
        int r = idx >> 3, c = idx & 7;
        uint32_t dst = sbase + 16384 + r * 128 + ((c ^ (r & 7)) << 4);
        const bf16* src = (c < 4 ? Bh : Bl) + (size_t)(bn + r) * K + kb * 32 + (c & 3) * 8;
        cp16(dst, src);
    }
}

__device__ __forceinline__
void gemm_mma_core(const bf16* __restrict__ Ah, const bf16* __restrict__ Al,
                   const bf16* __restrict__ Bh, const bf16* __restrict__ Bl,
                   float* __restrict__ C, int Nt, int K, int bm, int bn) {
    extern __shared__ char smg[];
    const uint32_t sbase = smem_u32(smg);
    const int tid  = threadIdx.x;
    const int lane = tid & 31;
    const int warp = tid >> 5;
    const int wm   = (warp & 3) * 32;      // warp M offset
    const int wn   = (warp >> 2) * 64;     // warp N offset

    float acc[2][8][4];
    #pragma unroll
    for (int am = 0; am < 2; am++)
        #pragma unroll
        for (int an = 0; an < 8; an++)
            #pragma unroll
            for (int j = 0; j < 4; j++) acc[am][an][j] = 0.f;

    const int KB = K >> 5;
    g_load_stage(smg, sbase,           Ah, Al, Bh, Bl, bm, bn, 0, K, tid); CP_COMMIT();
    g_load_stage(smg, sbase + GSTAGE,  Ah, Al, Bh, Bl, bm, bn, 1, K, tid); CP_COMMIT();

    // precomputed ldmatrix lane geometry
    const int a_row  = wm + (lane & 15);          // + am*16
    const int a_kh   = (lane >> 4) & 1;           // k-half chunk add
    const int b_n    = wn + (lane & 7) + ((lane >> 4) << 3);   // + g*16
    const int b_kh   = (lane >> 3) & 1;

    for (int t = 0; t < KB; t++) {
        CP_WAIT1();
        __syncthreads();
        const uint32_t sA = sbase + (t & 1) * GSTAGE;
        const uint32_t sB = sA + 16384;

        #pragma unroll
        for (int h = 0; h < 2; h++) {
            uint32_t bh[4][4], bl[4][4];
            #pragma unroll
            for (int g = 0; g < 4; g++) {
                int n = b_n + g * 16;
                int ch = h * 2 + b_kh;
                ldsm4(bh[g], sB + n * 128 + (((ch)     ^ (n & 7)) << 4));
                ldsm4(bl[g], sB + n * 128 + (((ch + 4) ^ (n & 7)) << 4));
            }
            #pragma unroll
            for (int am = 0; am < 2; am++) {
                int r  = a_row + am * 16;
                int ch = h * 2 + a_kh;
                uint32_t ah[4], al[4];
                ldsm4(ah, sA + r * 128 + (((ch)     ^ (r & 7)) << 4));
                ldsm4(al, sA + r * 128 + (((ch + 4) ^ (r & 7)) << 4));
                #pragma unroll
                for (int g = 0; g < 4; g++) {
                    mma_bf16(acc[am][2 * g],     ah, &bh[g][0]);
                    mma_bf16(acc[am][2 * g + 1], ah, &bh[g][2]);
                    mma_bf16(acc[am][2 * g],     al, &bh[g][0]);
                    mma_bf16(acc[am][2 * g + 1], al, &bh[g][2]);
                    mma_bf16(acc[am][2 * g],     ah, &bl[g][0]);
                    mma_bf16(acc[am][2 * g + 1], ah, &bl[g][2]);
                }
            }
        }
        __syncthreads();
        if (t + 2 < KB) {
            g_load_stage(smg + (t & 1) * GSTAGE, sA, Ah, Al, Bh, Bl, bm, bn, t + 2, K, tid);
        }
        CP_COMMIT();   // keep group count in lockstep even when empty
    }

    // epilogue: D frag -> C
    #pragma unroll
    for (int am = 0; am < 2; am++) {
        int r0 = bm + wm + am * 16 + (lane >> 2);
        #pragma unroll
        for (int an = 0; an < 8; an++) {
            int col = bn + wn + an * 8 + (lane & 3) * 2;
            *(float2*)&C[(size_t)r0 * Nt + col]       = make_float2(acc[am][an][0], acc[am][an][1]);
            *(float2*)&C[(size_t)(r0 + 8) * Nt + col] = make_float2(acc[am][an][2], acc[am][an][3]);
        }
    }
}

__global__ __launch_bounds__(256, 2)
void gemm_mma(const bf16* __restrict__ Ah, const bf16* __restrict__ Al,
              const bf16* __restrict__ Bh, const bf16* __restrict__ Bl,
              float* __restrict__ C, int Nt, int K) {
    gemm_mma_core(Ah, Al, Bh, Bl, C, Nt, K, blockIdx.y * 128, blockIdx.x * 128);
}

__global__ __launch_bounds__(256, 2)
void gemm_mma_kv(const bf16* __restrict__ Ah, const bf16* __restrict__ Al,
                 const bf16* __restrict__ Bkh, const bf16* __restrict__ Bkl,
                 const bf16* __restrict__ Bvh, const bf16* __restrict__ Bvl,
                 float* __restrict__ Ck, float* __restrict__ Cv, int Nt, int K) {
    const bf16* Bh = blockIdx.z ? Bvh : Bkh;
    const bf16* Bl = blockIdx.z ? Bvl : Bkl;
    float* C = blockIdx.z ? Cv : Ck;
    gemm_mma_core(Ah, Al, Bh, Bl, C, Nt, K, blockIdx.y * 128, blockIdx.x * 128);
}

// ---------------------------------------------------------------------------
// Flash attention, fp32, FFMA2-packed (unchanged, proven).
// ---------------------------------------------------------------------------
__global__ __launch_bounds__(256, 2)
void flashattn(const float* __restrict__ Q, const float* __restrict__ K,
               const float* __restrict__ V, float* __restrict__ Y) {
    extern __shared__ float sm[];
    float* Qt = sm;
    float* Kt = Qt + 64 * 132;
    float* Vs = Kt + 64 * 68;
    float* Ps = Vs + 64 * 68;

    const int tid = threadIdx.x;
    const int tx  = tid & 15;
    const int ty  = tid >> 4;
    const int qt  = gridDim.x - 1 - blockIdx.x;
    const int h   = blockIdx.y;
    const int b   = blockIdx.z;
    const int kvh = h >> 2;
    const float scale = 0.125f;

    {
        const float* Qg = Q + ((size_t)(b * SEQ + qt * 128)) * (NH * HD) + h * HD;
        for (int t = tid; t < 128 * 16; t += 256) {
            int r  = t >> 4;
            int d4 = (t & 15) * 4;
            float4 v = *(const float4*)(Qg + (size_t)r * (NH * HD) + d4);
            Qt[(d4 + 0) * 132 + r] = v.x * scale;
            Qt[(d4 + 1) * 132 + r] = v.y * scale;
            Qt[(d4 + 2) * 132 + r] = v.z * scale;
            Qt[(d4 + 3) * 132 + r] = v.w * scale;
        }
    }

    float m[2][4], l[2][4];
    u64 o2[2][4][2];
    #pragma unroll
    for (int ri = 0; ri < 2; ri++)
        #pragma unroll
        for (int i = 0; i < 4; i++) {
            m[ri][i] = -INFINITY;
            l[ri][i] = 0.f;
            o2[ri][i][0] = 0ull; o2[ri][i][1] = 0ull;
        }

    const int njt = 2 * qt + 2;
    for (int jt = 0; jt < njt; jt++) {
        __syncthreads();

        const float* Kg = K + ((size_t)(b * SEQ + jt * 64)) * (NKV * HD) + kvh * HD;
        const float* Vg = V + ((size_t)(b * SEQ + jt * 64)) * (NKV * HD) + kvh * HD;
        for (int t = tid; t < 64 * 16; t += 256) {
            int c  = t >> 4;
            int d4 = (t & 15) * 4;
            float4 kv = *(const float4*)(Kg + (size_t)c * (NKV * HD) + d4);
            Kt[(d4 + 0) * 68 + c] = kv.x;
            Kt[(d4 + 1) * 68 + c] = kv.y;
            Kt[(d4 + 2) * 68 + c] = kv.z;
            Kt[(d4 + 3) * 68 + c] = kv.w;
            float4 vv = *(const float4*)(Vg + (size_t)c * (NKV * HD) + d4);
            *(float4*)&Vs[c * 68 + d4] = vv;
        }
        __syncthreads();

        u64 s2[2][4][2];
        #pragma unroll
        for (int ri = 0; ri < 2; ri++)
            #pragma unroll
            for (int i = 0; i < 4; i++) { s2[ri][i][0] = 0ull; s2[ri][i][1] = 0ull; }

        #pragma unroll 4
        for (int d = 0; d < 64; d++) {
            float a0[4], a1[4];
            *(float4*)a0 = *(const float4*)&Qt[d * 132 + ty * 4];
            *(float4*)a1 = *(const float4*)&Qt[d * 132 + 64 + ty * 4];
            const u64* bp = (const u64*)&Kt[d * 68 + tx * 4];
            u64 B0 = bp[0], B1 = bp[1];
            #pragma unroll
            for (int i = 0; i < 4; i++) {
                u64 A0 = pk2(a0[i], a0[i]);
                u64 A1 = pk2(a1[i], a1[i]);
                fma2(s2[0][i][0], A0, B0);
                fma2(s2[0][i][1], A0, B1);
                fma2(s2[1][i][0], A1, B0);
                fma2(s2[1][i][1], A1, B1);
            }
        }

        #pragma unroll
        for (int ri = 0; ri < 2; ri++)
            #pragma unroll
            for (int i = 0; i < 4; i++) {
                float2 u0 = upk2(s2[ri][i][0]);
                float2 u1 = upk2(s2[ri][i][1]);
                float s0 = u0.x, s1 = u0.y, s2v = u1.x, s3 = u1.y;

                if (jt * 64 + 63 > qt * 128) {
                    int qr = qt * 128 + ri * 64 + ty * 4 + i;
                    int qc = jt * 64 + tx * 4;
                    if (qc + 0 > qr) s0  = -INFINITY;
                    if (qc + 1 > qr) s1  = -INFINITY;
                    if (qc + 2 > qr) s2v = -INFINITY;
                    if (qc + 3 > qr) s3  = -INFINITY;
                }

                float rm = fmaxf(fmaxf(s0, s1), fmaxf(s2v, s3));
                rm = fmaxf(rm, __shfl_xor_sync(0xffffffffu, rm, 1));
                rm = fmaxf(rm, __shfl_xor_sync(0xffffffffu, rm, 2));
                rm = fmaxf(rm, __shfl_xor_sync(0xffffffffu, rm, 4));
                rm = fmaxf(rm, __shfl_xor_sync(0xffffffffu, rm, 8));

                float mo = m[ri][i];
                float mn = fmaxf(mo, rm);
                float f  = __expf(mo - mn);
                float p0 = __expf(s0 - mn);
                float p1 = __expf(s1 - mn);
                float p2 = __expf(s2v - mn);
                float p3 = __expf(s3 - mn);
                float rs = (p0 + p1) + (p2 + p3);
                rs += __shfl_xor_sync(0xffffffffu, rs, 1);
                rs += __shfl_xor_sync(0xffffffffu, rs, 2);
                rs += __shfl_xor_sync(0xffffffffu, rs, 4);
                rs += __shfl_xor_sync(0xffffffffu, rs, 8);

                l[ri][i] = l[ri][i] * f + rs;
                m[ri][i] = mn;
                u64 fp = pk2(f, f);
                mul2(o2[ri][i][0], fp);
                mul2(o2[ri][i][1], fp);

                *(float4*)&Ps[(ri * 64 + ty * 4 + i) * 68 + tx * 4] =
                    make_float4(p0, p1, p2, p3);
            }
        __syncthreads();

        #pragma unroll 4
        for (int c4 = 0; c4 < 64; c4 += 4) {
            float4 pv[2][4];
            #pragma unroll
            for (int ri = 0; ri < 2; ri++)
                #pragma unroll
                for (int i = 0; i < 4; i++)
                    pv[ri][i] = *(const float4*)&Ps[(ri * 64 + ty * 4 + i) * 68 + c4];
            #pragma unroll
            for (int cc = 0; cc < 4; cc++) {
                const u64* bp = (const u64*)&Vs[(c4 + cc) * 68 + tx * 4];
                u64 B0 = bp[0], B1 = bp[1];
                #pragma unroll
                for (int ri = 0; ri < 2; ri++)
                    #pragma unroll
                    for (int i = 0; i < 4; i++) {
                        float p = cc == 0 ? pv[ri][i].x : cc == 1 ? pv[ri][i].y
                                : cc == 2 ? pv[ri][i].z : pv[ri][i].w;
                        u64 pp = pk2(p, p);
                        fma2(o2[ri][i][0], pp, B0);
                        fma2(o2[ri][i][1], pp, B1);
                    }
            }
        }
    }

    #pragma unroll
    for (int ri = 0; ri < 2; ri++)
        #pragma unroll
        for (int i = 0; i < 4; i++) {
            float inv = 1.f / l[ri][i];
            int row = b * SEQ + qt * 128 + ri * 64 + ty * 4 + i;
            float2 u0 = upk2(o2[ri][i][0]);
            float2 u1 = upk2(o2[ri][i][1]);
            float4 out = make_float4(u0.x * inv, u0.y * inv, u1.x * inv, u1.y * inv);
            *(float4*)&Y[(size_t)row * (NH * HD) + h * HD + tx * 4] = out;
        }
}

// ---------------------------------------------------------------------------
extern "C" void kernel_launch(void* const* d_in, const int* in_sizes, int n_in,
                              void* d_out, int out_size) {
    const float* x  = (const float*)d_in[0];
    const float* Wq = (const float*)d_in[1];
    const float* Wk = (const float*)d_in[2];
    const float* Wv = (const float*)d_in[3];
    const float* Wo = (const float*)d_in[4];
    float* out = (float*)d_out;

    float *Qp, *Kp, *Vp, *Yp;
    cudaGetSymbolAddress((void**)&Qp, g_Q);
    cudaGetSymbolAddress((void**)&Kp, g_K);
    cudaGetSymbolAddress((void**)&Vp, g_V);
    cudaGetSymbolAddress((void**)&Yp, g_Y);
    bf16 *xh, *xl, *Yh, *Yl, *Wqh, *Wql, *Wkh, *Wkl, *Wvh, *Wvl, *Woh, *Wol;
    cudaGetSymbolAddress((void**)&xh, g_xh);   cudaGetSymbolAddress((void**)&xl, g_xl);
    cudaGetSymbolAddress((void**)&Yh, g_Yh);   cudaGetSymbolAddress((void**)&Yl, g_Yl);
    cudaGetSymbolAddress((void**)&Wqh, g_Wqt_h); cudaGetSymbolAddress((void**)&Wql, g_Wqt_l);
    cudaGetSymbolAddress((void**)&Wkh, g_Wkt_h); cudaGetSymbolAddress((void**)&Wkl, g_Wkt_l);
    cudaGetSymbolAddress((void**)&Wvh, g_Wvt_h); cudaGetSymbolAddress((void**)&Wvl, g_Wvt_l);
    cudaGetSymbolAddress((void**)&Woh, g_Wot_h); cudaGetSymbolAddress((void**)&Wol, g_Wot_l);

    dim3 blk(256);

    rope_table<<<(SEQ * 32 + 255) / 256, blk>>>();

    // split x, transpose+split weights
    int totx = ROWS * MODEL;
    split_rows<<<(totx + 255) / 256, blk>>>(x, xh, xl, totx);
    transpose_split<<<dim3((NH * HD) / 32, MODEL / 32), blk>>>(Wq, Wqh, Wql, MODEL, NH * HD);
    transpose_split<<<dim3((NKV * HD) / 32, MODEL / 32), blk>>>(Wk, Wkh, Wkl, MODEL, NKV * HD);
    transpose_split<<<dim3((NKV * HD) / 32, MODEL / 32), blk>>>(Wv, Wvh, Wvl, MODEL, NKV * HD);
    transpose_split<<<dim3(MODEL / 32, (NH * HD) / 32), blk>>>(Wo, Woh, Wol, NH * HD, MODEL);

    // tensor-core projections (mma.sync, split-bf16)
    cudaFuncSetAttribute(gemm_mma, cudaFuncAttributeMaxDynamicSharedMemorySize, GEMM_SMEM);
    cudaFuncSetAttribute(gemm_mma_kv, cudaFuncAttributeMaxDynamicSharedMemorySize, GEMM_SMEM);
    gemm_mma<<<dim3((NH * HD) / 128, ROWS / 128), blk, GEMM_SMEM>>>(
        xh, xl, Wqh, Wql, Qp, NH * HD, MODEL);
    gemm_mma_kv<<<dim3((NKV * HD) / 128, ROWS / 128, 2), blk, GEMM_SMEM>>>(
        xh, xl, Wkh, Wkl, Wvh, Wvl, Kp, Vp, NKV * HD, MODEL);

    // RoPE
    int totq = ROWS * NH * 32;
    int totk = ROWS * NKV * 32;
    rope_kernel<<<(totq + 255) / 256, blk>>>(Qp, NH, totq);
    rope_kernel<<<(totk + 255) / 256, blk>>>(Kp, NKV, totk);

    // flash attention (fp32)
    const int SMEM = (64 * 132 + 64 * 68 + 64 * 68 + 128 * 68) * 4;
    cudaFuncSetAttribute(flashattn, cudaFuncAttributeMaxDynamicSharedMemorySize, SMEM);
    flashattn<<<dim3(SEQ / 128, NH, BATCH), blk, SMEM>>>(Qp, Kp, Vp, Yp);

    // split Y, output projection on tensor cores
    int toty = ROWS * NH * HD;
    split_rows<<<(toty + 255) / 256, blk>>>(Yp, Yh, Yl, toty);
    gemm_mma<<<dim3(MODEL / 128, ROWS / 128), blk, GEMM_SMEM>>>(
        Yh, Yl, Woh, Wol, out, MODEL, MODEL);
}

// round 6
// speedup vs baseline: 2.9262x; 1.5375x over previous
#include <cuda_runtime.h>
#include <cuda_bf16.h>
#include <math.h>
#include <stdint.h>

#define BATCH 2
#define SEQ   2048
#define MODEL 2048
#define NH    32
#define NKV   8
#define HD    64
#define ROWS  (BATCH*SEQ)   // 4096

typedef unsigned long long u64;
typedef __nv_bfloat16 bf16;

// ---------------- mma.sync helpers (baseline compute_103 features) ---------
__device__ __forceinline__ uint32_t smem_u32(const void* p) {
    uint32_t a;
    asm("{ .reg .u64 t; cvta.to.shared.u64 t, %1; cvt.u32.u64 %0, t; }" : "=r"(a) : "l"(p));
    return a;
}
__device__ __forceinline__ void ldsm4(uint32_t* r, uint32_t addr) {
    asm volatile("ldmatrix.sync.aligned.m8n8.x4.shared.b16 {%0,%1,%2,%3}, [%4];"
                 : "=r"(r[0]), "=r"(r[1]), "=r"(r[2]), "=r"(r[3]) : "r"(addr));
}
__device__ __forceinline__ void mma_bf16(float* d, const uint32_t* a, const uint32_t* b) {
    asm volatile("mma.sync.aligned.m16n8k16.row.col.f32.bf16.bf16.f32 "
                 "{%0,%1,%2,%3}, {%4,%5,%6,%7}, {%8,%9}, {%0,%1,%2,%3};"
                 : "+f"(d[0]), "+f"(d[1]), "+f"(d[2]), "+f"(d[3])
                 : "r"(a[0]), "r"(a[1]), "r"(a[2]), "r"(a[3]), "r"(b[0]), "r"(b[1]));
}
__device__ __forceinline__ void cp16(uint32_t dst, const void* src) {
    asm volatile("cp.async.cg.shared.global [%0], [%1], 16;" :: "r"(dst), "l"(src));
}
#define CP_COMMIT() asm volatile("cp.async.commit_group;" ::: "memory")
#define CP_WAIT1()  asm volatile("cp.async.wait_group 1;" ::: "memory")

// bf16x2 pack/split helpers: lo float -> bits[15:0], hi float -> bits[31:16]
__device__ __forceinline__ uint32_t pkbf2(float lo, float hi) {
    uint32_t r; asm("cvt.rn.bf16x2.f32 %0, %1, %2;" : "=r"(r) : "f"(hi), "f"(lo)); return r;
}
__device__ __forceinline__ float bflo(uint32_t p) { return __uint_as_float(p << 16); }
__device__ __forceinline__ float bfhi(uint32_t p) { return __uint_as_float(p & 0xffff0000u); }
// split pair (f0,f1) -> hi packed + residual packed
__device__ __forceinline__ void split2(float f0, float f1, uint32_t& hp, uint32_t& lp) {
    hp = pkbf2(f0, f1);
    lp = pkbf2(f0 - bflo(hp), f1 - bfhi(hp));
}

// ---------------- scratch --------------------------------------------------
__device__ float g_Q[(size_t)ROWS * NH  * HD];
__device__ float g_K[(size_t)ROWS * NKV * HD];
__device__ float g_V[(size_t)ROWS * NKV * HD];
__device__ float g_Y[(size_t)ROWS * NH  * HD];
__device__ float g_cs[(size_t)SEQ * 32 * 2];

__device__ bf16 g_xh[(size_t)ROWS * MODEL];
__device__ bf16 g_xl[(size_t)ROWS * MODEL];
__device__ bf16 g_Yh[(size_t)ROWS * NH * HD];
__device__ bf16 g_Yl[(size_t)ROWS * NH * HD];
__device__ bf16 g_Wqt_h[(size_t)(NH  * HD) * MODEL];
__device__ bf16 g_Wqt_l[(size_t)(NH  * HD) * MODEL];
__device__ bf16 g_Wkt_h[(size_t)(NKV * HD) * MODEL];
__device__ bf16 g_Wkt_l[(size_t)(NKV * HD) * MODEL];
__device__ bf16 g_Wvt_h[(size_t)(NKV * HD) * MODEL];
__device__ bf16 g_Wvt_l[(size_t)(NKV * HD) * MODEL];
__device__ bf16 g_Wot_h[(size_t)MODEL * (NH * HD)];
__device__ bf16 g_Wot_l[(size_t)MODEL * (NH * HD)];

// ---------------------------------------------------------------------------
// RoPE table + apply
// ---------------------------------------------------------------------------
__global__ __launch_bounds__(256)
void rope_table() {
    int i = blockIdx.x * 256 + threadIdx.x;
    if (i >= SEQ * 32) return;
    int d = i & 31;
    int s = i >> 5;
    double inv = exp2(-(double)d * (13.287712379549448882 / 32.0));
    double ang = (double)s * inv;
    double sd, cd;
    sincos(ang, &sd, &cd);
    g_cs[2 * i + 0] = (float)cd;
    g_cs[2 * i + 1] = (float)sd;
}

__global__ __launch_bounds__(256)
void rope_kernel(float* __restrict__ T, int nheads, int total) {
    int i = blockIdx.x * blockDim.x + threadIdx.x;
    if (i >= total) return;
    int d   = i & 31;
    int h   = (i >> 5) % nheads;
    int row = i / (32 * nheads);
    int s   = row % SEQ;
    float2 cs = *(const float2*)&g_cs[2 * (s * 32 + d)];
    float* p = T + (size_t)row * (nheads * 64) + h * 64 + d;
    float q0 = p[0];
    float q1 = p[32];
    p[0]  = q0 * cs.x - q1 * cs.y;
    p[32] = q1 * cs.x + q0 * cs.y;
}

// ---------------------------------------------------------------------------
// split fp32 -> (hi, lo) bf16
// ---------------------------------------------------------------------------
__global__ __launch_bounds__(256)
void split_rows(const float* __restrict__ X, bf16* __restrict__ H,
                bf16* __restrict__ L, int total) {
    int i = blockIdx.x * 256 + threadIdx.x;
    if (i >= total) return;
    float v = X[i];
    bf16 h = __float2bfloat16(v);
    H[i] = h;
    L[i] = __float2bfloat16(v - __bfloat162float(h));
}

// ---------------------------------------------------------------------------
// transpose + split: W[K,N] fp32 -> T[N,K] bf16 hi/lo
// ---------------------------------------------------------------------------
__global__ __launch_bounds__(256)
void transpose_split(const float* __restrict__ W, bf16* __restrict__ Th,
                     bf16* __restrict__ Tl, int Kd, int Nw) {
    __shared__ float tile[32][33];
    int n0 = blockIdx.x * 32, k0 = blockIdx.y * 32;
    int tx = threadIdx.x & 31, ty = threadIdx.x >> 5;
    #pragma unroll
    for (int j = ty; j < 32; j += 8)
        tile[j][tx] = W[(size_t)(k0 + j) * Nw + n0 + tx];
    __syncthreads();
    #pragma unroll
    for (int j = ty; j < 32; j += 8) {
        float v = tile[tx][j];
        bf16 h = __float2bfloat16(v);
        Th[(size_t)(n0 + j) * Kd + k0 + tx] = h;
        Tl[(size_t)(n0 + j) * Kd + k0 + tx] = __float2bfloat16(v - __bfloat162float(h));
    }
}

// ---------------------------------------------------------------------------
// Split-bf16 tensor-core GEMM (unchanged from Round 5, proven).
// ---------------------------------------------------------------------------
#define GSTAGE 32768
#define GEMM_SMEM (2 * GSTAGE)

__device__ __forceinline__ void g_load_stage(char* base, uint32_t sbase,
                                             const bf16* Ah, const bf16* Al,
                                             const bf16* Bh, const bf16* Bl,
                                             int bm, int bn, int kb, int K, int tid) {
    #pragma unroll
    for (int it = 0; it < 4; it++) {
        int idx = tid + it * 256;
        int r = idx >> 3, c = idx & 7;
        uint32_t dst = sbase + r * 128 + ((c ^ (r & 7)) << 4);
        const bf16* src = (c < 4 ? Ah : Al) + (size_t)(bm + r) * K + kb * 32 + (c & 3) * 8;
        cp16(dst, src);
    }
    #pragma unroll
    for (int it = 0; it < 4; it++) {
        int idx = tid + it * 256;
        int r = idx >> 3, c = idx & 7;
        uint32_t dst = sbase + 16384 + r * 128 + ((c ^ (r & 7)) << 4);
        const bf16* src = (c < 4 ? Bh : Bl) + (size_t)(bn + r) * K + kb * 32 + (c & 3) * 8;
        cp16(dst, src);
    }
}

__device__ __forceinline__
void gemm_mma_core(const bf16* __restrict__ Ah, const bf16* __restrict__ Al,
                   const bf16* __restrict__ Bh, const bf16* __restrict__ Bl,
                   float* __restrict__ C, int Nt, int K, int bm, int bn) {
    extern __shared__ char smg[];
    const uint32_t sbase = smem_u32(smg);
    const int tid  = threadIdx.x;
    const int lane = tid & 31;
    const int warp = tid >> 5;
    const int wm   = (warp & 3) * 32;
    const int wn   = (warp >> 2) * 64;

    float acc[2][8][4];
    #pragma unroll
    for (int am = 0; am < 2; am++)
        #pragma unroll
        for (int an = 0; an < 8; an++)
            #pragma unroll
            for (int j = 0; j < 4; j++) acc[am][an][j] = 0.f;

    const int KB = K >> 5;
    g_load_stage(smg, sbase,           Ah, Al, Bh, Bl, bm, bn, 0, K, tid); CP_COMMIT();
    g_load_stage(smg, sbase + GSTAGE,  Ah, Al, Bh, Bl, bm, bn, 1, K, tid); CP_COMMIT();

    const int a_row  = wm + (lane & 15);
    const int a_kh   = (lane >> 4) & 1;
    const int b_n    = wn + (lane & 7) + ((lane >> 4) << 3);
    const int b_kh   = (lane >> 3) & 1;

    for (int t = 0; t < KB; t++) {
        CP_WAIT1();
        __syncthreads();
        const uint32_t sA = sbase + (t & 1) * GSTAGE;
        const uint32_t sB = sA + 16384;

        #pragma unroll
        for (int h = 0; h < 2; h++) {
            uint32_t bh[4][4], bl[4][4];
            #pragma unroll
            for (int g = 0; g < 4; g++) {
                int n = b_n + g * 16;
                int ch = h * 2 + b_kh;
                ldsm4(bh[g], sB + n * 128 + (((ch)     ^ (n & 7)) << 4));
                ldsm4(bl[g], sB + n * 128 + (((ch + 4) ^ (n & 7)) << 4));
            }
            #pragma unroll
            for (int am = 0; am < 2; am++) {
                int r  = a_row + am * 16;
                int ch = h * 2 + a_kh;
                uint32_t ah[4], al[4];
                ldsm4(ah, sA + r * 128 + (((ch)     ^ (r & 7)) << 4));
                ldsm4(al, sA + r * 128 + (((ch + 4) ^ (r & 7)) << 4));
                #pragma unroll
                for (int g = 0; g < 4; g++) {
                    mma_bf16(acc[am][2 * g],     ah, &bh[g][0]);
                    mma_bf16(acc[am][2 * g + 1], ah, &bh[g][2]);
                    mma_bf16(acc[am][2 * g],     al, &bh[g][0]);
                    mma_bf16(acc[am][2 * g + 1], al, &bh[g][2]);
                    mma_bf16(acc[am][2 * g],     ah, &bl[g][0]);
                    mma_bf16(acc[am][2 * g + 1], ah, &bl[g][2]);
                }
            }
        }
        __syncthreads();
        if (t + 2 < KB) {
            g_load_stage(smg + (t & 1) * GSTAGE, sA, Ah, Al, Bh, Bl, bm, bn, t + 2, K, tid);
        }
        CP_COMMIT();
    }

    #pragma unroll
    for (int am = 0; am < 2; am++) {
        int r0 = bm + wm + am * 16 + (lane >> 2);
        #pragma unroll
        for (int an = 0; an < 8; an++) {
            int col = bn + wn + an * 8 + (lane & 3) * 2;
            *(float2*)&C[(size_t)r0 * Nt + col]       = make_float2(acc[am][an][0], acc[am][an][1]);
            *(float2*)&C[(size_t)(r0 + 8) * Nt + col] = make_float2(acc[am][an][2], acc[am][an][3]);
        }
    }
}

__global__ __launch_bounds__(256, 2)
void gemm_mma(const bf16* __restrict__ Ah, const bf16* __restrict__ Al,
              const bf16* __restrict__ Bh, const bf16* __restrict__ Bl,
              float* __restrict__ C, int Nt, int K) {
    gemm_mma_core(Ah, Al, Bh, Bl, C, Nt, K, blockIdx.y * 128, blockIdx.x * 128);
}

__global__ __launch_bounds__(256, 2)
void gemm_mma_kv(const bf16* __restrict__ Ah, const bf16* __restrict__ Al,
                 const bf16* __restrict__ Bkh, const bf16* __restrict__ Bkl,
                 const bf16* __restrict__ Bvh, const bf16* __restrict__ Bvl,
                 float* __restrict__ Ck, float* __restrict__ Cv, int Nt, int K) {
    const bf16* Bh = blockIdx.z ? Bvh : Bkh;
    const bf16* Bl = blockIdx.z ? Bvl : Bkl;
    float* C = blockIdx.z ? Cv : Ck;
    gemm_mma_core(Ah, Al, Bh, Bl, C, Nt, K, blockIdx.y * 128, blockIdx.x * 128);
}

// ---------------------------------------------------------------------------
// Tensor-core flash attention: mma.sync split-bf16 for S=QK^T and O+=P@V,
// fp32 online softmax in registers. Q tile 128 (8 warps x 16 rows), KV 64.
// smem: Q hi/lo [128][72 bf16] (stride 144B), K hi/lo [kv][d], Vt hi/lo [d][kv].
// ---------------------------------------------------------------------------
#define QSTR 144
#define FA_SQH 0
#define FA_SQL 18432
#define FA_SKH 36864
#define FA_SKL 46080
#define FA_SVH 55296
#define FA_SVL 64512
#define FA_SMEM 73728

__global__ __launch_bounds__(256)
void flashattn_mma(const float* __restrict__ Q, const float* __restrict__ K,
                   const float* __restrict__ V, float* __restrict__ Y) {
    extern __shared__ char sm[];
    const uint32_t base = smem_u32(sm);
    const int tid  = threadIdx.x;
    const int lane = tid & 31;
    const int warp = tid >> 5;
    const int qt   = gridDim.x - 1 - blockIdx.x;   // heavy tiles first
    const int h    = blockIdx.y;
    const int b    = blockIdx.z;
    const int kvh  = h >> 2;
    const int wm   = warp * 16;

    // ---- load Q tile once: fp32 -> scaled split bf16 hi/lo ----
    {
        const float* Qg = Q + ((size_t)(b * SEQ + qt * 128)) * (NH * HD) + h * HD;
        #pragma unroll
        for (int i = 0; i < 8; i++) {
            int idx = tid + i * 256;
            int r = idx >> 4, c4 = idx & 15;
            float4 v = *(const float4*)(Qg + (size_t)r * (NH * HD) + c4 * 4);
            v.x *= 0.125f; v.y *= 0.125f; v.z *= 0.125f; v.w *= 0.125f;
            uint32_t h01, l01, h23, l23;
            split2(v.x, v.y, h01, l01);
            split2(v.z, v.w, h23, l23);
            *(uint2*)(sm + FA_SQH + r * QSTR + c4 * 8) = make_uint2(h01, h23);
            *(uint2*)(sm + FA_SQL + r * QSTR + c4 * 8) = make_uint2(l01, l23);
        }
    }
    __syncthreads();

    // ---- Q fragments to registers (A operand, 4 k-chunks, hi/lo) ----
    const int a_row = wm + (lane & 15);
    const int a_kh  = (lane >> 4) & 1;
    uint32_t qh[4][4], ql[4][4];
    #pragma unroll
    for (int kc = 0; kc < 4; kc++) {
        ldsm4(qh[kc], base + FA_SQH + a_row * QSTR + kc * 32 + a_kh * 16);
        ldsm4(ql[kc], base + FA_SQL + a_row * QSTR + kc * 32 + a_kh * 16);
    }

    const int b_n  = (lane & 7) + ((lane >> 4) << 3);
    const int b_kh = (lane >> 3) & 1;

    float m0 = -INFINITY, m1 = -INFINITY, l0 = 0.f, l1 = 0.f;
    float oa[8][4];
    #pragma unroll
    for (int f = 0; f < 8; f++)
        #pragma unroll
        for (int j = 0; j < 4; j++) oa[f][j] = 0.f;

    const int njt = 2 * qt + 2;
    for (int jt = 0; jt < njt; jt++) {
        __syncthreads();   // prior tile's mma reads finished before overwrite

        // ---- load K tile [kv][d] split ----
        {
            const float* Kg = K + ((size_t)(b * SEQ + jt * 64)) * (NKV * HD) + kvh * HD;
            #pragma unroll
            for (int i = 0; i < 4; i++) {
                int idx = tid + i * 256;
                int r = idx >> 4, c4 = idx & 15;
                float4 v = *(const float4*)(Kg + (size_t)r * (NKV * HD) + c4 * 4);
                uint32_t h01, l01, h23, l23;
                split2(v.x, v.y, h01, l01);
                split2(v.z, v.w, h23, l23);
                *(uint2*)(sm + FA_SKH + r * QSTR + c4 * 8) = make_uint2(h01, h23);
                *(uint2*)(sm + FA_SKL + r * QSTR + c4 * 8) = make_uint2(l01, l23);
            }
        }
        // ---- load V tile transposed [d][kv] split ----
        {
            const float* Vg = V + ((size_t)(b * SEQ + jt * 64)) * (NKV * HD) + kvh * HD;
            int d   = tid & 63;
            int kvb = tid >> 6;           // 4 blocks of 16 kv
            float vv[16];
            #pragma unroll
            for (int i = 0; i < 16; i++)
                vv[i] = Vg[(size_t)(kvb * 16 + i) * (NKV * HD) + d];
            uint32_t hp[8], lp[8];
            #pragma unroll
            for (int i = 0; i < 8; i++) split2(vv[2 * i], vv[2 * i + 1], hp[i], lp[i]);
            *(uint4*)(sm + FA_SVH + d * QSTR + kvb * 32)      = make_uint4(hp[0], hp[1], hp[2], hp[3]);
            *(uint4*)(sm + FA_SVH + d * QSTR + kvb * 32 + 16) = make_uint4(hp[4], hp[5], hp[6], hp[7]);
            *(uint4*)(sm + FA_SVL + d * QSTR + kvb * 32)      = make_uint4(lp[0], lp[1], lp[2], lp[3]);
            *(uint4*)(sm + FA_SVL + d * QSTR + kvb * 32 + 16) = make_uint4(lp[4], lp[5], lp[6], lp[7]);
        }
        __syncthreads();

        // ---- S = Q @ K^T (128x64, this warp: 16x64) ----
        float sa[8][4];
        #pragma unroll
        for (int f = 0; f < 8; f++)
            #pragma unroll
            for (int j = 0; j < 4; j++) sa[f][j] = 0.f;

        #pragma unroll
        for (int kc = 0; kc < 4; kc++) {
            #pragma unroll
            for (int g = 0; g < 4; g++) {
                uint32_t kh4[4], kl4[4];
                ldsm4(kh4, base + FA_SKH + (b_n + g * 16) * QSTR + kc * 32 + b_kh * 16);
                ldsm4(kl4, base + FA_SKL + (b_n + g * 16) * QSTR + kc * 32 + b_kh * 16);
                mma_bf16(sa[2 * g],     qh[kc], &kh4[0]);
                mma_bf16(sa[2 * g + 1], qh[kc], &kh4[2]);
                mma_bf16(sa[2 * g],     ql[kc], &kh4[0]);
                mma_bf16(sa[2 * g + 1], ql[kc], &kh4[2]);
                mma_bf16(sa[2 * g],     qh[kc], &kl4[0]);
                mma_bf16(sa[2 * g + 1], qh[kc], &kl4[2]);
            }
        }

        // ---- causal mask (last two tiles only) ----
        if (jt * 64 + 63 > qt * 128) {
            int r0g = qt * 128 + wm + (lane >> 2);
            int r1g = r0g + 8;
            #pragma unroll
            for (int f = 0; f < 8; f++) {
                int c0 = jt * 64 + f * 8 + (lane & 3) * 2;
                if (c0 > r0g)     sa[f][0] = -INFINITY;
                if (c0 + 1 > r0g) sa[f][1] = -INFINITY;
                if (c0 > r1g)     sa[f][2] = -INFINITY;
                if (c0 + 1 > r1g) sa[f][3] = -INFINITY;
            }
        }

        // ---- online softmax (rows r0 = lane>>2, r1 = r0+8) ----
        float rm0 = -INFINITY, rm1 = -INFINITY;
        #pragma unroll
        for (int f = 0; f < 8; f++) {
            rm0 = fmaxf(rm0, fmaxf(sa[f][0], sa[f][1]));
            rm1 = fmaxf(rm1, fmaxf(sa[f][2], sa[f][3]));
        }
        rm0 = fmaxf(rm0, __shfl_xor_sync(0xffffffffu, rm0, 1));
        rm0 = fmaxf(rm0, __shfl_xor_sync(0xffffffffu, rm0, 2));
        rm1 = fmaxf(rm1, __shfl_xor_sync(0xffffffffu, rm1, 1));
        rm1 = fmaxf(rm1, __shfl_xor_sync(0xffffffffu, rm1, 2));

        float mn0 = fmaxf(m0, rm0), mn1 = fmaxf(m1, rm1);
        float f0 = __expf(m0 - mn0), f1 = __expf(m1 - mn1);
        float rs0 = 0.f, rs1 = 0.f;
        #pragma unroll
        for (int f = 0; f < 8; f++) {
            sa[f][0] = __expf(sa[f][0] - mn0);
            sa[f][1] = __expf(sa[f][1] - mn0);
            sa[f][2] = __expf(sa[f][2] - mn1);
            sa[f][3] = __expf(sa[f][3] - mn1);
            rs0 += sa[f][0] + sa[f][1];
            rs1 += sa[f][2] + sa[f][3];
        }
        rs0 += __shfl_xor_sync(0xffffffffu, rs0, 1);
        rs0 += __shfl_xor_sync(0xffffffffu, rs0, 2);
        rs1 += __shfl_xor_sync(0xffffffffu, rs1, 1);
        rs1 += __shfl_xor_sync(0xffffffffu, rs1, 2);

        l0 = l0 * f0 + rs0;  m0 = mn0;
        l1 = l1 * f1 + rs1;  m1 = mn1;
        #pragma unroll
        for (int f = 0; f < 8; f++) {
            oa[f][0] *= f0; oa[f][1] *= f0;
            oa[f][2] *= f1; oa[f][3] *= f1;
        }

        // ---- O += P @ V (P frags from sa registers, split hi/lo) ----
        #pragma unroll
        for (int kc = 0; kc < 4; kc++) {
            uint32_t ah[4], al[4];
            split2(sa[2 * kc][0],     sa[2 * kc][1],     ah[0], al[0]);
            split2(sa[2 * kc][2],     sa[2 * kc][3],     ah[1], al[1]);
            split2(sa[2 * kc + 1][0], sa[2 * kc + 1][1], ah[2], al[2]);
            split2(sa[2 * kc + 1][2], sa[2 * kc + 1][3], ah[3], al[3]);
            #pragma unroll
            for (int g = 0; g < 4; g++) {
                uint32_t vh4[4], vl4[4];
                ldsm4(vh4, base + FA_SVH + (b_n + g * 16) * QSTR + kc * 32 + b_kh * 16);
                ldsm4(vl4, base + FA_SVL + (b_n + g * 16) * QSTR + kc * 32 + b_kh * 16);
                mma_bf16(oa[2 * g],     ah, &vh4[0]);
                mma_bf16(oa[2 * g + 1], ah, &vh4[2]);
                mma_bf16(oa[2 * g],     al, &vh4[0]);
                mma_bf16(oa[2 * g + 1], al, &vh4[2]);
                mma_bf16(oa[2 * g],     ah, &vl4[0]);
                mma_bf16(oa[2 * g + 1], ah, &vl4[2]);
            }
        }
    }

    // ---- epilogue ----
    float inv0 = 1.f / l0, inv1 = 1.f / l1;
    int row0 = b * SEQ + qt * 128 + wm + (lane >> 2);
    #pragma unroll
    for (int f = 0; f < 8; f++) {
        int col = h * HD + f * 8 + (lane & 3) * 2;
        *(float2*)&Y[(size_t)row0 * (NH * HD) + col] =
            make_float2(oa[f][0] * inv0, oa[f][1] * inv0);
        *(float2*)&Y[(size_t)(row0 + 8) * (NH * HD) + col] =
            make_float2(oa[f][2] * inv1, oa[f][3] * inv1);
    }
}

// ---------------------------------------------------------------------------
extern "C" void kernel_launch(void* const* d_in, const int* in_sizes, int n_in,
                              void* d_out, int out_size) {
    const float* x  = (const float*)d_in[0];
    const float* Wq = (const float*)d_in[1];
    const float* Wk = (const float*)d_in[2];
    const float* Wv = (const float*)d_in[3];
    const float* Wo = (const float*)d_in[4];
    float* out = (float*)d_out;

    float *Qp, *Kp, *Vp, *Yp;
    cudaGetSymbolAddress((void**)&Qp, g_Q);
    cudaGetSymbolAddress((void**)&Kp, g_K);
    cudaGetSymbolAddress((void**)&Vp, g_V);
    cudaGetSymbolAddress((void**)&Yp, g_Y);
    bf16 *xh, *xl, *Yh, *Yl, *Wqh, *Wql, *Wkh, *Wkl, *Wvh, *Wvl, *Woh, *Wol;
    cudaGetSymbolAddress((void**)&xh, g_xh);   cudaGetSymbolAddress((void**)&xl, g_xl);
    cudaGetSymbolAddress((void**)&Yh, g_Yh);   cudaGetSymbolAddress((void**)&Yl, g_Yl);
    cudaGetSymbolAddress((void**)&Wqh, g_Wqt_h); cudaGetSymbolAddress((void**)&Wql, g_Wqt_l);
    cudaGetSymbolAddress((void**)&Wkh, g_Wkt_h); cudaGetSymbolAddress((void**)&Wkl, g_Wkt_l);
    cudaGetSymbolAddress((void**)&Wvh, g_Wvt_h); cudaGetSymbolAddress((void**)&Wvl, g_Wvt_l);
    cudaGetSymbolAddress((void**)&Woh, g_Wot_h); cudaGetSymbolAddress((void**)&Wol, g_Wot_l);

    dim3 blk(256);

    rope_table<<<(SEQ * 32 + 255) / 256, blk>>>();

    int totx = ROWS * MODEL;
    split_rows<<<(totx + 255) / 256, blk>>>(x, xh, xl, totx);
    transpose_split<<<dim3((NH * HD) / 32, MODEL / 32), blk>>>(Wq, Wqh, Wql, MODEL, NH * HD);
    transpose_split<<<dim3((NKV * HD) / 32, MODEL / 32), blk>>>(Wk, Wkh, Wkl, MODEL, NKV * HD);
    transpose_split<<<dim3((NKV * HD) / 32, MODEL / 32), blk>>>(Wv, Wvh, Wvl, MODEL, NKV * HD);
    transpose_split<<<dim3(MODEL / 32, (NH * HD) / 32), blk>>>(Wo, Woh, Wol, NH * HD, MODEL);

    cudaFuncSetAttribute(gemm_mma, cudaFuncAttributeMaxDynamicSharedMemorySize, GEMM_SMEM);
    cudaFuncSetAttribute(gemm_mma_kv, cudaFuncAttributeMaxDynamicSharedMemorySize, GEMM_SMEM);
    gemm_mma<<<dim3((NH * HD) / 128, ROWS / 128), blk, GEMM_SMEM>>>(
        xh, xl, Wqh, Wql, Qp, NH * HD, MODEL);
    gemm_mma_kv<<<dim3((NKV * HD) / 128, ROWS / 128, 2), blk, GEMM_SMEM>>>(
        xh, xl, Wkh, Wkl, Wvh, Wvl, Kp, Vp, NKV * HD, MODEL);

    int totq = ROWS * NH * 32;
    int totk = ROWS * NKV * 32;
    rope_kernel<<<(totq + 255) / 256, blk>>>(Qp, NH, totq);
    rope_kernel<<<(totk + 255) / 256, blk>>>(Kp, NKV, totk);

    // tensor-core flash attention
    cudaFuncSetAttribute(flashattn_mma, cudaFuncAttributeMaxDynamicSharedMemorySize, FA_SMEM);
    flashattn_mma<<<dim3(SEQ / 128, NH, BATCH), blk, FA_SMEM>>>(Qp, Kp, Vp, Yp);

    int toty = ROWS * NH * HD;
    split_rows<<<(toty + 255) / 256, blk>>>(Yp, Yh, Yl, toty);
    gemm_mma<<<dim3(MODEL / 128, ROWS / 128), blk, GEMM_SMEM>>>(
        Yh, Yl, Woh, Wol, out, MODEL, MODEL);
}

// round 7
// speedup vs baseline: 2.9614x; 1.0120x over previous
#include <cuda_runtime.h>
#include <cuda_bf16.h>
#include <math.h>
#include <stdint.h>

#define BATCH 2
#define SEQ   2048
#define MODEL 2048
#define NH    32
#define NKV   8
#define HD    64
#define ROWS  (BATCH*SEQ)   // 4096
#define KVW   (NKV*HD)      // 512

typedef unsigned long long u64;
typedef __nv_bfloat16 bf16;

// ---------------- mma.sync helpers -----------------------------------------
__device__ __forceinline__ uint32_t smem_u32(const void* p) {
    uint32_t a;
    asm("{ .reg .u64 t; cvta.to.shared.u64 t, %1; cvt.u32.u64 %0, t; }" : "=r"(a) : "l"(p));
    return a;
}
__device__ __forceinline__ void ldsm4(uint32_t* r, uint32_t addr) {
    asm volatile("ldmatrix.sync.aligned.m8n8.x4.shared.b16 {%0,%1,%2,%3}, [%4];"
                 : "=r"(r[0]), "=r"(r[1]), "=r"(r[2]), "=r"(r[3]) : "r"(addr));
}
__device__ __forceinline__ void mma_bf16(float* d, const uint32_t* a, const uint32_t* b) {
    asm volatile("mma.sync.aligned.m16n8k16.row.col.f32.bf16.bf16.f32 "
                 "{%0,%1,%2,%3}, {%4,%5,%6,%7}, {%8,%9}, {%0,%1,%2,%3};"
                 : "+f"(d[0]), "+f"(d[1]), "+f"(d[2]), "+f"(d[3])
                 : "r"(a[0]), "r"(a[1]), "r"(a[2]), "r"(a[3]), "r"(b[0]), "r"(b[1]));
}
__device__ __forceinline__ void cp16(uint32_t dst, const void* src) {
    asm volatile("cp.async.cg.shared.global [%0], [%1], 16;" :: "r"(dst), "l"(src));
}
#define CP_COMMIT() asm volatile("cp.async.commit_group;" ::: "memory")
#define CP_WAIT1()  asm volatile("cp.async.wait_group 1;" ::: "memory")

// bf16x2 pack/split: lo float -> bits[15:0], hi float -> bits[31:16]
__device__ __forceinline__ uint32_t pkbf2(float lo, float hi) {
    uint32_t r; asm("cvt.rn.bf16x2.f32 %0, %1, %2;" : "=r"(r) : "f"(hi), "f"(lo)); return r;
}
__device__ __forceinline__ float bflo(uint32_t p) { return __uint_as_float(p << 16); }
__device__ __forceinline__ float bfhi(uint32_t p) { return __uint_as_float(p & 0xffff0000u); }
__device__ __forceinline__ void split2(float f0, float f1, uint32_t& hp, uint32_t& lp) {
    hp = pkbf2(f0, f1);
    lp = pkbf2(f0 - bflo(hp), f1 - bfhi(hp));
}

// ---------------- scratch --------------------------------------------------
__device__ float g_Q[(size_t)ROWS * NH  * HD];
__device__ float g_K[(size_t)ROWS * KVW];
__device__ float g_V[(size_t)ROWS * KVW];
__device__ float g_cs[(size_t)SEQ * 32 * 2];

__device__ bf16 g_xh[(size_t)ROWS * MODEL];
__device__ bf16 g_xl[(size_t)ROWS * MODEL];
__device__ bf16 g_Kh[(size_t)ROWS * KVW];        // rope-applied, split
__device__ bf16 g_Kl[(size_t)ROWS * KVW];
__device__ bf16 g_Vth[(size_t)BATCH * KVW * SEQ];  // transposed [(b,kvh,d)][s]
__device__ bf16 g_Vtl[(size_t)BATCH * KVW * SEQ];
__device__ bf16 g_Yh[(size_t)ROWS * NH * HD];
__device__ bf16 g_Yl[(size_t)ROWS * NH * HD];
__device__ bf16 g_Wqt_h[(size_t)(NH  * HD) * MODEL];
__device__ bf16 g_Wqt_l[(size_t)(NH  * HD) * MODEL];
__device__ bf16 g_Wkt_h[(size_t)KVW * MODEL];
__device__ bf16 g_Wkt_l[(size_t)KVW * MODEL];
__device__ bf16 g_Wvt_h[(size_t)KVW * MODEL];
__device__ bf16 g_Wvt_l[(size_t)KVW * MODEL];
__device__ bf16 g_Wot_h[(size_t)MODEL * (NH * HD)];
__device__ bf16 g_Wot_l[(size_t)MODEL * (NH * HD)];

// ---------------------------------------------------------------------------
// RoPE cos/sin table (fp64 trig once)
// ---------------------------------------------------------------------------
__global__ __launch_bounds__(256)
void rope_table() {
    int i = blockIdx.x * 256 + threadIdx.x;
    if (i >= SEQ * 32) return;
    int d = i & 31;
    int s = i >> 5;
    double inv = exp2(-(double)d * (13.287712379549448882 / 32.0));
    double ang = (double)s * inv;
    double sd, cd;
    sincos(ang, &sd, &cd);
    g_cs[2 * i + 0] = (float)cd;
    g_cs[2 * i + 1] = (float)sd;
}

// ---------------------------------------------------------------------------
// K: rope + split fp32 -> bf16 hi/lo, one pass
// ---------------------------------------------------------------------------
__global__ __launch_bounds__(256)
void rope_split_k(const float* __restrict__ Kf, bf16* __restrict__ Kh,
                  bf16* __restrict__ Kl) {
    int i = blockIdx.x * 256 + threadIdx.x;     // ROWS*NKV*32 total
    if (i >= ROWS * NKV * 32) return;
    int d   = i & 31;
    int kvh = (i >> 5) & 7;
    int row = i >> 8;
    int s   = row & (SEQ - 1);
    float2 cs = *(const float2*)&g_cs[2 * (s * 32 + d)];
    size_t off = (size_t)row * KVW + kvh * 64 + d;
    float q0 = Kf[off];
    float q1 = Kf[off + 32];
    float r0 = q0 * cs.x - q1 * cs.y;
    float r1 = q1 * cs.x + q0 * cs.y;
    bf16 h0 = __float2bfloat16(r0);
    bf16 h1 = __float2bfloat16(r1);
    Kh[off]      = h0;
    Kh[off + 32] = h1;
    Kl[off]      = __float2bfloat16(r0 - __bfloat162float(h0));
    Kl[off + 32] = __float2bfloat16(r1 - __bfloat162float(h1));
}

// ---------------------------------------------------------------------------
// V: transpose + split  [b*SEQ+s][kvh*64+d] fp32 -> [(b*NKV+kvh)*64+d][s] bf16
// ---------------------------------------------------------------------------
__global__ __launch_bounds__(256)
void transpose_split_v(const float* __restrict__ V, bf16* __restrict__ Th,
                       bf16* __restrict__ Tl) {
    __shared__ float tile[32][33];
    int n0 = blockIdx.x * 32;   // col within 512
    int k0 = blockIdx.y * 32;   // row within 4096
    int tx = threadIdx.x & 31, ty = threadIdx.x >> 5;
    #pragma unroll
    for (int j = ty; j < 32; j += 8)
        tile[j][tx] = V[(size_t)(k0 + j) * KVW + n0 + tx];
    __syncthreads();
    int b = k0 >> 11;
    int s = (k0 & (SEQ - 1)) + tx;
    #pragma unroll
    for (int j = ty; j < 32; j += 8) {
        int c = n0 + j;
        int out_r = (b * NKV + (c >> 6)) * 64 + (c & 63);
        float v = tile[tx][j];
        bf16 h = __float2bfloat16(v);
        Th[(size_t)out_r * SEQ + s] = h;
        Tl[(size_t)out_r * SEQ + s] = __float2bfloat16(v - __bfloat162float(h));
    }
}

// ---------------------------------------------------------------------------
// split fp32 -> (hi, lo) bf16 (x only)
// ---------------------------------------------------------------------------
__global__ __launch_bounds__(256)
void split_rows(const float* __restrict__ X, bf16* __restrict__ H,
                bf16* __restrict__ L, int total) {
    int i = blockIdx.x * 256 + threadIdx.x;
    if (i >= total) return;
    float v = X[i];
    bf16 h = __float2bfloat16(v);
    H[i] = h;
    L[i] = __float2bfloat16(v - __bfloat162float(h));
}

// ---------------------------------------------------------------------------
// transpose + split weights: W[K,N] fp32 -> T[N,K] bf16 hi/lo
// ---------------------------------------------------------------------------
__global__ __launch_bounds__(256)
void transpose_split(const float* __restrict__ W, bf16* __restrict__ Th,
                     bf16* __restrict__ Tl, int Kd, int Nw) {
    __shared__ float tile[32][33];
    int n0 = blockIdx.x * 32, k0 = blockIdx.y * 32;
    int tx = threadIdx.x & 31, ty = threadIdx.x >> 5;
    #pragma unroll
    for (int j = ty; j < 32; j += 8)
        tile[j][tx] = W[(size_t)(k0 + j) * Nw + n0 + tx];
    __syncthreads();
    #pragma unroll
    for (int j = ty; j < 32; j += 8) {
        float v = tile[tx][j];
        bf16 h = __float2bfloat16(v);
        Th[(size_t)(n0 + j) * Kd + k0 + tx] = h;
        Tl[(size_t)(n0 + j) * Kd + k0 + tx] = __float2bfloat16(v - __bfloat162float(h));
    }
}

// ---------------------------------------------------------------------------
// Split-bf16 tensor-core GEMM (proven, unchanged).
// ---------------------------------------------------------------------------
#define GSTAGE 32768
#define GEMM_SMEM (2 * GSTAGE)

__device__ __forceinline__ void g_load_stage(char* base, uint32_t sbase,
                                             const bf16* Ah, const bf16* Al,
                                             const bf16* Bh, const bf16* Bl,
                                             int bm, int bn, int kb, int K, int tid) {
    #pragma unroll
    for (int it = 0; it < 4; it++) {
        int idx = tid + it * 256;
        int r = idx >> 3, c = idx & 7;
        uint32_t dst = sbase + r * 128 + ((c ^ (r & 7)) << 4);
        const bf16* src = (c < 4 ? Ah : Al) + (size_t)(bm + r) * K + kb * 32 + (c & 3) * 8;
        cp16(dst, src);
    }
    #pragma unroll
    for (int it = 0; it < 4; it++) {
        int idx = tid + it * 256;
        int r = idx >> 3, c = idx & 7;
        uint32_t dst = sbase + 16384 + r * 128 + ((c ^ (r & 7)) << 4);
        const bf16* src = (c < 4 ? Bh : Bl) + (size_t)(bn + r) * K + kb * 32 + (c & 3) * 8;
        cp16(dst, src);
    }
}

__device__ __forceinline__
void gemm_mma_core(const bf16* __restrict__ Ah, const bf16* __restrict__ Al,
                   const bf16* __restrict__ Bh, const bf16* __restrict__ Bl,
                   float* __restrict__ C, int Nt, int K, int bm, int bn) {
    extern __shared__ char smg[];
    const uint32_t sbase = smem_u32(smg);
    const int tid  = threadIdx.x;
    const int lane = tid & 31;
    const int warp = tid >> 5;
    const int wm   = (warp & 3) * 32;
    const int wn   = (warp >> 2) * 64;

    float acc[2][8][4];
    #pragma unroll
    for (int am = 0; am < 2; am++)
        #pragma unroll
        for (int an = 0; an < 8; an++)
            #pragma unroll
            for (int j = 0; j < 4; j++) acc[am][an][j] = 0.f;

    const int KB = K >> 5;
    g_load_stage(smg, sbase,           Ah, Al, Bh, Bl, bm, bn, 0, K, tid); CP_COMMIT();
    g_load_stage(smg, sbase + GSTAGE,  Ah, Al, Bh, Bl, bm, bn, 1, K, tid); CP_COMMIT();

    const int a_row  = wm + (lane & 15);
    const int a_kh   = (lane >> 4) & 1;
    const int b_n    = wn + (lane & 7) + ((lane >> 4) << 3);
    const int b_kh   = (lane >> 3) & 1;

    for (int t = 0; t < KB; t++) {
        CP_WAIT1();
        __syncthreads();
        const uint32_t sA = sbase + (t & 1) * GSTAGE;
        const uint32_t sB = sA + 16384;

        #pragma unroll
        for (int h = 0; h < 2; h++) {
            uint32_t bh[4][4], bl[4][4];
            #pragma unroll
            for (int g = 0; g < 4; g++) {
                int n = b_n + g * 16;
                int ch = h * 2 + b_kh;
                ldsm4(bh[g], sB + n * 128 + (((ch)     ^ (n & 7)) << 4));
                ldsm4(bl[g], sB + n * 128 + (((ch + 4) ^ (n & 7)) << 4));
            }
            #pragma unroll
            for (int am = 0; am < 2; am++) {
                int r  = a_row + am * 16;
                int ch = h * 2 + a_kh;
                uint32_t ah[4], al[4];
                ldsm4(ah, sA + r * 128 + (((ch)     ^ (r & 7)) << 4));
                ldsm4(al, sA + r * 128 + (((ch + 4) ^ (r & 7)) << 4));
                #pragma unroll
                for (int g = 0; g < 4; g++) {
                    mma_bf16(acc[am][2 * g],     ah, &bh[g][0]);
                    mma_bf16(acc[am][2 * g + 1], ah, &bh[g][2]);
                    mma_bf16(acc[am][2 * g],     al, &bh[g][0]);
                    mma_bf16(acc[am][2 * g + 1], al, &bh[g][2]);
                    mma_bf16(acc[am][2 * g],     ah, &bl[g][0]);
                    mma_bf16(acc[am][2 * g + 1], ah, &bl[g][2]);
                }
            }
        }
        __syncthreads();
        if (t + 2 < KB) {
            g_load_stage(smg + (t & 1) * GSTAGE, sA, Ah, Al, Bh, Bl, bm, bn, t + 2, K, tid);
        }
        CP_COMMIT();
    }

    #pragma unroll
    for (int am = 0; am < 2; am++) {
        int r0 = bm + wm + am * 16 + (lane >> 2);
        #pragma unroll
        for (int an = 0; an < 8; an++) {
            int col = bn + wn + an * 8 + (lane & 3) * 2;
            *(float2*)&C[(size_t)r0 * Nt + col]       = make_float2(acc[am][an][0], acc[am][an][1]);
            *(float2*)&C[(size_t)(r0 + 8) * Nt + col] = make_float2(acc[am][an][2], acc[am][an][3]);
        }
    }
}

__global__ __launch_bounds__(256, 2)
void gemm_mma(const bf16* __restrict__ Ah, const bf16* __restrict__ Al,
              const bf16* __restrict__ Bh, const bf16* __restrict__ Bl,
              float* __restrict__ C, int Nt, int K) {
    gemm_mma_core(Ah, Al, Bh, Bl, C, Nt, K, blockIdx.y * 128, blockIdx.x * 128);
}

__global__ __launch_bounds__(256, 2)
void gemm_mma_kv(const bf16* __restrict__ Ah, const bf16* __restrict__ Al,
                 const bf16* __restrict__ Bkh, const bf16* __restrict__ Bkl,
                 const bf16* __restrict__ Bvh, const bf16* __restrict__ Bvl,
                 float* __restrict__ Ck, float* __restrict__ Cv, int Nt, int K) {
    const bf16* Bh = blockIdx.z ? Bvh : Bkh;
    const bf16* Bl = blockIdx.z ? Bvl : Bkl;
    float* C = blockIdx.z ? Cv : Ck;
    gemm_mma_core(Ah, Al, Bh, Bl, C, Nt, K, blockIdx.y * 128, blockIdx.x * 128);
}

// ---------------------------------------------------------------------------
// Tensor-core flash attention v2:
//  - Q rope fused into the (once per CTA) Q load
//  - K/V pre-split bf16, loaded via cp.async double-buffered stages
//  - epilogue writes split Yh/Yl directly
// smem: Q hi/lo (2x18432) + 2 KV stages (KH,KL,VH,VL each 64x144B).
// ---------------------------------------------------------------------------
#define QSTR 144
#define FA_SQH 0
#define FA_SQL 18432
#define FA_STG 36864
#define FA_STG_SZ 36864
#define FA_SMEM (FA_STG + 2 * FA_STG_SZ)   // 110592

__device__ __forceinline__
void fa_load_kv(uint32_t sb, const bf16* __restrict__ Khp, const bf16* __restrict__ Klp,
                const bf16* __restrict__ Vhp, const bf16* __restrict__ Vlp,
                size_t krow0, int s0, int tid) {
    #pragma unroll
    for (int i = 0; i < 2; i++) {
        int idx = tid + i * 256;
        int r = idx >> 3, c = idx & 7;
        uint32_t so = r * QSTR + c * 16;
        cp16(sb + so,         Khp + (krow0 + r) * KVW + c * 8);
        cp16(sb + 9216 + so,  Klp + (krow0 + r) * KVW + c * 8);
        cp16(sb + 18432 + so, Vhp + (size_t)r * SEQ + s0 + c * 8);
        cp16(sb + 27648 + so, Vlp + (size_t)r * SEQ + s0 + c * 8);
    }
}

__global__ __launch_bounds__(256)
void flashattn_mma(const float* __restrict__ Q, const bf16* __restrict__ Kh,
                   const bf16* __restrict__ Kl, const bf16* __restrict__ Vth,
                   const bf16* __restrict__ Vtl,
                   bf16* __restrict__ Yh, bf16* __restrict__ Yl) {
    extern __shared__ char sm[];
    const uint32_t base = smem_u32(sm);
    const int tid  = threadIdx.x;
    const int lane = tid & 31;
    const int warp = tid >> 5;
    const int qt   = gridDim.x - 1 - blockIdx.x;
    const int h    = blockIdx.y;
    const int b    = blockIdx.z;
    const int kvh  = h >> 2;
    const int wm   = warp * 16;

    const bf16* Khp = Kh + kvh * 64;
    const bf16* Klp = Kl + kvh * 64;
    const bf16* Vhp = Vth + (size_t)((b * NKV + kvh) * 64) * SEQ;
    const bf16* Vlp = Vtl + (size_t)((b * NKV + kvh) * 64) * SEQ;
    const int njt = 2 * qt + 2;

    // prefetch first KV tile immediately
    fa_load_kv(base + FA_STG, Khp, Klp, Vhp, Vlp, (size_t)b * SEQ, 0, tid);
    CP_COMMIT();

    // ---- Q load: fp32 -> rope -> *0.125 -> split bf16 hi/lo in smem ----
    {
        const float* Qg = Q + ((size_t)(b * SEQ + qt * 128)) * (NH * HD) + h * HD;
        #pragma unroll
        for (int i = 0; i < 4; i++) {
            int idx = tid + i * 256;
            int r  = idx >> 3;
            int c4 = idx & 7;               // d0 = c4*4 in [0,32)
            int d0 = c4 * 4;
            int s  = qt * 128 + r;
            float4 q0 = *(const float4*)(Qg + (size_t)r * (NH * HD) + d0);
            float4 q1 = *(const float4*)(Qg + (size_t)r * (NH * HD) + 32 + d0);
            float4 csA = *(const float4*)&g_cs[2 * (s * 32 + d0)];
            float4 csB = *(const float4*)&g_cs[2 * (s * 32 + d0 + 2)];
            float lo0 = (q0.x * csA.x - q1.x * csA.y) * 0.125f;
            float lo1 = (q0.y * csA.z - q1.y * csA.w) * 0.125f;
            float lo2 = (q0.z * csB.x - q1.z * csB.y) * 0.125f;
            float lo3 = (q0.w * csB.z - q1.w * csB.w) * 0.125f;
            float hi0 = (q1.x * csA.x + q0.x * csA.y) * 0.125f;
            float hi1 = (q1.y * csA.z + q0.y * csA.w) * 0.125f;
            float hi2 = (q1.z * csB.x + q0.z * csB.y) * 0.125f;
            float hi3 = (q1.w * csB.z + q0.w * csB.w) * 0.125f;
            uint32_t hA, lA, hB, lB;
            split2(lo0, lo1, hA, lA);
            split2(lo2, lo3, hB, lB);
            *(uint2*)(sm + FA_SQH + r * QSTR + d0 * 2) = make_uint2(hA, hB);
            *(uint2*)(sm + FA_SQL + r * QSTR + d0 * 2) = make_uint2(lA, lB);
            split2(hi0, hi1, hA, lA);
            split2(hi2, hi3, hB, lB);
            *(uint2*)(sm + FA_SQH + r * QSTR + 64 + d0 * 2) = make_uint2(hA, hB);
            *(uint2*)(sm + FA_SQL + r * QSTR + 64 + d0 * 2) = make_uint2(lA, lB);
        }
    }
    __syncthreads();

    // ---- Q fragments to registers ----
    const int a_row = wm + (lane & 15);
    const int a_kh  = (lane >> 4) & 1;
    uint32_t qh[4][4], ql[4][4];
    #pragma unroll
    for (int kc = 0; kc < 4; kc++) {
        ldsm4(qh[kc], base + FA_SQH + a_row * QSTR + kc * 32 + a_kh * 16);
        ldsm4(ql[kc], base + FA_SQL + a_row * QSTR + kc * 32 + a_kh * 16);
    }

    const int b_n  = (lane & 7) + ((lane >> 4) << 3);
    const int b_kh = (lane >> 3) & 1;

    float m0 = -INFINITY, m1 = -INFINITY, l0 = 0.f, l1 = 0.f;
    float oa[8][4];
    #pragma unroll
    for (int f = 0; f < 8; f++)
        #pragma unroll
        for (int j = 0; j < 4; j++) oa[f][j] = 0.f;

    for (int jt = 0; jt < njt; jt++) {
        const uint32_t stg = base + FA_STG + (jt & 1) * FA_STG_SZ;

        __syncthreads();   // A: prior iter's reads of the other stage done
        if (jt + 1 < njt) {
            fa_load_kv(base + FA_STG + ((jt + 1) & 1) * FA_STG_SZ,
                       Khp, Klp, Vhp, Vlp,
                       (size_t)b * SEQ + (jt + 1) * 64, (jt + 1) * 64, tid);
        }
        CP_COMMIT();
        CP_WAIT1();        // current stage's group complete
        __syncthreads();   // B: stage data visible to all threads

        // ---- S = Q @ K^T ----
        float sa[8][4];
        #pragma unroll
        for (int f = 0; f < 8; f++)
            #pragma unroll
            for (int j = 0; j < 4; j++) sa[f][j] = 0.f;

        #pragma unroll
        for (int kc = 0; kc < 4; kc++) {
            #pragma unroll
            for (int g = 0; g < 4; g++) {
                uint32_t kh4[4], kl4[4];
                ldsm4(kh4, stg + (b_n + g * 16) * QSTR + kc * 32 + b_kh * 16);
                ldsm4(kl4, stg + 9216 + (b_n + g * 16) * QSTR + kc * 32 + b_kh * 16);
                mma_bf16(sa[2 * g],     qh[kc], &kh4[0]);
                mma_bf16(sa[2 * g + 1], qh[kc], &kh4[2]);
                mma_bf16(sa[2 * g],     ql[kc], &kh4[0]);
                mma_bf16(sa[2 * g + 1], ql[kc], &kh4[2]);
                mma_bf16(sa[2 * g],     qh[kc], &kl4[0]);
                mma_bf16(sa[2 * g + 1], qh[kc], &kl4[2]);
            }
        }

        // ---- causal mask ----
        if (jt * 64 + 63 > qt * 128) {
            int r0g = qt * 128 + wm + (lane >> 2);
            int r1g = r0g + 8;
            #pragma unroll
            for (int f = 0; f < 8; f++) {
                int c0 = jt * 64 + f * 8 + (lane & 3) * 2;
                if (c0 > r0g)     sa[f][0] = -INFINITY;
                if (c0 + 1 > r0g) sa[f][1] = -INFINITY;
                if (c0 > r1g)     sa[f][2] = -INFINITY;
                if (c0 + 1 > r1g) sa[f][3] = -INFINITY;
            }
        }

        // ---- online softmax ----
        float rm0 = -INFINITY, rm1 = -INFINITY;
        #pragma unroll
        for (int f = 0; f < 8; f++) {
            rm0 = fmaxf(rm0, fmaxf(sa[f][0], sa[f][1]));
            rm1 = fmaxf(rm1, fmaxf(sa[f][2], sa[f][3]));
        }
        rm0 = fmaxf(rm0, __shfl_xor_sync(0xffffffffu, rm0, 1));
        rm0 = fmaxf(rm0, __shfl_xor_sync(0xffffffffu, rm0, 2));
        rm1 = fmaxf(rm1, __shfl_xor_sync(0xffffffffu, rm1, 1));
        rm1 = fmaxf(rm1, __shfl_xor_sync(0xffffffffu, rm1, 2));

        float mn0 = fmaxf(m0, rm0), mn1 = fmaxf(m1, rm1);
        float f0 = __expf(m0 - mn0), f1 = __expf(m1 - mn1);
        float rs0 = 0.f, rs1 = 0.f;
        #pragma unroll
        for (int f = 0; f < 8; f++) {
            sa[f][0] = __expf(sa[f][0] - mn0);
            sa[f][1] = __expf(sa[f][1] - mn0);
            sa[f][2] = __expf(sa[f][2] - mn1);
            sa[f][3] = __expf(sa[f][3] - mn1);
            rs0 += sa[f][0] + sa[f][1];
            rs1 += sa[f][2] + sa[f][3];
        }
        rs0 += __shfl_xor_sync(0xffffffffu, rs0, 1);
        rs0 += __shfl_xor_sync(0xffffffffu, rs0, 2);
        rs1 += __shfl_xor_sync(0xffffffffu, rs1, 1);
        rs1 += __shfl_xor_sync(0xffffffffu, rs1, 2);

        l0 = l0 * f0 + rs0;  m0 = mn0;
        l1 = l1 * f1 + rs1;  m1 = mn1;
        #pragma unroll
        for (int f = 0; f < 8; f++) {
            oa[f][0] *= f0; oa[f][1] *= f0;
            oa[f][2] *= f1; oa[f][3] *= f1;
        }

        // ---- O += P @ V ----
        #pragma unroll
        for (int kc = 0; kc < 4; kc++) {
            uint32_t ah[4], al[4];
            split2(sa[2 * kc][0],     sa[2 * kc][1],     ah[0], al[0]);
            split2(sa[2 * kc][2],     sa[2 * kc][3],     ah[1], al[1]);
            split2(sa[2 * kc + 1][0], sa[2 * kc + 1][1], ah[2], al[2]);
            split2(sa[2 * kc + 1][2], sa[2 * kc + 1][3], ah[3], al[3]);
            #pragma unroll
            for (int g = 0; g < 4; g++) {
                uint32_t vh4[4], vl4[4];
                ldsm4(vh4, stg + 18432 + (b_n + g * 16) * QSTR + kc * 32 + b_kh * 16);
                ldsm4(vl4, stg + 27648 + (b_n + g * 16) * QSTR + kc * 32 + b_kh * 16);
                mma_bf16(oa[2 * g],     ah, &vh4[0]);
                mma_bf16(oa[2 * g + 1], ah, &vh4[2]);
                mma_bf16(oa[2 * g],     al, &vh4[0]);
                mma_bf16(oa[2 * g + 1], al, &vh4[2]);
                mma_bf16(oa[2 * g],     ah, &vl4[0]);
                mma_bf16(oa[2 * g + 1], ah, &vl4[2]);
            }
        }
    }

    // ---- epilogue: normalize, split, write Yh/Yl ----
    float inv0 = 1.f / l0, inv1 = 1.f / l1;
    size_t row0 = (size_t)(b * SEQ + qt * 128 + wm + (lane >> 2));
    #pragma unroll
    for (int f = 0; f < 8; f++) {
        int col = h * HD + f * 8 + (lane & 3) * 2;
        uint32_t hp, lp;
        split2(oa[f][0] * inv0, oa[f][1] * inv0, hp, lp);
        *(uint32_t*)&Yh[row0 * (NH * HD) + col] = hp;
        *(uint32_t*)&Yl[row0 * (NH * HD) + col] = lp;
        split2(oa[f][2] * inv1, oa[f][3] * inv1, hp, lp);
        *(uint32_t*)&Yh[(row0 + 8) * (NH * HD) + col] = hp;
        *(uint32_t*)&Yl[(row0 + 8) * (NH * HD) + col] = lp;
    }
}

// ---------------------------------------------------------------------------
extern "C" void kernel_launch(void* const* d_in, const int* in_sizes, int n_in,
                              void* d_out, int out_size) {
    const float* x  = (const float*)d_in[0];
    const float* Wq = (const float*)d_in[1];
    const float* Wk = (const float*)d_in[2];
    const float* Wv = (const float*)d_in[3];
    const float* Wo = (const float*)d_in[4];
    float* out = (float*)d_out;

    float *Qp, *Kp, *Vp;
    cudaGetSymbolAddress((void**)&Qp, g_Q);
    cudaGetSymbolAddress((void**)&Kp, g_K);
    cudaGetSymbolAddress((void**)&Vp, g_V);
    bf16 *xh, *xl, *Kh, *Kl, *Vth, *Vtl, *Yh, *Yl;
    bf16 *Wqh, *Wql, *Wkh, *Wkl, *Wvh, *Wvl, *Woh, *Wol;
    cudaGetSymbolAddress((void**)&xh, g_xh);   cudaGetSymbolAddress((void**)&xl, g_xl);
    cudaGetSymbolAddress((void**)&Kh, g_Kh);   cudaGetSymbolAddress((void**)&Kl, g_Kl);
    cudaGetSymbolAddress((void**)&Vth, g_Vth); cudaGetSymbolAddress((void**)&Vtl, g_Vtl);
    cudaGetSymbolAddress((void**)&Yh, g_Yh);   cudaGetSymbolAddress((void**)&Yl, g_Yl);
    cudaGetSymbolAddress((void**)&Wqh, g_Wqt_h); cudaGetSymbolAddress((void**)&Wql, g_Wqt_l);
    cudaGetSymbolAddress((void**)&Wkh, g_Wkt_h); cudaGetSymbolAddress((void**)&Wkl, g_Wkt_l);
    cudaGetSymbolAddress((void**)&Wvh, g_Wvt_h); cudaGetSymbolAddress((void**)&Wvl, g_Wvt_l);
    cudaGetSymbolAddress((void**)&Woh, g_Wot_h); cudaGetSymbolAddress((void**)&Wol, g_Wot_l);

    dim3 blk(256);

    rope_table<<<(SEQ * 32 + 255) / 256, blk>>>();

    int totx = ROWS * MODEL;
    split_rows<<<(totx + 255) / 256, blk>>>(x, xh, xl, totx);
    transpose_split<<<dim3((NH * HD) / 32, MODEL / 32), blk>>>(Wq, Wqh, Wql, MODEL, NH * HD);
    transpose_split<<<dim3(KVW / 32, MODEL / 32), blk>>>(Wk, Wkh, Wkl, MODEL, KVW);
    transpose_split<<<dim3(KVW / 32, MODEL / 32), blk>>>(Wv, Wvh, Wvl, MODEL, KVW);
    transpose_split<<<dim3(MODEL / 32, (NH * HD) / 32), blk>>>(Wo, Woh, Wol, NH * HD, MODEL);

    cudaFuncSetAttribute(gemm_mma, cudaFuncAttributeMaxDynamicSharedMemorySize, GEMM_SMEM);
    cudaFuncSetAttribute(gemm_mma_kv, cudaFuncAttributeMaxDynamicSharedMemorySize, GEMM_SMEM);
    gemm_mma<<<dim3((NH * HD) / 128, ROWS / 128), blk, GEMM_SMEM>>>(
        xh, xl, Wqh, Wql, Qp, NH * HD, MODEL);
    gemm_mma_kv<<<dim3(KVW / 128, ROWS / 128, 2), blk, GEMM_SMEM>>>(
        xh, xl, Wkh, Wkl, Wvh, Wvl, Kp, Vp, KVW, MODEL);

    // K: rope + split; V: transpose + split
    int totk = ROWS * NKV * 32;
    rope_split_k<<<(totk + 255) / 256, blk>>>(Kp, Kh, Kl);
    transpose_split_v<<<dim3(KVW / 32, ROWS / 32), blk>>>(Vp, Vth, Vtl);

    // flash attention (Q rope fused, bf16 KV, split-Y epilogue)
    cudaFuncSetAttribute(flashattn_mma, cudaFuncAttributeMaxDynamicSharedMemorySize, FA_SMEM);
    flashattn_mma<<<dim3(SEQ / 128, NH, BATCH), blk, FA_SMEM>>>(
        Qp, Kh, Kl, Vth, Vtl, Yh, Yl);

    // output projection
    gemm_mma<<<dim3(MODEL / 128, ROWS / 128), blk, GEMM_SMEM>>>(
        Yh, Yl, Woh, Wol, out, MODEL, MODEL);
}

// round 8
// speedup vs baseline: 3.0269x; 1.0221x over previous
#include <cuda_runtime.h>
#include <cuda_bf16.h>
#include <math.h>
#include <stdint.h>

#define BATCH 2
#define SEQ   2048
#define MODEL 2048
#define NH    32
#define NKV   8
#define HD    64
#define ROWS  (BATCH*SEQ)   // 4096
#define KVW   (NKV*HD)      // 512

typedef unsigned long long u64;
typedef __nv_bfloat16 bf16;

// ---------------- mma.sync helpers -----------------------------------------
__device__ __forceinline__ uint32_t smem_u32(const void* p) {
    uint32_t a;
    asm("{ .reg .u64 t; cvta.to.shared.u64 t, %1; cvt.u32.u64 %0, t; }" : "=r"(a) : "l"(p));
    return a;
}
__device__ __forceinline__ void ldsm4(uint32_t* r, uint32_t addr) {
    asm volatile("ldmatrix.sync.aligned.m8n8.x4.shared.b16 {%0,%1,%2,%3}, [%4];"
                 : "=r"(r[0]), "=r"(r[1]), "=r"(r[2]), "=r"(r[3]) : "r"(addr));
}
__device__ __forceinline__ void mma_bf16(float* d, const uint32_t* a, const uint32_t* b) {
    asm volatile("mma.sync.aligned.m16n8k16.row.col.f32.bf16.bf16.f32 "
                 "{%0,%1,%2,%3}, {%4,%5,%6,%7}, {%8,%9}, {%0,%1,%2,%3};"
                 : "+f"(d[0]), "+f"(d[1]), "+f"(d[2]), "+f"(d[3])
                 : "r"(a[0]), "r"(a[1]), "r"(a[2]), "r"(a[3]), "r"(b[0]), "r"(b[1]));
}
__device__ __forceinline__ void cp16(uint32_t dst, const void* src) {
    asm volatile("cp.async.cg.shared.global [%0], [%1], 16;" :: "r"(dst), "l"(src));
}
#define CP_COMMIT() asm volatile("cp.async.commit_group;" ::: "memory")
#define CP_WAIT1()  asm volatile("cp.async.wait_group 1;" ::: "memory")

// bf16x2 pack/split: lo float -> bits[15:0], hi float -> bits[31:16]
__device__ __forceinline__ uint32_t pkbf2(float lo, float hi) {
    uint32_t r; asm("cvt.rn.bf16x2.f32 %0, %1, %2;" : "=r"(r) : "f"(hi), "f"(lo)); return r;
}
__device__ __forceinline__ float bflo(uint32_t p) { return __uint_as_float(p << 16); }
__device__ __forceinline__ float bfhi(uint32_t p) { return __uint_as_float(p & 0xffff0000u); }
__device__ __forceinline__ void split2(float f0, float f1, uint32_t& hp, uint32_t& lp) {
    hp = pkbf2(f0, f1);
    lp = pkbf2(f0 - bflo(hp), f1 - bfhi(hp));
}

// ---------------- scratch --------------------------------------------------
__device__ float g_Q[(size_t)ROWS * NH  * HD];
__device__ float g_K[(size_t)ROWS * KVW];
__device__ float g_V[(size_t)ROWS * KVW];
__device__ float g_cs[(size_t)SEQ * 32 * 2];

__device__ bf16 g_xh[(size_t)ROWS * MODEL];
__device__ bf16 g_xl[(size_t)ROWS * MODEL];
__device__ bf16 g_Kh[(size_t)ROWS * KVW];
__device__ bf16 g_Kl[(size_t)ROWS * KVW];
__device__ bf16 g_Vth[(size_t)BATCH * KVW * SEQ];
__device__ bf16 g_Vtl[(size_t)BATCH * KVW * SEQ];
__device__ bf16 g_Yh[(size_t)ROWS * NH * HD];
__device__ bf16 g_Yl[(size_t)ROWS * NH * HD];
__device__ bf16 g_Wqt_h[(size_t)(NH  * HD) * MODEL];
__device__ bf16 g_Wqt_l[(size_t)(NH  * HD) * MODEL];
__device__ bf16 g_Wkt_h[(size_t)KVW * MODEL];
__device__ bf16 g_Wkt_l[(size_t)KVW * MODEL];
__device__ bf16 g_Wvt_h[(size_t)KVW * MODEL];
__device__ bf16 g_Wvt_l[(size_t)KVW * MODEL];
__device__ bf16 g_Wot_h[(size_t)MODEL * (NH * HD)];
__device__ bf16 g_Wot_l[(size_t)MODEL * (NH * HD)];

// ---------------------------------------------------------------------------
// RoPE cos/sin table (fp64 trig once)
// ---------------------------------------------------------------------------
__global__ __launch_bounds__(256)
void rope_table() {
    int i = blockIdx.x * 256 + threadIdx.x;
    if (i >= SEQ * 32) return;
    int d = i & 31;
    int s = i >> 5;
    double inv = exp2(-(double)d * (13.287712379549448882 / 32.0));
    double ang = (double)s * inv;
    double sd, cd;
    sincos(ang, &sd, &cd);
    g_cs[2 * i + 0] = (float)cd;
    g_cs[2 * i + 1] = (float)sd;
}

// ---------------------------------------------------------------------------
// K: rope + split fp32 -> bf16 hi/lo
// ---------------------------------------------------------------------------
__global__ __launch_bounds__(256)
void rope_split_k(const float* __restrict__ Kf, bf16* __restrict__ Kh,
                  bf16* __restrict__ Kl) {
    int i = blockIdx.x * 256 + threadIdx.x;
    if (i >= ROWS * NKV * 32) return;
    int d   = i & 31;
    int kvh = (i >> 5) & 7;
    int row = i >> 8;
    int s   = row & (SEQ - 1);
    float2 cs = *(const float2*)&g_cs[2 * (s * 32 + d)];
    size_t off = (size_t)row * KVW + kvh * 64 + d;
    float q0 = Kf[off];
    float q1 = Kf[off + 32];
    float r0 = q0 * cs.x - q1 * cs.y;
    float r1 = q1 * cs.x + q0 * cs.y;
    bf16 h0 = __float2bfloat16(r0);
    bf16 h1 = __float2bfloat16(r1);
    Kh[off]      = h0;
    Kh[off + 32] = h1;
    Kl[off]      = __float2bfloat16(r0 - __bfloat162float(h0));
    Kl[off + 32] = __float2bfloat16(r1 - __bfloat162float(h1));
}

// ---------------------------------------------------------------------------
// V: transpose + split
// ---------------------------------------------------------------------------
__global__ __launch_bounds__(256)
void transpose_split_v(const float* __restrict__ V, bf16* __restrict__ Th,
                       bf16* __restrict__ Tl) {
    __shared__ float tile[32][33];
    int n0 = blockIdx.x * 32;
    int k0 = blockIdx.y * 32;
    int tx = threadIdx.x & 31, ty = threadIdx.x >> 5;
    #pragma unroll
    for (int j = ty; j < 32; j += 8)
        tile[j][tx] = V[(size_t)(k0 + j) * KVW + n0 + tx];
    __syncthreads();
    int b = k0 >> 11;
    int s = (k0 & (SEQ - 1)) + tx;
    #pragma unroll
    for (int j = ty; j < 32; j += 8) {
        int c = n0 + j;
        int out_r = (b * NKV + (c >> 6)) * 64 + (c & 63);
        float v = tile[tx][j];
        bf16 h = __float2bfloat16(v);
        Th[(size_t)out_r * SEQ + s] = h;
        Tl[(size_t)out_r * SEQ + s] = __float2bfloat16(v - __bfloat162float(h));
    }
}

// ---------------------------------------------------------------------------
// split fp32 -> (hi, lo) bf16
// ---------------------------------------------------------------------------
__global__ __launch_bounds__(256)
void split_rows(const float* __restrict__ X, bf16* __restrict__ H,
                bf16* __restrict__ L, int total) {
    int i = blockIdx.x * 256 + threadIdx.x;
    if (i >= total) return;
    float v = X[i];
    bf16 h = __float2bfloat16(v);
    H[i] = h;
    L[i] = __float2bfloat16(v - __bfloat162float(h));
}

// ---------------------------------------------------------------------------
// transpose + split weights
// ---------------------------------------------------------------------------
__global__ __launch_bounds__(256)
void transpose_split(const float* __restrict__ W, bf16* __restrict__ Th,
                     bf16* __restrict__ Tl, int Kd, int Nw) {
    __shared__ float tile[32][33];
    int n0 = blockIdx.x * 32, k0 = blockIdx.y * 32;
    int tx = threadIdx.x & 31, ty = threadIdx.x >> 5;
    #pragma unroll
    for (int j = ty; j < 32; j += 8)
        tile[j][tx] = W[(size_t)(k0 + j) * Nw + n0 + tx];
    __syncthreads();
    #pragma unroll
    for (int j = ty; j < 32; j += 8) {
        float v = tile[tx][j];
        bf16 h = __float2bfloat16(v);
        Th[(size_t)(n0 + j) * Kd + k0 + tx] = h;
        Tl[(size_t)(n0 + j) * Kd + k0 + tx] = __float2bfloat16(v - __bfloat162float(h));
    }
}

// ---------------------------------------------------------------------------
// Split-bf16 tensor-core GEMM (proven, unchanged).
// ---------------------------------------------------------------------------
#define GSTAGE 32768
#define GEMM_SMEM (2 * GSTAGE)

__device__ __forceinline__ void g_load_stage(char* base, uint32_t sbase,
                                             const bf16* Ah, const bf16* Al,
                                             const bf16* Bh, const bf16* Bl,
                                             int bm, int bn, int kb, int K, int tid) {
    #pragma unroll
    for (int it = 0; it < 4; it++) {
        int idx = tid + it * 256;
        int r = idx >> 3, c = idx & 7;
        uint32_t dst = sbase + r * 128 + ((c ^ (r & 7)) << 4);
        const bf16* src = (c < 4 ? Ah : Al) + (size_t)(bm + r) * K + kb * 32 + (c & 3) * 8;
        cp16(dst, src);
    }
    #pragma unroll
    for (int it = 0; it < 4; it++) {
        int idx = tid + it * 256;
        int r = idx >> 3, c = idx & 7;
        uint32_t dst = sbase + 16384 + r * 128 + ((c ^ (r & 7)) << 4);
        const bf16* src = (c < 4 ? Bh : Bl) + (size_t)(bn + r) * K + kb * 32 + (c & 3) * 8;
        cp16(dst, src);
    }
}

__device__ __forceinline__
void gemm_mma_core(const bf16* __restrict__ Ah, const bf16* __restrict__ Al,
                   const bf16* __restrict__ Bh, const bf16* __restrict__ Bl,
                   float* __restrict__ C, int Nt, int K, int bm, int bn) {
    extern __shared__ char smg[];
    const uint32_t sbase = smem_u32(smg);
    const int tid  = threadIdx.x;
    const int lane = tid & 31;
    const int warp = tid >> 5;
    const int wm   = (warp & 3) * 32;
    const int wn   = (warp >> 2) * 64;

    float acc[2][8][4];
    #pragma unroll
    for (int am = 0; am < 2; am++)
        #pragma unroll
        for (int an = 0; an < 8; an++)
            #pragma unroll
            for (int j = 0; j < 4; j++) acc[am][an][j] = 0.f;

    const int KB = K >> 5;
    g_load_stage(smg, sbase,           Ah, Al, Bh, Bl, bm, bn, 0, K, tid); CP_COMMIT();
    g_load_stage(smg, sbase + GSTAGE,  Ah, Al, Bh, Bl, bm, bn, 1, K, tid); CP_COMMIT();

    const int a_row  = wm + (lane & 15);
    const int a_kh   = (lane >> 4) & 1;
    const int b_n    = wn + (lane & 7) + ((lane >> 4) << 3);
    const int b_kh   = (lane >> 3) & 1;

    for (int t = 0; t < KB; t++) {
        CP_WAIT1();
        __syncthreads();
        const uint32_t sA = sbase + (t & 1) * GSTAGE;
        const uint32_t sB = sA + 16384;

        #pragma unroll
        for (int h = 0; h < 2; h++) {
            uint32_t bh[4][4], bl[4][4];
            #pragma unroll
            for (int g = 0; g < 4; g++) {
                int n = b_n + g * 16;
                int ch = h * 2 + b_kh;
                ldsm4(bh[g], sB + n * 128 + (((ch)     ^ (n & 7)) << 4));
                ldsm4(bl[g], sB + n * 128 + (((ch + 4) ^ (n & 7)) << 4));
            }
            #pragma unroll
            for (int am = 0; am < 2; am++) {
                int r  = a_row + am * 16;
                int ch = h * 2 + a_kh;
                uint32_t ah[4], al[4];
                ldsm4(ah, sA + r * 128 + (((ch)     ^ (r & 7)) << 4));
                ldsm4(al, sA + r * 128 + (((ch + 4) ^ (r & 7)) << 4));
                #pragma unroll
                for (int g = 0; g < 4; g++) {
                    mma_bf16(acc[am][2 * g],     ah, &bh[g][0]);
                    mma_bf16(acc[am][2 * g + 1], ah, &bh[g][2]);
                    mma_bf16(acc[am][2 * g],     al, &bh[g][0]);
                    mma_bf16(acc[am][2 * g + 1], al, &bh[g][2]);
                    mma_bf16(acc[am][2 * g],     ah, &bl[g][0]);
                    mma_bf16(acc[am][2 * g + 1], ah, &bl[g][2]);
                }
            }
        }
        __syncthreads();
        if (t + 2 < KB) {
            g_load_stage(smg + (t & 1) * GSTAGE, sA, Ah, Al, Bh, Bl, bm, bn, t + 2, K, tid);
        }
        CP_COMMIT();
    }

    #pragma unroll
    for (int am = 0; am < 2; am++) {
        int r0 = bm + wm + am * 16 + (lane >> 2);
        #pragma unroll
        for (int an = 0; an < 8; an++) {
            int col = bn + wn + an * 8 + (lane & 3) * 2;
            *(float2*)&C[(size_t)r0 * Nt + col]       = make_float2(acc[am][an][0], acc[am][an][1]);
            *(float2*)&C[(size_t)(r0 + 8) * Nt + col] = make_float2(acc[am][an][2], acc[am][an][3]);
        }
    }
}

__global__ __launch_bounds__(256, 2)
void gemm_mma(const bf16* __restrict__ Ah, const bf16* __restrict__ Al,
              const bf16* __restrict__ Bh, const bf16* __restrict__ Bl,
              float* __restrict__ C, int Nt, int K) {
    gemm_mma_core(Ah, Al, Bh, Bl, C, Nt, K, blockIdx.y * 128, blockIdx.x * 128);
}

__global__ __launch_bounds__(256, 2)
void gemm_mma_kv(const bf16* __restrict__ Ah, const bf16* __restrict__ Al,
                 const bf16* __restrict__ Bkh, const bf16* __restrict__ Bkl,
                 const bf16* __restrict__ Bvh, const bf16* __restrict__ Bvl,
                 float* __restrict__ Ck, float* __restrict__ Cv, int Nt, int K) {
    const bf16* Bh = blockIdx.z ? Bvh : Bkh;
    const bf16* Bl = blockIdx.z ? Bvl : Bkl;
    float* C = blockIdx.z ? Cv : Ck;
    gemm_mma_core(Ah, Al, Bh, Bl, C, Nt, K, blockIdx.y * 128, blockIdx.x * 128);
}

// ---------------------------------------------------------------------------
// Tensor-core flash attention v3:
//  - Q smem region OVERLAPS KV stage 1 (Q frags live in regs after prologue)
//    -> FA_SMEM 73728, 2 CTAs/SM
//  - exp2-based softmax (log2e folded into Q scale)
// smem layout: [stage0: 36864][stage1 / Q hi+lo: 36864]
// ---------------------------------------------------------------------------
#define QSTR 144
#define FA_STG_SZ 36864
#define FA_SQH 36864
#define FA_SQL 55296
#define FA_SMEM 73728

__device__ __forceinline__
void fa_load_kv(uint32_t sb, const bf16* __restrict__ Khp, const bf16* __restrict__ Klp,
                const bf16* __restrict__ Vhp, const bf16* __restrict__ Vlp,
                size_t krow0, int s0, int tid) {
    #pragma unroll
    for (int i = 0; i < 2; i++) {
        int idx = tid + i * 256;
        int r = idx >> 3, c = idx & 7;
        uint32_t so = r * QSTR + c * 16;
        cp16(sb + so,         Khp + (krow0 + r) * KVW + c * 8);
        cp16(sb + 9216 + so,  Klp + (krow0 + r) * KVW + c * 8);
        cp16(sb + 18432 + so, Vhp + (size_t)r * SEQ + s0 + c * 8);
        cp16(sb + 27648 + so, Vlp + (size_t)r * SEQ + s0 + c * 8);
    }
}

__global__ __launch_bounds__(256, 2)
void flashattn_mma(const float* __restrict__ Q, const bf16* __restrict__ Kh,
                   const bf16* __restrict__ Kl, const bf16* __restrict__ Vth,
                   const bf16* __restrict__ Vtl,
                   bf16* __restrict__ Yh, bf16* __restrict__ Yl) {
    extern __shared__ char sm[];
    const uint32_t base = smem_u32(sm);
    const int tid  = threadIdx.x;
    const int lane = tid & 31;
    const int warp = tid >> 5;
    const int qt   = gridDim.x - 1 - blockIdx.x;
    const int h    = blockIdx.y;
    const int b    = blockIdx.z;
    const int kvh  = h >> 2;
    const int wm   = warp * 16;

    const bf16* Khp = Kh + kvh * 64;
    const bf16* Klp = Kl + kvh * 64;
    const bf16* Vhp = Vth + (size_t)((b * NKV + kvh) * 64) * SEQ;
    const bf16* Vlp = Vtl + (size_t)((b * NKV + kvh) * 64) * SEQ;
    const int njt = 2 * qt + 2;

    // prefetch first KV tile into stage0
    fa_load_kv(base, Khp, Klp, Vhp, Vlp, (size_t)b * SEQ, 0, tid);
    CP_COMMIT();

    // ---- Q load into stage-1 footprint: rope -> *scale -> split bf16 ----
    // scale = 1/sqrt(64) * log2(e): softmax computed base-2 (exact rescale).
    const float QSC = 0.125f * 1.4426950408889634f;
    {
        const float* Qg = Q + ((size_t)(b * SEQ + qt * 128)) * (NH * HD) + h * HD;
        #pragma unroll
        for (int i = 0; i < 4; i++) {
            int idx = tid + i * 256;
            int r  = idx >> 3;
            int c4 = idx & 7;
            int d0 = c4 * 4;
            int s  = qt * 128 + r;
            float4 q0 = *(const float4*)(Qg + (size_t)r * (NH * HD) + d0);
            float4 q1 = *(const float4*)(Qg + (size_t)r * (NH * HD) + 32 + d0);
            float4 csA = *(const float4*)&g_cs[2 * (s * 32 + d0)];
            float4 csB = *(const float4*)&g_cs[2 * (s * 32 + d0 + 2)];
            float lo0 = (q0.x * csA.x - q1.x * csA.y) * QSC;
            float lo1 = (q0.y * csA.z - q1.y * csA.w) * QSC;
            float lo2 = (q0.z * csB.x - q1.z * csB.y) * QSC;
            float lo3 = (q0.w * csB.z - q1.w * csB.w) * QSC;
            float hi0 = (q1.x * csA.x + q0.x * csA.y) * QSC;
            float hi1 = (q1.y * csA.z + q0.y * csA.w) * QSC;
            float hi2 = (q1.z * csB.x + q0.z * csB.y) * QSC;
            float hi3 = (q1.w * csB.z + q0.w * csB.w) * QSC;
            uint32_t hA, lA, hB, lB;
            split2(lo0, lo1, hA, lA);
            split2(lo2, lo3, hB, lB);
            *(uint2*)(sm + FA_SQH + r * QSTR + d0 * 2) = make_uint2(hA, hB);
            *(uint2*)(sm + FA_SQL + r * QSTR + d0 * 2) = make_uint2(lA, lB);
            split2(hi0, hi1, hA, lA);
            split2(hi2, hi3, hB, lB);
            *(uint2*)(sm + FA_SQH + r * QSTR + 64 + d0 * 2) = make_uint2(hA, hB);
            *(uint2*)(sm + FA_SQL + r * QSTR + 64 + d0 * 2) = make_uint2(lA, lB);
        }
    }
    __syncthreads();

    // ---- Q fragments to registers (then Q smem is dead -> becomes stage1) ----
    const int a_row = wm + (lane & 15);
    const int a_kh  = (lane >> 4) & 1;
    uint32_t qh[4][4], ql[4][4];
    #pragma unroll
    for (int kc = 0; kc < 4; kc++) {
        ldsm4(qh[kc], base + FA_SQH + a_row * QSTR + kc * 32 + a_kh * 16);
        ldsm4(ql[kc], base + FA_SQL + a_row * QSTR + kc * 32 + a_kh * 16);
    }

    const int b_n  = (lane & 7) + ((lane >> 4) << 3);
    const int b_kh = (lane >> 3) & 1;

    float m0 = -INFINITY, m1 = -INFINITY, l0 = 0.f, l1 = 0.f;
    float oa[8][4];
    #pragma unroll
    for (int f = 0; f < 8; f++)
        #pragma unroll
        for (int j = 0; j < 4; j++) oa[f][j] = 0.f;

    for (int jt = 0; jt < njt; jt++) {
        const uint32_t stg = base + (jt & 1) * FA_STG_SZ;

        __syncthreads();   // all warps done with the other stage (and Q frags @ jt=0)
        if (jt + 1 < njt) {
            fa_load_kv(base + ((jt + 1) & 1) * FA_STG_SZ,
                       Khp, Klp, Vhp, Vlp,
                       (size_t)b * SEQ + (jt + 1) * 64, (jt + 1) * 64, tid);
        }
        CP_COMMIT();
        CP_WAIT1();
        __syncthreads();

        // ---- S = Q @ K^T (base-2 scaled) ----
        float sa[8][4];
        #pragma unroll
        for (int f = 0; f < 8; f++)
            #pragma unroll
            for (int j = 0; j < 4; j++) sa[f][j] = 0.f;

        #pragma unroll
        for (int kc = 0; kc < 4; kc++) {
            #pragma unroll
            for (int g = 0; g < 4; g++) {
                uint32_t kh4[4], kl4[4];
                ldsm4(kh4, stg + (b_n + g * 16) * QSTR + kc * 32 + b_kh * 16);
                ldsm4(kl4, stg + 9216 + (b_n + g * 16) * QSTR + kc * 32 + b_kh * 16);
                mma_bf16(sa[2 * g],     qh[kc], &kh4[0]);
                mma_bf16(sa[2 * g + 1], qh[kc], &kh4[2]);
                mma_bf16(sa[2 * g],     ql[kc], &kh4[0]);
                mma_bf16(sa[2 * g + 1], ql[kc], &kh4[2]);
                mma_bf16(sa[2 * g],     qh[kc], &kl4[0]);
                mma_bf16(sa[2 * g + 1], qh[kc], &kl4[2]);
            }
        }

        // ---- causal mask ----
        if (jt * 64 + 63 > qt * 128) {
            int r0g = qt * 128 + wm + (lane >> 2);
            int r1g = r0g + 8;
            #pragma unroll
            for (int f = 0; f < 8; f++) {
                int c0 = jt * 64 + f * 8 + (lane & 3) * 2;
                if (c0 > r0g)     sa[f][0] = -INFINITY;
                if (c0 + 1 > r0g) sa[f][1] = -INFINITY;
                if (c0 > r1g)     sa[f][2] = -INFINITY;
                if (c0 + 1 > r1g) sa[f][3] = -INFINITY;
            }
        }

        // ---- online softmax (base 2) ----
        float rm0 = -INFINITY, rm1 = -INFINITY;
        #pragma unroll
        for (int f = 0; f < 8; f++) {
            rm0 = fmaxf(rm0, fmaxf(sa[f][0], sa[f][1]));
            rm1 = fmaxf(rm1, fmaxf(sa[f][2], sa[f][3]));
        }
        rm0 = fmaxf(rm0, __shfl_xor_sync(0xffffffffu, rm0, 1));
        rm0 = fmaxf(rm0, __shfl_xor_sync(0xffffffffu, rm0, 2));
        rm1 = fmaxf(rm1, __shfl_xor_sync(0xffffffffu, rm1, 1));
        rm1 = fmaxf(rm1, __shfl_xor_sync(0xffffffffu, rm1, 2));

        float mn0 = fmaxf(m0, rm0), mn1 = fmaxf(m1, rm1);
        float f0 = exp2f(m0 - mn0), f1 = exp2f(m1 - mn1);
        float rs0 = 0.f, rs1 = 0.f;
        #pragma unroll
        for (int f = 0; f < 8; f++) {
            sa[f][0] = exp2f(sa[f][0] - mn0);
            sa[f][1] = exp2f(sa[f][1] - mn0);
            sa[f][2] = exp2f(sa[f][2] - mn1);
            sa[f][3] = exp2f(sa[f][3] - mn1);
            rs0 += sa[f][0] + sa[f][1];
            rs1 += sa[f][2] + sa[f][3];
        }
        rs0 += __shfl_xor_sync(0xffffffffu, rs0, 1);
        rs0 += __shfl_xor_sync(0xffffffffu, rs0, 2);
        rs1 += __shfl_xor_sync(0xffffffffu, rs1, 1);
        rs1 += __shfl_xor_sync(0xffffffffu, rs1, 2);

        l0 = l0 * f0 + rs0;  m0 = mn0;
        l1 = l1 * f1 + rs1;  m1 = mn1;
        #pragma unroll
        for (int f = 0; f < 8; f++) {
            oa[f][0] *= f0; oa[f][1] *= f0;
            oa[f][2] *= f1; oa[f][3] *= f1;
        }

        // ---- O += P @ V ----
        #pragma unroll
        for (int kc = 0; kc < 4; kc++) {
            uint32_t ah[4], al[4];
            split2(sa[2 * kc][0],     sa[2 * kc][1],     ah[0], al[0]);
            split2(sa[2 * kc][2],     sa[2 * kc][3],     ah[1], al[1]);
            split2(sa[2 * kc + 1][0], sa[2 * kc + 1][1], ah[2], al[2]);
            split2(sa[2 * kc + 1][2], sa[2 * kc + 1][3], ah[3], al[3]);
            #pragma unroll
            for (int g = 0; g < 4; g++) {
                uint32_t vh4[4], vl4[4];
                ldsm4(vh4, stg + 18432 + (b_n + g * 16) * QSTR + kc * 32 + b_kh * 16);
                ldsm4(vl4, stg + 27648 + (b_n + g * 16) * QSTR + kc * 32 + b_kh * 16);
                mma_bf16(oa[2 * g],     ah, &vh4[0]);
                mma_bf16(oa[2 * g + 1], ah, &vh4[2]);
                mma_bf16(oa[2 * g],     al, &vh4[0]);
                mma_bf16(oa[2 * g + 1], al, &vh4[2]);
                mma_bf16(oa[2 * g],     ah, &vl4[0]);
                mma_bf16(oa[2 * g + 1], ah, &vl4[2]);
            }
        }
    }

    // ---- epilogue: normalize, split, write Yh/Yl ----
    float inv0 = 1.f / l0, inv1 = 1.f / l1;
    size_t row0 = (size_t)(b * SEQ + qt * 128 + wm + (lane >> 2));
    #pragma unroll
    for (int f = 0; f < 8; f++) {
        int col = h * HD + f * 8 + (lane & 3) * 2;
        uint32_t hp, lp;
        split2(oa[f][0] * inv0, oa[f][1] * inv0, hp, lp);
        *(uint32_t*)&Yh[row0 * (NH * HD) + col] = hp;
        *(uint32_t*)&Yl[row0 * (NH * HD) + col] = lp;
        split2(oa[f][2] * inv1, oa[f][3] * inv1, hp, lp);
        *(uint32_t*)&Yh[(row0 + 8) * (NH * HD) + col] = hp;
        *(uint32_t*)&Yl[(row0 + 8) * (NH * HD) + col] = lp;
    }
}

// ---------------------------------------------------------------------------
extern "C" void kernel_launch(void* const* d_in, const int* in_sizes, int n_in,
                              void* d_out, int out_size) {
    const float* x  = (const float*)d_in[0];
    const float* Wq = (const float*)d_in[1];
    const float* Wk = (const float*)d_in[2];
    const float* Wv = (const float*)d_in[3];
    const float* Wo = (const float*)d_in[4];
    float* out = (float*)d_out;

    float *Qp, *Kp, *Vp;
    cudaGetSymbolAddress((void**)&Qp, g_Q);
    cudaGetSymbolAddress((void**)&Kp, g_K);
    cudaGetSymbolAddress((void**)&Vp, g_V);
    bf16 *xh, *xl, *Kh, *Kl, *Vth, *Vtl, *Yh, *Yl;
    bf16 *Wqh, *Wql, *Wkh, *Wkl, *Wvh, *Wvl, *Woh, *Wol;
    cudaGetSymbolAddress((void**)&xh, g_xh);   cudaGetSymbolAddress((void**)&xl, g_xl);
    cudaGetSymbolAddress((void**)&Kh, g_Kh);   cudaGetSymbolAddress((void**)&Kl, g_Kl);
    cudaGetSymbolAddress((void**)&Vth, g_Vth); cudaGetSymbolAddress((void**)&Vtl, g_Vtl);
    cudaGetSymbolAddress((void**)&Yh, g_Yh);   cudaGetSymbolAddress((void**)&Yl, g_Yl);
    cudaGetSymbolAddress((void**)&Wqh, g_Wqt_h); cudaGetSymbolAddress((void**)&Wql, g_Wqt_l);
    cudaGetSymbolAddress((void**)&Wkh, g_Wkt_h); cudaGetSymbolAddress((void**)&Wkl, g_Wkt_l);
    cudaGetSymbolAddress((void**)&Wvh, g_Wvt_h); cudaGetSymbolAddress((void**)&Wvl, g_Wvt_l);
    cudaGetSymbolAddress((void**)&Woh, g_Wot_h); cudaGetSymbolAddress((void**)&Wol, g_Wot_l);

    dim3 blk(256);

    rope_table<<<(SEQ * 32 + 255) / 256, blk>>>();

    int totx = ROWS * MODEL;
    split_rows<<<(totx + 255) / 256, blk>>>(x, xh, xl, totx);
    transpose_split<<<dim3((NH * HD) / 32, MODEL / 32), blk>>>(Wq, Wqh, Wql, MODEL, NH * HD);
    transpose_split<<<dim3(KVW / 32, MODEL / 32), blk>>>(Wk, Wkh, Wkl, MODEL, KVW);
    transpose_split<<<dim3(KVW / 32, MODEL / 32), blk>>>(Wv, Wvh, Wvl, MODEL, KVW);
    transpose_split<<<dim3(MODEL / 32, (NH * HD) / 32), blk>>>(Wo, Woh, Wol, NH * HD, MODEL);

    cudaFuncSetAttribute(gemm_mma, cudaFuncAttributeMaxDynamicSharedMemorySize, GEMM_SMEM);
    cudaFuncSetAttribute(gemm_mma_kv, cudaFuncAttributeMaxDynamicSharedMemorySize, GEMM_SMEM);
    gemm_mma<<<dim3((NH * HD) / 128, ROWS / 128), blk, GEMM_SMEM>>>(
        xh, xl, Wqh, Wql, Qp, NH * HD, MODEL);
    gemm_mma_kv<<<dim3(KVW / 128, ROWS / 128, 2), blk, GEMM_SMEM>>>(
        xh, xl, Wkh, Wkl, Wvh, Wvl, Kp, Vp, KVW, MODEL);

    int totk = ROWS * NKV * 32;
    rope_split_k<<<(totk + 255) / 256, blk>>>(Kp, Kh, Kl);
    transpose_split_v<<<dim3(KVW / 32, ROWS / 32), blk>>>(Vp, Vth, Vtl);

    cudaFuncSetAttribute(flashattn_mma, cudaFuncAttributeMaxDynamicSharedMemorySize, FA_SMEM);
    flashattn_mma<<<dim3(SEQ / 128, NH, BATCH), blk, FA_SMEM>>>(
        Qp, Kh, Kl, Vth, Vtl, Yh, Yl);

    gemm_mma<<<dim3(MODEL / 128, ROWS / 128), blk, GEMM_SMEM>>>(
        Yh, Yl, Woh, Wol, out, MODEL, MODEL);
}

// round 9
// speedup vs baseline: 3.0476x; 1.0068x over previous
#include <cuda_runtime.h>
#include <cuda_bf16.h>
#include <math.h>
#include <stdint.h>

#define BATCH 2
#define SEQ   2048
#define MODEL 2048
#define NH    32
#define NKV   8
#define HD    64
#define ROWS  (BATCH*SEQ)   // 4096
#define KVW   (NKV*HD)      // 512

typedef unsigned long long u64;
typedef __nv_bfloat16 bf16;

// ---------------- mma.sync helpers -----------------------------------------
__device__ __forceinline__ uint32_t smem_u32(const void* p) {
    uint32_t a;
    asm("{ .reg .u64 t; cvta.to.shared.u64 t, %1; cvt.u32.u64 %0, t; }" : "=r"(a) : "l"(p));
    return a;
}
__device__ __forceinline__ void ldsm4(uint32_t* r, uint32_t addr) {
    asm volatile("ldmatrix.sync.aligned.m8n8.x4.shared.b16 {%0,%1,%2,%3}, [%4];"
                 : "=r"(r[0]), "=r"(r[1]), "=r"(r[2]), "=r"(r[3]) : "r"(addr));
}
__device__ __forceinline__ void mma_bf16(float* d, const uint32_t* a, const uint32_t* b) {
    asm volatile("mma.sync.aligned.m16n8k16.row.col.f32.bf16.bf16.f32 "
                 "{%0,%1,%2,%3}, {%4,%5,%6,%7}, {%8,%9}, {%0,%1,%2,%3};"
                 : "+f"(d[0]), "+f"(d[1]), "+f"(d[2]), "+f"(d[3])
                 : "r"(a[0]), "r"(a[1]), "r"(a[2]), "r"(a[3]), "r"(b[0]), "r"(b[1]));
}
__device__ __forceinline__ void cp16(uint32_t dst, const void* src) {
    asm volatile("cp.async.cg.shared.global [%0], [%1], 16;" :: "r"(dst), "l"(src));
}
#define CP_COMMIT() asm volatile("cp.async.commit_group;" ::: "memory")
#define CP_WAIT1()  asm volatile("cp.async.wait_group 1;" ::: "memory")

// bf16x2 pack/split: lo float -> bits[15:0], hi float -> bits[31:16]
__device__ __forceinline__ uint32_t pkbf2(float lo, float hi) {
    uint32_t r; asm("cvt.rn.bf16x2.f32 %0, %1, %2;" : "=r"(r) : "f"(hi), "f"(lo)); return r;
}
__device__ __forceinline__ float bflo(uint32_t p) { return __uint_as_float(p << 16); }
__device__ __forceinline__ float bfhi(uint32_t p) { return __uint_as_float(p & 0xffff0000u); }
__device__ __forceinline__ void split2(float f0, float f1, uint32_t& hp, uint32_t& lp) {
    hp = pkbf2(f0, f1);
    lp = pkbf2(f0 - bflo(hp), f1 - bfhi(hp));
}

// ---------------- scratch --------------------------------------------------
__device__ float g_V[(size_t)ROWS * KVW];
__device__ float g_cs[(size_t)SEQ * 32 * 2];

__device__ bf16 g_xh[(size_t)ROWS * MODEL];
__device__ bf16 g_xl[(size_t)ROWS * MODEL];
__device__ bf16 g_Qh[(size_t)ROWS * NH * HD];    // rope+scale applied, split
__device__ bf16 g_Ql[(size_t)ROWS * NH * HD];
__device__ bf16 g_Kh[(size_t)ROWS * KVW];        // rope applied, split
__device__ bf16 g_Kl[(size_t)ROWS * KVW];
__device__ bf16 g_Vth[(size_t)BATCH * KVW * SEQ];  // transposed [(b,kvh,d)][s]
__device__ bf16 g_Vtl[(size_t)BATCH * KVW * SEQ];
__device__ bf16 g_Yh[(size_t)ROWS * NH * HD];
__device__ bf16 g_Yl[(size_t)ROWS * NH * HD];
__device__ bf16 g_Wqt_h[(size_t)(NH  * HD) * MODEL];
__device__ bf16 g_Wqt_l[(size_t)(NH  * HD) * MODEL];
__device__ bf16 g_Wkt_h[(size_t)KVW * MODEL];
__device__ bf16 g_Wkt_l[(size_t)KVW * MODEL];
__device__ bf16 g_Wvt_h[(size_t)KVW * MODEL];
__device__ bf16 g_Wvt_l[(size_t)KVW * MODEL];
__device__ bf16 g_Wot_h[(size_t)MODEL * (NH * HD)];
__device__ bf16 g_Wot_l[(size_t)MODEL * (NH * HD)];

// ---------------------------------------------------------------------------
// RoPE cos/sin table (fp64 trig once)
// ---------------------------------------------------------------------------
__global__ __launch_bounds__(256)
void rope_table() {
    int i = blockIdx.x * 256 + threadIdx.x;
    if (i >= SEQ * 32) return;
    int d = i & 31;
    int s = i >> 5;
    double inv = exp2(-(double)d * (13.287712379549448882 / 32.0));
    double ang = (double)s * inv;
    double sd, cd;
    sincos(ang, &sd, &cd);
    g_cs[2 * i + 0] = (float)cd;
    g_cs[2 * i + 1] = (float)sd;
}

// ---------------------------------------------------------------------------
// V: transpose + split
// ---------------------------------------------------------------------------
__global__ __launch_bounds__(256)
void transpose_split_v(const float* __restrict__ V, bf16* __restrict__ Th,
                       bf16* __restrict__ Tl) {
    __shared__ float tile[32][33];
    int n0 = blockIdx.x * 32;
    int k0 = blockIdx.y * 32;
    int tx = threadIdx.x & 31, ty = threadIdx.x >> 5;
    #pragma unroll
    for (int j = ty; j < 32; j += 8)
        tile[j][tx] = V[(size_t)(k0 + j) * KVW + n0 + tx];
    __syncthreads();
    int b = k0 >> 11;
    int s = (k0 & (SEQ - 1)) + tx;
    #pragma unroll
    for (int j = ty; j < 32; j += 8) {
        int c = n0 + j;
        int out_r = (b * NKV + (c >> 6)) * 64 + (c & 63);
        float v = tile[tx][j];
        bf16 h = __float2bfloat16(v);
        Th[(size_t)out_r * SEQ + s] = h;
        Tl[(size_t)out_r * SEQ + s] = __float2bfloat16(v - __bfloat162float(h));
    }
}

// ---------------------------------------------------------------------------
// split fp32 -> (hi, lo) bf16
// ---------------------------------------------------------------------------
__global__ __launch_bounds__(256)
void split_rows(const float* __restrict__ X, bf16* __restrict__ H,
                bf16* __restrict__ L, int total) {
    int i = blockIdx.x * 256 + threadIdx.x;
    if (i >= total) return;
    float v = X[i];
    bf16 h = __float2bfloat16(v);
    H[i] = h;
    L[i] = __float2bfloat16(v - __bfloat162float(h));
}

// ---------------------------------------------------------------------------
// transpose + split weights
// ---------------------------------------------------------------------------
__global__ __launch_bounds__(256)
void transpose_split(const float* __restrict__ W, bf16* __restrict__ Th,
                     bf16* __restrict__ Tl, int Kd, int Nw) {
    __shared__ float tile[32][33];
    int n0 = blockIdx.x * 32, k0 = blockIdx.y * 32;
    int tx = threadIdx.x & 31, ty = threadIdx.x >> 5;
    #pragma unroll
    for (int j = ty; j < 32; j += 8)
        tile[j][tx] = W[(size_t)(k0 + j) * Nw + n0 + tx];
    __syncthreads();
    #pragma unroll
    for (int j = ty; j < 32; j += 8) {
        float v = tile[tx][j];
        bf16 h = __float2bfloat16(v);
        Th[(size_t)(n0 + j) * Kd + k0 + tx] = h;
        Tl[(size_t)(n0 + j) * Kd + k0 + tx] = __float2bfloat16(v - __bfloat162float(h));
    }
}

// ---------------------------------------------------------------------------
// Split-bf16 tensor-core GEMM. MODE 0: fp32 C. MODE 1: rope+scale+split
// epilogue writing (Ch, Cl) bf16 — used for Q (scale=0.125*log2e) and K (1).
// ---------------------------------------------------------------------------
#define GSTAGE 32768
#define GEMM_SMEM (2 * GSTAGE)

__device__ __forceinline__ void g_load_stage(char* base, uint32_t sbase,
                                             const bf16* Ah, const bf16* Al,
                                             const bf16* Bh, const bf16* Bl,
                                             int bm, int bn, int kb, int K, int tid) {
    #pragma unroll
    for (int it = 0; it < 4; it++) {
        int idx = tid + it * 256;
        int r = idx >> 3, c = idx & 7;
        uint32_t dst = sbase + r * 128 + ((c ^ (r & 7)) << 4);
        const bf16* src = (c < 4 ? Ah : Al) + (size_t)(bm + r) * K + kb * 32 + (c & 3) * 8;
        cp16(dst, src);
    }
    #pragma unroll
    for (int it = 0; it < 4; it++) {
        int idx = tid + it * 256;
        int r = idx >> 3, c = idx & 7;
        uint32_t dst = sbase + 16384 + r * 128 + ((c ^ (r & 7)) << 4);
        const bf16* src = (c < 4 ? Bh : Bl) + (size_t)(bn + r) * K + kb * 32 + (c & 3) * 8;
        cp16(dst, src);
    }
}

template<int MODE>
__device__ __forceinline__
void gemm_mma_core(const bf16* __restrict__ Ah, const bf16* __restrict__ Al,
                   const bf16* __restrict__ Bh, const bf16* __restrict__ Bl,
                   float* __restrict__ C, bf16* __restrict__ Ch,
                   bf16* __restrict__ Cl, float rscale,
                   int Nt, int K, int bm, int bn) {
    extern __shared__ char smg[];
    const uint32_t sbase = smem_u32(smg);
    const int tid  = threadIdx.x;
    const int lane = tid & 31;
    const int warp = tid >> 5;
    const int wm   = (warp & 3) * 32;
    const int wn   = (warp >> 2) * 64;

    float acc[2][8][4];
    #pragma unroll
    for (int am = 0; am < 2; am++)
        #pragma unroll
        for (int an = 0; an < 8; an++)
            #pragma unroll
            for (int j = 0; j < 4; j++) acc[am][an][j] = 0.f;

    const int KB = K >> 5;
    g_load_stage(smg, sbase,           Ah, Al, Bh, Bl, bm, bn, 0, K, tid); CP_COMMIT();
    g_load_stage(smg, sbase + GSTAGE,  Ah, Al, Bh, Bl, bm, bn, 1, K, tid); CP_COMMIT();

    const int a_row  = wm + (lane & 15);
    const int a_kh   = (lane >> 4) & 1;
    const int b_n    = wn + (lane & 7) + ((lane >> 4) << 3);
    const int b_kh   = (lane >> 3) & 1;

    for (int t = 0; t < KB; t++) {
        CP_WAIT1();
        __syncthreads();
        const uint32_t sA = sbase + (t & 1) * GSTAGE;
        const uint32_t sB = sA + 16384;

        #pragma unroll
        for (int h = 0; h < 2; h++) {
            uint32_t bh[4][4], bl[4][4];
            #pragma unroll
            for (int g = 0; g < 4; g++) {
                int n = b_n + g * 16;
                int ch = h * 2 + b_kh;
                ldsm4(bh[g], sB + n * 128 + (((ch)     ^ (n & 7)) << 4));
                ldsm4(bl[g], sB + n * 128 + (((ch + 4) ^ (n & 7)) << 4));
            }
            #pragma unroll
            for (int am = 0; am < 2; am++) {
                int r  = a_row + am * 16;
                int ch = h * 2 + a_kh;
                uint32_t ah[4], al[4];
                ldsm4(ah, sA + r * 128 + (((ch)     ^ (r & 7)) << 4));
                ldsm4(al, sA + r * 128 + (((ch + 4) ^ (r & 7)) << 4));
                #pragma unroll
                for (int g = 0; g < 4; g++) {
                    mma_bf16(acc[am][2 * g],     ah, &bh[g][0]);
                    mma_bf16(acc[am][2 * g + 1], ah, &bh[g][2]);
                    mma_bf16(acc[am][2 * g],     al, &bh[g][0]);
                    mma_bf16(acc[am][2 * g + 1], al, &bh[g][2]);
                    mma_bf16(acc[am][2 * g],     ah, &bl[g][0]);
                    mma_bf16(acc[am][2 * g + 1], ah, &bl[g][2]);
                }
            }
        }
        __syncthreads();
        if (t + 2 < KB) {
            g_load_stage(smg + (t & 1) * GSTAGE, sA, Ah, Al, Bh, Bl, bm, bn, t + 2, K, tid);
        }
        CP_COMMIT();
    }

    if (MODE == 0) {
        #pragma unroll
        for (int am = 0; am < 2; am++) {
            int r0 = bm + wm + am * 16 + (lane >> 2);
            #pragma unroll
            for (int an = 0; an < 8; an++) {
                int col = bn + wn + an * 8 + (lane & 3) * 2;
                *(float2*)&C[(size_t)r0 * Nt + col]       = make_float2(acc[am][an][0], acc[am][an][1]);
                *(float2*)&C[(size_t)(r0 + 8) * Nt + col] = make_float2(acc[am][an][2], acc[am][an][3]);
            }
        }
    } else {
        // rope + scale + split epilogue. d (col&31) pairs with d+32 = an+4.
        #pragma unroll
        for (int am = 0; am < 2; am++) {
            int r0 = bm + wm + am * 16 + (lane >> 2);
            #pragma unroll
            for (int rh = 0; rh < 2; rh++) {
                int row = r0 + rh * 8;
                int s   = row & (SEQ - 1);
                #pragma unroll
                for (int an = 0; an < 4; an++) {
                    int col = bn + wn + an * 8 + (lane & 3) * 2;
                    int d0  = col & 31;
                    float2 cs0 = *(const float2*)&g_cs[2 * (s * 32 + d0)];
                    float2 cs1 = *(const float2*)&g_cs[2 * (s * 32 + d0 + 1)];
                    float v0a = acc[am][an][rh * 2],     v0b = acc[am][an][rh * 2 + 1];
                    float v1a = acc[am][an + 4][rh * 2], v1b = acc[am][an + 4][rh * 2 + 1];
                    float loa = (v0a * cs0.x - v1a * cs0.y) * rscale;
                    float lob = (v0b * cs1.x - v1b * cs1.y) * rscale;
                    float hia = (v1a * cs0.x + v0a * cs0.y) * rscale;
                    float hib = (v1b * cs1.x + v0b * cs1.y) * rscale;
                    uint32_t hp, lp;
                    split2(loa, lob, hp, lp);
                    *(uint32_t*)&Ch[(size_t)row * Nt + col] = hp;
                    *(uint32_t*)&Cl[(size_t)row * Nt + col] = lp;
                    split2(hia, hib, hp, lp);
                    *(uint32_t*)&Ch[(size_t)row * Nt + col + 32] = hp;
                    *(uint32_t*)&Cl[(size_t)row * Nt + col + 32] = lp;
                }
            }
        }
    }
}

__global__ __launch_bounds__(256, 2)
void gemm_mma(const bf16* __restrict__ Ah, const bf16* __restrict__ Al,
              const bf16* __restrict__ Bh, const bf16* __restrict__ Bl,
              float* __restrict__ C, int Nt, int K) {
    gemm_mma_core<0>(Ah, Al, Bh, Bl, C, nullptr, nullptr, 0.f,
                     Nt, K, blockIdx.y * 128, blockIdx.x * 128);
}

__global__ __launch_bounds__(256, 2)
void gemm_mma_rope(const bf16* __restrict__ Ah, const bf16* __restrict__ Al,
                   const bf16* __restrict__ Bh, const bf16* __restrict__ Bl,
                   bf16* __restrict__ Ch, bf16* __restrict__ Cl,
                   float rscale, int Nt, int K) {
    gemm_mma_core<1>(Ah, Al, Bh, Bl, nullptr, Ch, Cl, rscale,
                     Nt, K, blockIdx.y * 128, blockIdx.x * 128);
}

// K (z=0, rope+split) and V (z=1, fp32) fused into one launch for a full wave
__global__ __launch_bounds__(256, 2)
void gemm_mma_kv(const bf16* __restrict__ Ah, const bf16* __restrict__ Al,
                 const bf16* __restrict__ Bkh, const bf16* __restrict__ Bkl,
                 const bf16* __restrict__ Bvh, const bf16* __restrict__ Bvl,
                 bf16* __restrict__ Kh, bf16* __restrict__ Kl,
                 float* __restrict__ Vf, int Nt, int K) {
    if (blockIdx.z == 0)
        gemm_mma_core<1>(Ah, Al, Bkh, Bkl, nullptr, Kh, Kl, 1.0f,
                         Nt, K, blockIdx.y * 128, blockIdx.x * 128);
    else
        gemm_mma_core<0>(Ah, Al, Bvh, Bvl, Vf, nullptr, nullptr, 0.f,
                         Nt, K, blockIdx.y * 128, blockIdx.x * 128);
}

// ---------------------------------------------------------------------------
// Tensor-core flash attention v4: Q pre-split/pre-roped in global bf16;
// Q loads via cp.async into the stage-1 footprint (dead after frag ldsm).
// ---------------------------------------------------------------------------
#define QSTR 144
#define FA_STG_SZ 36864
#define FA_SQH 36864
#define FA_SQL 55296
#define FA_SMEM 73728

__device__ __forceinline__
void fa_load_kv(uint32_t sb, const bf16* __restrict__ Khp, const bf16* __restrict__ Klp,
                const bf16* __restrict__ Vhp, const bf16* __restrict__ Vlp,
                size_t krow0, int s0, int tid) {
    #pragma unroll
    for (int i = 0; i < 2; i++) {
        int idx = tid + i * 256;
        int r = idx >> 3, c = idx & 7;
        uint32_t so = r * QSTR + c * 16;
        cp16(sb + so,         Khp + (krow0 + r) * KVW + c * 8);
        cp16(sb + 9216 + so,  Klp + (krow0 + r) * KVW + c * 8);
        cp16(sb + 18432 + so, Vhp + (size_t)r * SEQ + s0 + c * 8);
        cp16(sb + 27648 + so, Vlp + (size_t)r * SEQ + s0 + c * 8);
    }
}

__global__ __launch_bounds__(256, 2)
void flashattn_mma(const bf16* __restrict__ Qh, const bf16* __restrict__ Ql,
                   const bf16* __restrict__ Kh, const bf16* __restrict__ Kl,
                   const bf16* __restrict__ Vth, const bf16* __restrict__ Vtl,
                   bf16* __restrict__ Yh, bf16* __restrict__ Yl) {
    extern __shared__ char sm[];
    const uint32_t base = smem_u32(sm);
    const int tid  = threadIdx.x;
    const int lane = tid & 31;
    const int warp = tid >> 5;
    const int qt   = gridDim.x - 1 - blockIdx.x;
    const int h    = blockIdx.y;
    const int b    = blockIdx.z;
    const int kvh  = h >> 2;
    const int wm   = warp * 16;

    const bf16* Khp = Kh + kvh * 64;
    const bf16* Klp = Kl + kvh * 64;
    const bf16* Vhp = Vth + (size_t)((b * NKV + kvh) * 64) * SEQ;
    const bf16* Vlp = Vtl + (size_t)((b * NKV + kvh) * 64) * SEQ;
    const int njt = 2 * qt + 2;

    // ---- Q cp.async into stage-1 footprint (group 0, waited first) ----
    {
        size_t qrow0 = (size_t)(b * SEQ + qt * 128);
        int hoff = h * HD;
        #pragma unroll
        for (int i = 0; i < 4; i++) {
            int idx = tid + i * 256;
            int r = idx >> 3, c = idx & 7;
            cp16(base + FA_SQH + r * QSTR + c * 16, Qh + (qrow0 + r) * (NH * HD) + hoff + c * 8);
            cp16(base + FA_SQL + r * QSTR + c * 16, Ql + (qrow0 + r) * (NH * HD) + hoff + c * 8);
        }
    }
    CP_COMMIT();

    // ---- prefetch first KV tile into stage0 (group 1) ----
    fa_load_kv(base, Khp, Klp, Vhp, Vlp, (size_t)b * SEQ, 0, tid);
    CP_COMMIT();

    CP_WAIT1();        // Q group done (KV0 may still be in flight)
    __syncthreads();

    // ---- Q fragments to registers (then Q smem is dead -> becomes stage1) ----
    const int a_row = wm + (lane & 15);
    const int a_kh  = (lane >> 4) & 1;
    uint32_t qh[4][4], ql[4][4];
    #pragma unroll
    for (int kc = 0; kc < 4; kc++) {
        ldsm4(qh[kc], base + FA_SQH + a_row * QSTR + kc * 32 + a_kh * 16);
        ldsm4(ql[kc], base + FA_SQL + a_row * QSTR + kc * 32 + a_kh * 16);
    }

    const int b_n  = (lane & 7) + ((lane >> 4) << 3);
    const int b_kh = (lane >> 3) & 1;

    float m0 = -INFINITY, m1 = -INFINITY, l0 = 0.f, l1 = 0.f;
    float oa[8][4];
    #pragma unroll
    for (int f = 0; f < 8; f++)
        #pragma unroll
        for (int j = 0; j < 4; j++) oa[f][j] = 0.f;

    for (int jt = 0; jt < njt; jt++) {
        const uint32_t stg = base + (jt & 1) * FA_STG_SZ;

        __syncthreads();   // all warps done with the other stage (and Q frags @ jt=0)
        if (jt + 1 < njt) {
            fa_load_kv(base + ((jt + 1) & 1) * FA_STG_SZ,
                       Khp, Klp, Vhp, Vlp,
                       (size_t)b * SEQ + (jt + 1) * 64, (jt + 1) * 64, tid);
        }
        CP_COMMIT();
        CP_WAIT1();
        __syncthreads();

        // ---- S = Q @ K^T (base-2 scaled) ----
        float sa[8][4];
        #pragma unroll
        for (int f = 0; f < 8; f++)
            #pragma unroll
            for (int j = 0; j < 4; j++) sa[f][j] = 0.f;

        #pragma unroll
        for (int kc = 0; kc < 4; kc++) {
            #pragma unroll
            for (int g = 0; g < 4; g++) {
                uint32_t kh4[4], kl4[4];
                ldsm4(kh4, stg + (b_n + g * 16) * QSTR + kc * 32 + b_kh * 16);
                ldsm4(kl4, stg + 9216 + (b_n + g * 16) * QSTR + kc * 32 + b_kh * 16);
                mma_bf16(sa[2 * g],     qh[kc], &kh4[0]);
                mma_bf16(sa[2 * g + 1], qh[kc], &kh4[2]);
                mma_bf16(sa[2 * g],     ql[kc], &kh4[0]);
                mma_bf16(sa[2 * g + 1], ql[kc], &kh4[2]);
                mma_bf16(sa[2 * g],     qh[kc], &kl4[0]);
                mma_bf16(sa[2 * g + 1], qh[kc], &kl4[2]);
            }
        }

        // ---- causal mask ----
        if (jt * 64 + 63 > qt * 128) {
            int r0g = qt * 128 + wm + (lane >> 2);
            int r1g = r0g + 8;
            #pragma unroll
            for (int f = 0; f < 8; f++) {
                int c0 = jt * 64 + f * 8 + (lane & 3) * 2;
                if (c0 > r0g)     sa[f][0] = -INFINITY;
                if (c0 + 1 > r0g) sa[f][1] = -INFINITY;
                if (c0 > r1g)     sa[f][2] = -INFINITY;
                if (c0 + 1 > r1g) sa[f][3] = -INFINITY;
            }
        }

        // ---- online softmax (base 2) ----
        float rm0 = -INFINITY, rm1 = -INFINITY;
        #pragma unroll
        for (int f = 0; f < 8; f++) {
            rm0 = fmaxf(rm0, fmaxf(sa[f][0], sa[f][1]));
            rm1 = fmaxf(rm1, fmaxf(sa[f][2], sa[f][3]));
        }
        rm0 = fmaxf(rm0, __shfl_xor_sync(0xffffffffu, rm0, 1));
        rm0 = fmaxf(rm0, __shfl_xor_sync(0xffffffffu, rm0, 2));
        rm1 = fmaxf(rm1, __shfl_xor_sync(0xffffffffu, rm1, 1));
        rm1 = fmaxf(rm1, __shfl_xor_sync(0xffffffffu, rm1, 2));

        float mn0 = fmaxf(m0, rm0), mn1 = fmaxf(m1, rm1);
        float f0 = exp2f(m0 - mn0), f1 = exp2f(m1 - mn1);
        float rs0 = 0.f, rs1 = 0.f;
        #pragma unroll
        for (int f = 0; f < 8; f++) {
            sa[f][0] = exp2f(sa[f][0] - mn0);
            sa[f][1] = exp2f(sa[f][1] - mn0);
            sa[f][2] = exp2f(sa[f][2] - mn1);
            sa[f][3] = exp2f(sa[f][3] - mn1);
            rs0 += sa[f][0] + sa[f][1];
            rs1 += sa[f][2] + sa[f][3];
        }
        rs0 += __shfl_xor_sync(0xffffffffu, rs0, 1);
        rs0 += __shfl_xor_sync(0xffffffffu, rs0, 2);
        rs1 += __shfl_xor_sync(0xffffffffu, rs1, 1);
        rs1 += __shfl_xor_sync(0xffffffffu, rs1, 2);

        l0 = l0 * f0 + rs0;  m0 = mn0;
        l1 = l1 * f1 + rs1;  m1 = mn1;
        #pragma unroll
        for (int f = 0; f < 8; f++) {
            oa[f][0] *= f0; oa[f][1] *= f0;
            oa[f][2] *= f1; oa[f][3] *= f1;
        }

        // ---- O += P @ V ----
        #pragma unroll
        for (int kc = 0; kc < 4; kc++) {
            uint32_t ah[4], al[4];
            split2(sa[2 * kc][0],     sa[2 * kc][1],     ah[0], al[0]);
            split2(sa[2 * kc][2],     sa[2 * kc][3],     ah[1], al[1]);
            split2(sa[2 * kc + 1][0], sa[2 * kc + 1][1], ah[2], al[2]);
            split2(sa[2 * kc + 1][2], sa[2 * kc + 1][3], ah[3], al[3]);
            #pragma unroll
            for (int g = 0; g < 4; g++) {
                uint32_t vh4[4], vl4[4];
                ldsm4(vh4, stg + 18432 + (b_n + g * 16) * QSTR + kc * 32 + b_kh * 16);
                ldsm4(vl4, stg + 27648 + (b_n + g * 16) * QSTR + kc * 32 + b_kh * 16);
                mma_bf16(oa[2 * g],     ah, &vh4[0]);
                mma_bf16(oa[2 * g + 1], ah, &vh4[2]);
                mma_bf16(oa[2 * g],     al, &vh4[0]);
                mma_bf16(oa[2 * g + 1], al, &vh4[2]);
                mma_bf16(oa[2 * g],     ah, &vl4[0]);
                mma_bf16(oa[2 * g + 1], ah, &vl4[2]);
            }
        }
    }

    // ---- epilogue: normalize, split, write Yh/Yl ----
    float inv0 = 1.f / l0, inv1 = 1.f / l1;
    size_t row0 = (size_t)(b * SEQ + qt * 128 + wm + (lane >> 2));
    #pragma unroll
    for (int f = 0; f < 8; f++) {
        int col = h * HD + f * 8 + (lane & 3) * 2;
        uint32_t hp, lp;
        split2(oa[f][0] * inv0, oa[f][1] * inv0, hp, lp);
        *(uint32_t*)&Yh[row0 * (NH * HD) + col] = hp;
        *(uint32_t*)&Yl[row0 * (NH * HD) + col] = lp;
        split2(oa[f][2] * inv1, oa[f][3] * inv1, hp, lp);
        *(uint32_t*)&Yh[(row0 + 8) * (NH * HD) + col] = hp;
        *(uint32_t*)&Yl[(row0 + 8) * (NH * HD) + col] = lp;
    }
}

// ---------------------------------------------------------------------------
extern "C" void kernel_launch(void* const* d_in, const int* in_sizes, int n_in,
                              void* d_out, int out_size) {
    const float* x  = (const float*)d_in[0];
    const float* Wq = (const float*)d_in[1];
    const float* Wk = (const float*)d_in[2];
    const float* Wv = (const float*)d_in[3];
    const float* Wo = (const float*)d_in[4];
    float* out = (float*)d_out;

    float* Vp;
    cudaGetSymbolAddress((void**)&Vp, g_V);
    bf16 *xh, *xl, *Qh, *Ql, *Kh, *Kl, *Vth, *Vtl, *Yh, *Yl;
    bf16 *Wqh, *Wql, *Wkh, *Wkl, *Wvh, *Wvl, *Woh, *Wol;
    cudaGetSymbolAddress((void**)&xh, g_xh);   cudaGetSymbolAddress((void**)&xl, g_xl);
    cudaGetSymbolAddress((void**)&Qh, g_Qh);   cudaGetSymbolAddress((void**)&Ql, g_Ql);
    cudaGetSymbolAddress((void**)&Kh, g_Kh);   cudaGetSymbolAddress((void**)&Kl, g_Kl);
    cudaGetSymbolAddress((void**)&Vth, g_Vth); cudaGetSymbolAddress((void**)&Vtl, g_Vtl);
    cudaGetSymbolAddress((void**)&Yh, g_Yh);   cudaGetSymbolAddress((void**)&Yl, g_Yl);
    cudaGetSymbolAddress((void**)&Wqh, g_Wqt_h); cudaGetSymbolAddress((void**)&Wql, g_Wqt_l);
    cudaGetSymbolAddress((void**)&Wkh, g_Wkt_h); cudaGetSymbolAddress((void**)&Wkl, g_Wkt_l);
    cudaGetSymbolAddress((void**)&Wvh, g_Wvt_h); cudaGetSymbolAddress((void**)&Wvl, g_Wvt_l);
    cudaGetSymbolAddress((void**)&Woh, g_Wot_h); cudaGetSymbolAddress((void**)&Wol, g_Wot_l);

    dim3 blk(256);
    const float QSC = 0.125f * 1.4426950408889634f;   // 1/sqrt(64) * log2(e)

    rope_table<<<(SEQ * 32 + 255) / 256, blk>>>();

    int totx = ROWS * MODEL;
    split_rows<<<(totx + 255) / 256, blk>>>(x, xh, xl, totx);
    transpose_split<<<dim3((NH * HD) / 32, MODEL / 32), blk>>>(Wq, Wqh, Wql, MODEL, NH * HD);
    transpose_split<<<dim3(KVW / 32, MODEL / 32), blk>>>(Wk, Wkh, Wkl, MODEL, KVW);
    transpose_split<<<dim3(KVW / 32, MODEL / 32), blk>>>(Wv, Wvh, Wvl, MODEL, KVW);
    transpose_split<<<dim3(MODEL / 32, (NH * HD) / 32), blk>>>(Wo, Woh, Wol, NH * HD, MODEL);

    cudaFuncSetAttribute(gemm_mma, cudaFuncAttributeMaxDynamicSharedMemorySize, GEMM_SMEM);
    cudaFuncSetAttribute(gemm_mma_rope, cudaFuncAttributeMaxDynamicSharedMemorySize, GEMM_SMEM);
    cudaFuncSetAttribute(gemm_mma_kv, cudaFuncAttributeMaxDynamicSharedMemorySize, GEMM_SMEM);

    // Q projection with fused rope+scale+split epilogue
    gemm_mma_rope<<<dim3((NH * HD) / 128, ROWS / 128), blk, GEMM_SMEM>>>(
        xh, xl, Wqh, Wql, Qh, Ql, QSC, NH * HD, MODEL);
    // K (rope+split) and V (fp32) projections in one launch
    gemm_mma_kv<<<dim3(KVW / 128, ROWS / 128, 2), blk, GEMM_SMEM>>>(
        xh, xl, Wkh, Wkl, Wvh, Wvl, Kh, Kl, Vp, KVW, MODEL);

    // V: transpose + split
    transpose_split_v<<<dim3(KVW / 32, ROWS / 32), blk>>>(Vp, Vth, Vtl);

    // flash attention
    cudaFuncSetAttribute(flashattn_mma, cudaFuncAttributeMaxDynamicSharedMemorySize, FA_SMEM);
    flashattn_mma<<<dim3(SEQ / 128, NH, BATCH), blk, FA_SMEM>>>(
        Qh, Ql, Kh, Kl, Vth, Vtl, Yh, Yl);

    // output projection
    gemm_mma<<<dim3(MODEL / 128, ROWS / 128), blk, GEMM_SMEM>>>(
        Yh, Yl, Woh, Wol, out, MODEL, MODEL);
}

// round 10
// speedup vs baseline: 3.0701x; 1.0074x over previous
#include <cuda_runtime.h>
#include <cuda_bf16.h>
#include <math.h>
#include <stdint.h>

#define BATCH 2
#define SEQ   2048
#define MODEL 2048
#define NH    32
#define NKV   8
#define HD    64
#define ROWS  (BATCH*SEQ)   // 4096
#define KVW   (NKV*HD)      // 512

typedef unsigned long long u64;
typedef __nv_bfloat16 bf16;

// ---------------- mma.sync helpers -----------------------------------------
__device__ __forceinline__ uint32_t smem_u32(const void* p) {
    uint32_t a;
    asm("{ .reg .u64 t; cvta.to.shared.u64 t, %1; cvt.u32.u64 %0, t; }" : "=r"(a) : "l"(p));
    return a;
}
__device__ __forceinline__ void ldsm4(uint32_t* r, uint32_t addr) {
    asm volatile("ldmatrix.sync.aligned.m8n8.x4.shared.b16 {%0,%1,%2,%3}, [%4];"
                 : "=r"(r[0]), "=r"(r[1]), "=r"(r[2]), "=r"(r[3]) : "r"(addr));
}
__device__ __forceinline__ void mma_bf16(float* d, const uint32_t* a, const uint32_t* b) {
    asm volatile("mma.sync.aligned.m16n8k16.row.col.f32.bf16.bf16.f32 "
                 "{%0,%1,%2,%3}, {%4,%5,%6,%7}, {%8,%9}, {%0,%1,%2,%3};"
                 : "+f"(d[0]), "+f"(d[1]), "+f"(d[2]), "+f"(d[3])
                 : "r"(a[0]), "r"(a[1]), "r"(a[2]), "r"(a[3]), "r"(b[0]), "r"(b[1]));
}
__device__ __forceinline__ void cp16(uint32_t dst, const void* src) {
    asm volatile("cp.async.cg.shared.global [%0], [%1], 16;" :: "r"(dst), "l"(src));
}
#define CP_COMMIT() asm volatile("cp.async.commit_group;" ::: "memory")
#define CP_WAIT1()  asm volatile("cp.async.wait_group 1;" ::: "memory")

// bf16x2 pack/split: lo float -> bits[15:0], hi float -> bits[31:16]
__device__ __forceinline__ uint32_t pkbf2(float lo, float hi) {
    uint32_t r; asm("cvt.rn.bf16x2.f32 %0, %1, %2;" : "=r"(r) : "f"(hi), "f"(lo)); return r;
}
__device__ __forceinline__ float bflo(uint32_t p) { return __uint_as_float(p << 16); }
__device__ __forceinline__ float bfhi(uint32_t p) { return __uint_as_float(p & 0xffff0000u); }
__device__ __forceinline__ void split2(float f0, float f1, uint32_t& hp, uint32_t& lp) {
    hp = pkbf2(f0, f1);
    lp = pkbf2(f0 - bflo(hp), f1 - bfhi(hp));
}

// ---------------- scratch --------------------------------------------------
__device__ float g_cs[(size_t)SEQ * 32 * 2];

__device__ bf16 g_xh[(size_t)ROWS * MODEL];
__device__ bf16 g_xl[(size_t)ROWS * MODEL];
__device__ bf16 g_Qh[(size_t)ROWS * NH * HD];
__device__ bf16 g_Ql[(size_t)ROWS * NH * HD];
__device__ bf16 g_Kh[(size_t)ROWS * KVW];
__device__ bf16 g_Kl[(size_t)ROWS * KVW];
__device__ bf16 g_Vth[(size_t)BATCH * KVW * SEQ];
__device__ bf16 g_Vtl[(size_t)BATCH * KVW * SEQ];
__device__ bf16 g_Yh[(size_t)ROWS * NH * HD];
__device__ bf16 g_Yl[(size_t)ROWS * NH * HD];
__device__ bf16 g_Wqt_h[(size_t)(NH  * HD) * MODEL];
__device__ bf16 g_Wqt_l[(size_t)(NH  * HD) * MODEL];
__device__ bf16 g_Wkt_h[(size_t)KVW * MODEL];
__device__ bf16 g_Wkt_l[(size_t)KVW * MODEL];
__device__ bf16 g_Wvt_h[(size_t)KVW * MODEL];
__device__ bf16 g_Wvt_l[(size_t)KVW * MODEL];
__device__ bf16 g_Wot_h[(size_t)MODEL * (NH * HD)];
__device__ bf16 g_Wot_l[(size_t)MODEL * (NH * HD)];

// ---------------------------------------------------------------------------
// RoPE cos/sin table (fp64 trig once)
// ---------------------------------------------------------------------------
__global__ __launch_bounds__(256)
void rope_table() {
    int i = blockIdx.x * 256 + threadIdx.x;
    if (i >= SEQ * 32) return;
    int d = i & 31;
    int s = i >> 5;
    double inv = exp2(-(double)d * (13.287712379549448882 / 32.0));
    double ang = (double)s * inv;
    double sd, cd;
    sincos(ang, &sd, &cd);
    g_cs[2 * i + 0] = (float)cd;
    g_cs[2 * i + 1] = (float)sd;
}

// ---------------------------------------------------------------------------
// split fp32 -> (hi, lo) bf16  (x only)
// ---------------------------------------------------------------------------
__global__ __launch_bounds__(256)
void split_rows(const float* __restrict__ X, bf16* __restrict__ H,
                bf16* __restrict__ L, int total) {
    int i = blockIdx.x * 256 + threadIdx.x;
    if (i >= total) return;
    float v = X[i];
    bf16 h = __float2bfloat16(v);
    H[i] = h;
    L[i] = __float2bfloat16(v - __bfloat162float(h));
}

// ---------------------------------------------------------------------------
// ALL weight transposes in one launch: z=0 Wq, 1 Wo, 2 Wk, 3 Wv
// ---------------------------------------------------------------------------
__global__ __launch_bounds__(256)
void ts_all(const float* __restrict__ Wq, const float* __restrict__ Wk,
            const float* __restrict__ Wv, const float* __restrict__ Wo) {
    __shared__ float tile[32][33];
    const float* W; bf16 *Th, *Tl; int Kd, Nw, nx;
    switch (blockIdx.z) {
        case 0:  W = Wq; Th = g_Wqt_h; Tl = g_Wqt_l; Kd = MODEL;   Nw = NH * HD; nx = 64; break;
        case 1:  W = Wo; Th = g_Wot_h; Tl = g_Wot_l; Kd = NH * HD; Nw = MODEL;   nx = 64; break;
        case 2:  W = Wk; Th = g_Wkt_h; Tl = g_Wkt_l; Kd = MODEL;   Nw = KVW;     nx = 16; break;
        default: W = Wv; Th = g_Wvt_h; Tl = g_Wvt_l; Kd = MODEL;   Nw = KVW;     nx = 16; break;
    }
    if ((int)blockIdx.x >= nx) return;
    int n0 = blockIdx.x * 32, k0 = blockIdx.y * 32;
    int tx = threadIdx.x & 31, ty = threadIdx.x >> 5;
    #pragma unroll
    for (int j = ty; j < 32; j += 8)
        tile[j][tx] = W[(size_t)(k0 + j) * Nw + n0 + tx];
    __syncthreads();
    #pragma unroll
    for (int j = ty; j < 32; j += 8) {
        float v = tile[tx][j];
        bf16 h = __float2bfloat16(v);
        Th[(size_t)(n0 + j) * Kd + k0 + tx] = h;
        Tl[(size_t)(n0 + j) * Kd + k0 + tx] = __float2bfloat16(v - __bfloat162float(h));
    }
}

// ---------------------------------------------------------------------------
// Split-bf16 tensor-core GEMM core.
// MODE 0: fp32 C.
// MODE 1: rope+scale+split epilogue -> (Ch, Cl) bf16 (Q: scale=.125*log2e, K: 1).
// MODE 2: V transpose+split epilogue -> Vth/Vtl [(b,kvh,d)][s] bf16.
// Inner loop is TERM-MAJOR: accumulator reuse spacing 8 (was 2).
// ---------------------------------------------------------------------------
#define GSTAGE 32768
#define GEMM_SMEM (2 * GSTAGE)

__device__ __forceinline__ void g_load_stage(uint32_t sbase,
                                             const bf16* Ah, const bf16* Al,
                                             const bf16* Bh, const bf16* Bl,
                                             int bm, int bn, int kb, int K, int tid) {
    #pragma unroll
    for (int it = 0; it < 4; it++) {
        int idx = tid + it * 256;
        int r = idx >> 3, c = idx & 7;
        uint32_t dst = sbase + r * 128 + ((c ^ (r & 7)) << 4);
        const bf16* src = (c < 4 ? Ah : Al) + (size_t)(bm + r) * K + kb * 32 + (c & 3) * 8;
        cp16(dst, src);
    }
    #pragma unroll
    for (int it = 0; it < 4; it++) {
        int idx = tid + it * 256;
        int r = idx >> 3, c = idx & 7;
        uint32_t dst = sbase + 16384 + r * 128 + ((c ^ (r & 7)) << 4);
        const bf16* src = (c < 4 ? Bh : Bl) + (size_t)(bn + r) * K + kb * 32 + (c & 3) * 8;
        cp16(dst, src);
    }
}

template<int MODE>
__device__ __forceinline__
void gemm_mma_core(const bf16* __restrict__ Ah, const bf16* __restrict__ Al,
                   const bf16* __restrict__ Bh, const bf16* __restrict__ Bl,
                   float* __restrict__ C, bf16* __restrict__ Ch,
                   bf16* __restrict__ Cl, float rscale,
                   int Nt, int K, int bm, int bn) {
    extern __shared__ char smg[];
    const uint32_t sbase = smem_u32(smg);
    const int tid  = threadIdx.x;
    const int lane = tid & 31;
    const int warp = tid >> 5;
    const int wm   = (warp & 3) * 32;
    const int wn   = (warp >> 2) * 64;

    float acc[2][8][4];
    #pragma unroll
    for (int am = 0; am < 2; am++)
        #pragma unroll
        for (int an = 0; an < 8; an++)
            #pragma unroll
            for (int j = 0; j < 4; j++) acc[am][an][j] = 0.f;

    const int KB = K >> 5;
    g_load_stage(sbase,          Ah, Al, Bh, Bl, bm, bn, 0, K, tid); CP_COMMIT();
    g_load_stage(sbase + GSTAGE, Ah, Al, Bh, Bl, bm, bn, 1, K, tid); CP_COMMIT();

    const int a_row  = wm + (lane & 15);
    const int a_kh   = (lane >> 4) & 1;
    const int b_n    = wn + (lane & 7) + ((lane >> 4) << 3);
    const int b_kh   = (lane >> 3) & 1;

    for (int t = 0; t < KB; t++) {
        CP_WAIT1();
        __syncthreads();
        const uint32_t sA = sbase + (t & 1) * GSTAGE;
        const uint32_t sB = sA + 16384;

        #pragma unroll
        for (int h = 0; h < 2; h++) {
            uint32_t bh[4][4], bl[4][4];
            #pragma unroll
            for (int g = 0; g < 4; g++) {
                int n = b_n + g * 16;
                int ch = h * 2 + b_kh;
                ldsm4(bh[g], sB + n * 128 + (((ch)     ^ (n & 7)) << 4));
                ldsm4(bl[g], sB + n * 128 + (((ch + 4) ^ (n & 7)) << 4));
            }
            #pragma unroll
            for (int am = 0; am < 2; am++) {
                int r  = a_row + am * 16;
                int ch = h * 2 + a_kh;
                uint32_t ah[4], al[4];
                ldsm4(ah, sA + r * 128 + (((ch)     ^ (r & 7)) << 4));
                ldsm4(al, sA + r * 128 + (((ch + 4) ^ (r & 7)) << 4));
                // term-major: each accumulator touched at spacing 8
                #pragma unroll
                for (int g = 0; g < 4; g++) {
                    mma_bf16(acc[am][2 * g],     ah, &bh[g][0]);
                    mma_bf16(acc[am][2 * g + 1], ah, &bh[g][2]);
                }
                #pragma unroll
                for (int g = 0; g < 4; g++) {
                    mma_bf16(acc[am][2 * g],     al, &bh[g][0]);
                    mma_bf16(acc[am][2 * g + 1], al, &bh[g][2]);
                }
                #pragma unroll
                for (int g = 0; g < 4; g++) {
                    mma_bf16(acc[am][2 * g],     ah, &bl[g][0]);
                    mma_bf16(acc[am][2 * g + 1], ah, &bl[g][2]);
                }
            }
        }
        __syncthreads();
        if (t + 2 < KB) {
            g_load_stage(sA, Ah, Al, Bh, Bl, bm, bn, t + 2, K, tid);
        }
        CP_COMMIT();
    }

    if (MODE == 0) {
        #pragma unroll
        for (int am = 0; am < 2; am++) {
            int r0 = bm + wm + am * 16 + (lane >> 2);
            #pragma unroll
            for (int an = 0; an < 8; an++) {
                int col = bn + wn + an * 8 + (lane & 3) * 2;
                *(float2*)&C[(size_t)r0 * Nt + col]       = make_float2(acc[am][an][0], acc[am][an][1]);
                *(float2*)&C[(size_t)(r0 + 8) * Nt + col] = make_float2(acc[am][an][2], acc[am][an][3]);
            }
        }
    } else if (MODE == 1) {
        // rope + scale + split epilogue. d (col&31) pairs with d+32 = an+4.
        #pragma unroll
        for (int am = 0; am < 2; am++) {
            int r0 = bm + wm + am * 16 + (lane >> 2);
            #pragma unroll
            for (int rh = 0; rh < 2; rh++) {
                int row = r0 + rh * 8;
                int s   = row & (SEQ - 1);
                #pragma unroll
                for (int an = 0; an < 4; an++) {
                    int col = bn + wn + an * 8 + (lane & 3) * 2;
                    int d0  = col & 31;
                    float2 cs0 = *(const float2*)&g_cs[2 * (s * 32 + d0)];
                    float2 cs1 = *(const float2*)&g_cs[2 * (s * 32 + d0 + 1)];
                    float v0a = acc[am][an][rh * 2],     v0b = acc[am][an][rh * 2 + 1];
                    float v1a = acc[am][an + 4][rh * 2], v1b = acc[am][an + 4][rh * 2 + 1];
                    float loa = (v0a * cs0.x - v1a * cs0.y) * rscale;
                    float lob = (v0b * cs1.x - v1b * cs1.y) * rscale;
                    float hia = (v1a * cs0.x + v0a * cs0.y) * rscale;
                    float hib = (v1b * cs1.x + v0b * cs1.y) * rscale;
                    uint32_t hp, lp;
                    split2(loa, lob, hp, lp);
                    *(uint32_t*)&Ch[(size_t)row * Nt + col] = hp;
                    *(uint32_t*)&Cl[(size_t)row * Nt + col] = lp;
                    split2(hia, hib, hp, lp);
                    *(uint32_t*)&Ch[(size_t)row * Nt + col + 32] = hp;
                    *(uint32_t*)&Cl[(size_t)row * Nt + col + 32] = lp;
                }
            }
        }
    } else {
        // V transpose + split epilogue: out[(b*NKV + c>>6)*64 + (c&63)][s]
        #pragma unroll
        for (int am = 0; am < 2; am++) {
            int r0 = bm + wm + am * 16 + (lane >> 2);
            #pragma unroll
            for (int rh = 0; rh < 2; rh++) {
                int row = r0 + rh * 8;
                int bb  = row >> 11;
                int sl  = row & (SEQ - 1);
                #pragma unroll
                for (int an = 0; an < 8; an++) {
                    int col = bn + wn + an * 8 + (lane & 3) * 2;
                    float va = acc[am][an][rh * 2];
                    float vb = acc[am][an][rh * 2 + 1];
                    size_t o0 = ((size_t)(bb * NKV + (col >> 6)) * 64 + (col & 63)) * SEQ + sl;
                    size_t o1 = o0 + SEQ;
                    bf16 ha = __float2bfloat16(va);
                    Ch[o0] = ha;
                    Cl[o0] = __float2bfloat16(va - __bfloat162float(ha));
                    bf16 hb = __float2bfloat16(vb);
                    Ch[o1] = hb;
                    Cl[o1] = __float2bfloat16(vb - __bfloat162float(hb));
                }
            }
        }
    }
}

__global__ __launch_bounds__(256, 2)
void gemm_mma(const bf16* __restrict__ Ah, const bf16* __restrict__ Al,
              const bf16* __restrict__ Bh, const bf16* __restrict__ Bl,
              float* __restrict__ C, int Nt, int K) {
    gemm_mma_core<0>(Ah, Al, Bh, Bl, C, nullptr, nullptr, 0.f,
                     Nt, K, blockIdx.y * 128, blockIdx.x * 128);
}

__global__ __launch_bounds__(256, 2)
void gemm_mma_rope(const bf16* __restrict__ Ah, const bf16* __restrict__ Al,
                   const bf16* __restrict__ Bh, const bf16* __restrict__ Bl,
                   bf16* __restrict__ Ch, bf16* __restrict__ Cl,
                   float rscale, int Nt, int K) {
    gemm_mma_core<1>(Ah, Al, Bh, Bl, nullptr, Ch, Cl, rscale,
                     Nt, K, blockIdx.y * 128, blockIdx.x * 128);
}

// K (z=0, rope+split) and V (z=1, transpose+split) in one launch
__global__ __launch_bounds__(256, 2)
void gemm_mma_kv(const bf16* __restrict__ Ah, const bf16* __restrict__ Al,
                 const bf16* __restrict__ Bkh, const bf16* __restrict__ Bkl,
                 const bf16* __restrict__ Bvh, const bf16* __restrict__ Bvl,
                 bf16* __restrict__ Kh, bf16* __restrict__ Kl,
                 bf16* __restrict__ Vth, bf16* __restrict__ Vtl, int Nt, int K) {
    if (blockIdx.z == 0)
        gemm_mma_core<1>(Ah, Al, Bkh, Bkl, nullptr, Kh, Kl, 1.0f,
                         Nt, K, blockIdx.y * 128, blockIdx.x * 128);
    else
        gemm_mma_core<2>(Ah, Al, Bvh, Bvl, nullptr, Vth, Vtl, 0.f,
                         Nt, K, blockIdx.y * 128, blockIdx.x * 128);
}

// ---------------------------------------------------------------------------
// Tensor-core flash attention (unchanged numerics; now launch slot 6 = profiled)
// ---------------------------------------------------------------------------
#define QSTR 144
#define FA_STG_SZ 36864
#define FA_SQH 36864
#define FA_SQL 55296
#define FA_SMEM 73728

__device__ __forceinline__
void fa_load_kv(uint32_t sb, const bf16* __restrict__ Khp, const bf16* __restrict__ Klp,
                const bf16* __restrict__ Vhp, const bf16* __restrict__ Vlp,
                size_t krow0, int s0, int tid) {
    #pragma unroll
    for (int i = 0; i < 2; i++) {
        int idx = tid + i * 256;
        int r = idx >> 3, c = idx & 7;
        uint32_t so = r * QSTR + c * 16;
        cp16(sb + so,         Khp + (krow0 + r) * KVW + c * 8);
        cp16(sb + 9216 + so,  Klp + (krow0 + r) * KVW + c * 8);
        cp16(sb + 18432 + so, Vhp + (size_t)r * SEQ + s0 + c * 8);
        cp16(sb + 27648 + so, Vlp + (size_t)r * SEQ + s0 + c * 8);
    }
}

__global__ __launch_bounds__(256, 2)
void flashattn_mma(const bf16* __restrict__ Qh, const bf16* __restrict__ Ql,
                   const bf16* __restrict__ Kh, const bf16* __restrict__ Kl,
                   const bf16* __restrict__ Vth, const bf16* __restrict__ Vtl,
                   bf16* __restrict__ Yh, bf16* __restrict__ Yl) {
    extern __shared__ char sm[];
    const uint32_t base = smem_u32(sm);
    const int tid  = threadIdx.x;
    const int lane = tid & 31;
    const int warp = tid >> 5;
    const int qt   = gridDim.x - 1 - blockIdx.x;
    const int h    = blockIdx.y;
    const int b    = blockIdx.z;
    const int kvh  = h >> 2;
    const int wm   = warp * 16;

    const bf16* Khp = Kh + kvh * 64;
    const bf16* Klp = Kl + kvh * 64;
    const bf16* Vhp = Vth + (size_t)((b * NKV + kvh) * 64) * SEQ;
    const bf16* Vlp = Vtl + (size_t)((b * NKV + kvh) * 64) * SEQ;
    const int njt = 2 * qt + 2;

    // ---- Q cp.async into stage-1 footprint (group 0, waited first) ----
    {
        size_t qrow0 = (size_t)(b * SEQ + qt * 128);
        int hoff = h * HD;
        #pragma unroll
        for (int i = 0; i < 4; i++) {
            int idx = tid + i * 256;
            int r = idx >> 3, c = idx & 7;
            cp16(base + FA_SQH + r * QSTR + c * 16, Qh + (qrow0 + r) * (NH * HD) + hoff + c * 8);
            cp16(base + FA_SQL + r * QSTR + c * 16, Ql + (qrow0 + r) * (NH * HD) + hoff + c * 8);
        }
    }
    CP_COMMIT();

    // ---- prefetch first KV tile into stage0 (group 1) ----
    fa_load_kv(base, Khp, Klp, Vhp, Vlp, (size_t)b * SEQ, 0, tid);
    CP_COMMIT();

    CP_WAIT1();        // Q group done (KV0 may still be in flight)
    __syncthreads();

    // ---- Q fragments to registers (then Q smem is dead -> becomes stage1) ----
    const int a_row = wm + (lane & 15);
    const int a_kh  = (lane >> 4) & 1;
    uint32_t qh[4][4], ql[4][4];
    #pragma unroll
    for (int kc = 0; kc < 4; kc++) {
        ldsm4(qh[kc], base + FA_SQH + a_row * QSTR + kc * 32 + a_kh * 16);
        ldsm4(ql[kc], base + FA_SQL + a_row * QSTR + kc * 32 + a_kh * 16);
    }

    const int b_n  = (lane & 7) + ((lane >> 4) << 3);
    const int b_kh = (lane >> 3) & 1;

    float m0 = -INFINITY, m1 = -INFINITY, l0 = 0.f, l1 = 0.f;
    float oa[8][4];
    #pragma unroll
    for (int f = 0; f < 8; f++)
        #pragma unroll
        for (int j = 0; j < 4; j++) oa[f][j] = 0.f;

    for (int jt = 0; jt < njt; jt++) {
        const uint32_t stg = base + (jt & 1) * FA_STG_SZ;

        __syncthreads();
        if (jt + 1 < njt) {
            fa_load_kv(base + ((jt + 1) & 1) * FA_STG_SZ,
                       Khp, Klp, Vhp, Vlp,
                       (size_t)b * SEQ + (jt + 1) * 64, (jt + 1) * 64, tid);
        }
        CP_COMMIT();
        CP_WAIT1();
        __syncthreads();

        // ---- S = Q @ K^T (base-2 scaled) ----
        float sa[8][4];
        #pragma unroll
        for (int f = 0; f < 8; f++)
            #pragma unroll
            for (int j = 0; j < 4; j++) sa[f][j] = 0.f;

        #pragma unroll
        for (int kc = 0; kc < 4; kc++) {
            #pragma unroll
            for (int g = 0; g < 4; g++) {
                uint32_t kh4[4], kl4[4];
                ldsm4(kh4, stg + (b_n + g * 16) * QSTR + kc * 32 + b_kh * 16);
                ldsm4(kl4, stg + 9216 + (b_n + g * 16) * QSTR + kc * 32 + b_kh * 16);
                mma_bf16(sa[2 * g],     qh[kc], &kh4[0]);
                mma_bf16(sa[2 * g + 1], qh[kc], &kh4[2]);
                mma_bf16(sa[2 * g],     ql[kc], &kh4[0]);
                mma_bf16(sa[2 * g + 1], ql[kc], &kh4[2]);
                mma_bf16(sa[2 * g],     qh[kc], &kl4[0]);
                mma_bf16(sa[2 * g + 1], qh[kc], &kl4[2]);
            }
        }

        // ---- causal mask ----
        if (jt * 64 + 63 > qt * 128) {
            int r0g = qt * 128 + wm + (lane >> 2);
            int r1g = r0g + 8;
            #pragma unroll
            for (int f = 0; f < 8; f++) {
                int c0 = jt * 64 + f * 8 + (lane & 3) * 2;
                if (c0 > r0g)     sa[f][0] = -INFINITY;
                if (c0 + 1 > r0g) sa[f][1] = -INFINITY;
                if (c0 > r1g)     sa[f][2] = -INFINITY;
                if (c0 + 1 > r1g) sa[f][3] = -INFINITY;
            }
        }

        // ---- online softmax (base 2) ----
        float rm0 = -INFINITY, rm1 = -INFINITY;
        #pragma unroll
        for (int f = 0; f < 8; f++) {
            rm0 = fmaxf(rm0, fmaxf(sa[f][0], sa[f][1]));
            rm1 = fmaxf(rm1, fmaxf(sa[f][2], sa[f][3]));
        }
        rm0 = fmaxf(rm0, __shfl_xor_sync(0xffffffffu, rm0, 1));
        rm0 = fmaxf(rm0, __shfl_xor_sync(0xffffffffu, rm0, 2));
        rm1 = fmaxf(rm1, __shfl_xor_sync(0xffffffffu, rm1, 1));
        rm1 = fmaxf(rm1, __shfl_xor_sync(0xffffffffu, rm1, 2));

        float mn0 = fmaxf(m0, rm0), mn1 = fmaxf(m1, rm1);
        float f0 = exp2f(m0 - mn0), f1 = exp2f(m1 - mn1);
        float rs0 = 0.f, rs1 = 0.f;
        #pragma unroll
        for (int f = 0; f < 8; f++) {
            sa[f][0] = exp2f(sa[f][0] - mn0);
            sa[f][1] = exp2f(sa[f][1] - mn0);
            sa[f][2] = exp2f(sa[f][2] - mn1);
            sa[f][3] = exp2f(sa[f][3] - mn1);
            rs0 += sa[f][0] + sa[f][1];
            rs1 += sa[f][2] + sa[f][3];
        }
        rs0 += __shfl_xor_sync(0xffffffffu, rs0, 1);
        rs0 += __shfl_xor_sync(0xffffffffu, rs0, 2);
        rs1 += __shfl_xor_sync(0xffffffffu, rs1, 1);
        rs1 += __shfl_xor_sync(0xffffffffu, rs1, 2);

        l0 = l0 * f0 + rs0;  m0 = mn0;
        l1 = l1 * f1 + rs1;  m1 = mn1;
        #pragma unroll
        for (int f = 0; f < 8; f++) {
            oa[f][0] *= f0; oa[f][1] *= f0;
            oa[f][2] *= f1; oa[f][3] *= f1;
        }

        // ---- O += P @ V ----
        #pragma unroll
        for (int kc = 0; kc < 4; kc++) {
            uint32_t ah[4], al[4];
            split2(sa[2 * kc][0],     sa[2 * kc][1],     ah[0], al[0]);
            split2(sa[2 * kc][2],     sa[2 * kc][3],     ah[1], al[1]);
            split2(sa[2 * kc + 1][0], sa[2 * kc + 1][1], ah[2], al[2]);
            split2(sa[2 * kc + 1][2], sa[2 * kc + 1][3], ah[3], al[3]);
            #pragma unroll
            for (int g = 0; g < 4; g++) {
                uint32_t vh4[4], vl4[4];
                ldsm4(vh4, stg + 18432 + (b_n + g * 16) * QSTR + kc * 32 + b_kh * 16);
                ldsm4(vl4, stg + 27648 + (b_n + g * 16) * QSTR + kc * 32 + b_kh * 16);
                mma_bf16(oa[2 * g],     ah, &vh4[0]);
                mma_bf16(oa[2 * g + 1], ah, &vh4[2]);
                mma_bf16(oa[2 * g],     al, &vh4[0]);
                mma_bf16(oa[2 * g + 1], al, &vh4[2]);
                mma_bf16(oa[2 * g],     ah, &vl4[0]);
                mma_bf16(oa[2 * g + 1], ah, &vl4[2]);
            }
        }
    }

    // ---- epilogue: normalize, split, write Yh/Yl ----
    float inv0 = 1.f / l0, inv1 = 1.f / l1;
    size_t row0 = (size_t)(b * SEQ + qt * 128 + wm + (lane >> 2));
    #pragma unroll
    for (int f = 0; f < 8; f++) {
        int col = h * HD + f * 8 + (lane & 3) * 2;
        uint32_t hp, lp;
        split2(oa[f][0] * inv0, oa[f][1] * inv0, hp, lp);
        *(uint32_t*)&Yh[row0 * (NH * HD) + col] = hp;
        *(uint32_t*)&Yl[row0 * (NH * HD) + col] = lp;
        split2(oa[f][2] * inv1, oa[f][3] * inv1, hp, lp);
        *(uint32_t*)&Yh[(row0 + 8) * (NH * HD) + col] = hp;
        *(uint32_t*)&Yl[(row0 + 8) * (NH * HD) + col] = lp;
    }
}

// ---------------------------------------------------------------------------
extern "C" void kernel_launch(void* const* d_in, const int* in_sizes, int n_in,
                              void* d_out, int out_size) {
    const float* x  = (const float*)d_in[0];
    const float* Wq = (const float*)d_in[1];
    const float* Wk = (const float*)d_in[2];
    const float* Wv = (const float*)d_in[3];
    const float* Wo = (const float*)d_in[4];
    float* out = (float*)d_out;

    bf16 *xh, *xl, *Qh, *Ql, *Kh, *Kl, *Vth, *Vtl, *Yh, *Yl;
    bf16 *Wqh, *Wql, *Wkh, *Wkl, *Wvh, *Wvl, *Woh, *Wol;
    cudaGetSymbolAddress((void**)&xh, g_xh);   cudaGetSymbolAddress((void**)&xl, g_xl);
    cudaGetSymbolAddress((void**)&Qh, g_Qh);   cudaGetSymbolAddress((void**)&Ql, g_Ql);
    cudaGetSymbolAddress((void**)&Kh, g_Kh);   cudaGetSymbolAddress((void**)&Kl, g_Kl);
    cudaGetSymbolAddress((void**)&Vth, g_Vth); cudaGetSymbolAddress((void**)&Vtl, g_Vtl);
    cudaGetSymbolAddress((void**)&Yh, g_Yh);   cudaGetSymbolAddress((void**)&Yl, g_Yl);
    cudaGetSymbolAddress((void**)&Wqh, g_Wqt_h); cudaGetSymbolAddress((void**)&Wql, g_Wqt_l);
    cudaGetSymbolAddress((void**)&Wkh, g_Wkt_h); cudaGetSymbolAddress((void**)&Wkl, g_Wkt_l);
    cudaGetSymbolAddress((void**)&Wvh, g_Wvt_h); cudaGetSymbolAddress((void**)&Wvl, g_Wvt_l);
    cudaGetSymbolAddress((void**)&Woh, g_Wot_h); cudaGetSymbolAddress((void**)&Wol, g_Wot_l);

    dim3 blk(256);
    const float QSC = 0.125f * 1.4426950408889634f;   // 1/sqrt(64) * log2(e)

    // (1) rope table
    rope_table<<<(SEQ * 32 + 255) / 256, blk>>>();
    // (2) split x
    int totx = ROWS * MODEL;
    split_rows<<<(totx + 255) / 256, blk>>>(x, xh, xl, totx);
    // (3) all weight transposes
    ts_all<<<dim3(64, 64, 4), blk>>>(Wq, Wk, Wv, Wo);

    cudaFuncSetAttribute(gemm_mma, cudaFuncAttributeMaxDynamicSharedMemorySize, GEMM_SMEM);
    cudaFuncSetAttribute(gemm_mma_rope, cudaFuncAttributeMaxDynamicSharedMemorySize, GEMM_SMEM);
    cudaFuncSetAttribute(gemm_mma_kv, cudaFuncAttributeMaxDynamicSharedMemorySize, GEMM_SMEM);

    // (4) Q projection with fused rope+scale+split epilogue
    gemm_mma_rope<<<dim3((NH * HD) / 128, ROWS / 128), blk, GEMM_SMEM>>>(
        xh, xl, Wqh, Wql, Qh, Ql, QSC, NH * HD, MODEL);
    // (5) K (rope+split) and V (transpose+split) projections in one launch
    gemm_mma_kv<<<dim3(KVW / 128, ROWS / 128, 2), blk, GEMM_SMEM>>>(
        xh, xl, Wkh, Wkl, Wvh, Wvl, Kh, Kl, Vth, Vtl, KVW, MODEL);

    // (6) flash attention  [PROFILED SLOT]
    cudaFuncSetAttribute(flashattn_mma, cudaFuncAttributeMaxDynamicSharedMemorySize, FA_SMEM);
    flashattn_mma<<<dim3(SEQ / 128, NH, BATCH), blk, FA_SMEM>>>(
        Qh, Ql, Kh, Kl, Vth, Vtl, Yh, Yl);

    // (7) output projection
    gemm_mma<<<dim3(MODEL / 128, ROWS / 128), blk, GEMM_SMEM>>>(
        Yh, Yl, Woh, Wol, out, MODEL, MODEL);
}

// round 11
// speedup vs baseline: 3.2920x; 1.0723x over previous
#include <cuda_runtime.h>
#include <cuda_bf16.h>
#include <math.h>
#include <stdint.h>

#define BATCH 2
#define SEQ   2048
#define MODEL 2048
#define NH    32
#define NKV   8
#define HD    64
#define ROWS  (BATCH*SEQ)   // 4096
#define KVW   (NKV*HD)      // 512

typedef unsigned long long u64;
typedef __nv_bfloat16 bf16;

// ---------------- mma.sync helpers -----------------------------------------
__device__ __forceinline__ uint32_t smem_u32(const void* p) {
    uint32_t a;
    asm("{ .reg .u64 t; cvta.to.shared.u64 t, %1; cvt.u32.u64 %0, t; }" : "=r"(a) : "l"(p));
    return a;
}
__device__ __forceinline__ void ldsm4(uint32_t* r, uint32_t addr) {
    asm volatile("ldmatrix.sync.aligned.m8n8.x4.shared.b16 {%0,%1,%2,%3}, [%4];"
                 : "=r"(r[0]), "=r"(r[1]), "=r"(r[2]), "=r"(r[3]) : "r"(addr));
}
__device__ __forceinline__ void mma_bf16(float* d, const uint32_t* a, const uint32_t* b) {
    asm volatile("mma.sync.aligned.m16n8k16.row.col.f32.bf16.bf16.f32 "
                 "{%0,%1,%2,%3}, {%4,%5,%6,%7}, {%8,%9}, {%0,%1,%2,%3};"
                 : "+f"(d[0]), "+f"(d[1]), "+f"(d[2]), "+f"(d[3])
                 : "r"(a[0]), "r"(a[1]), "r"(a[2]), "r"(a[3]), "r"(b[0]), "r"(b[1]));
}
__device__ __forceinline__ void cp16(uint32_t dst, const void* src) {
    asm volatile("cp.async.cg.shared.global [%0], [%1], 16;" :: "r"(dst), "l"(src));
}
#define CP_COMMIT() asm volatile("cp.async.commit_group;" ::: "memory")
#define CP_WAIT1()  asm volatile("cp.async.wait_group 1;" ::: "memory")

// bf16x2 pack/split: lo float -> bits[15:0], hi float -> bits[31:16]
__device__ __forceinline__ uint32_t pkbf2(float lo, float hi) {
    uint32_t r; asm("cvt.rn.bf16x2.f32 %0, %1, %2;" : "=r"(r) : "f"(hi), "f"(lo)); return r;
}
__device__ __forceinline__ float bflo(uint32_t p) { return __uint_as_float(p << 16); }
__device__ __forceinline__ float bfhi(uint32_t p) { return __uint_as_float(p & 0xffff0000u); }
__device__ __forceinline__ void split2(float f0, float f1, uint32_t& hp, uint32_t& lp) {
    hp = pkbf2(f0, f1);
    lp = pkbf2(f0 - bflo(hp), f1 - bfhi(hp));
}

// ---------------- scratch --------------------------------------------------
__device__ float g_cs[(size_t)SEQ * 32 * 2];

__device__ bf16 g_xh[(size_t)ROWS * MODEL];
__device__ bf16 g_xl[(size_t)ROWS * MODEL];
__device__ bf16 g_Qh[(size_t)ROWS * NH * HD];
__device__ bf16 g_Ql[(size_t)ROWS * NH * HD];
__device__ bf16 g_Kh[(size_t)ROWS * KVW];
__device__ bf16 g_Kl[(size_t)ROWS * KVW];
__device__ bf16 g_Vth[(size_t)BATCH * KVW * SEQ];
__device__ bf16 g_Vtl[(size_t)BATCH * KVW * SEQ];
__device__ bf16 g_Yh[(size_t)ROWS * NH * HD];
__device__ bf16 g_Yl[(size_t)ROWS * NH * HD];
__device__ bf16 g_Wqt_h[(size_t)(NH  * HD) * MODEL];
__device__ bf16 g_Wqt_l[(size_t)(NH  * HD) * MODEL];
__device__ bf16 g_Wkt_h[(size_t)KVW * MODEL];
__device__ bf16 g_Wkt_l[(size_t)KVW * MODEL];
__device__ bf16 g_Wvt_h[(size_t)KVW * MODEL];
__device__ bf16 g_Wvt_l[(size_t)KVW * MODEL];
__device__ bf16 g_Wot_h[(size_t)MODEL * (NH * HD)];
__device__ bf16 g_Wot_l[(size_t)MODEL * (NH * HD)];

// ---------------------------------------------------------------------------
// RoPE cos/sin table (fp64 trig once)
// ---------------------------------------------------------------------------
__global__ __launch_bounds__(256)
void rope_table() {
    int i = blockIdx.x * 256 + threadIdx.x;
    if (i >= SEQ * 32) return;
    int d = i & 31;
    int s = i >> 5;
    double inv = exp2(-(double)d * (13.287712379549448882 / 32.0));
    double ang = (double)s * inv;
    double sd, cd;
    sincos(ang, &sd, &cd);
    g_cs[2 * i + 0] = (float)cd;
    g_cs[2 * i + 1] = (float)sd;
}

// ---------------------------------------------------------------------------
// split fp32 -> (hi, lo) bf16  (x only)
// ---------------------------------------------------------------------------
__global__ __launch_bounds__(256)
void split_rows(const float* __restrict__ X, bf16* __restrict__ H,
                bf16* __restrict__ L, int total) {
    int i = blockIdx.x * 256 + threadIdx.x;
    if (i >= total) return;
    float v = X[i];
    bf16 h = __float2bfloat16(v);
    H[i] = h;
    L[i] = __float2bfloat16(v - __bfloat162float(h));
}

// ---------------------------------------------------------------------------
// ALL weight transposes in one launch: z=0 Wq, 1 Wo, 2 Wk, 3 Wv
// ---------------------------------------------------------------------------
__global__ __launch_bounds__(256)
void ts_all(const float* __restrict__ Wq, const float* __restrict__ Wk,
            const float* __restrict__ Wv, const float* __restrict__ Wo) {
    __shared__ float tile[32][33];
    const float* W; bf16 *Th, *Tl; int Kd, Nw, nx;
    switch (blockIdx.z) {
        case 0:  W = Wq; Th = g_Wqt_h; Tl = g_Wqt_l; Kd = MODEL;   Nw = NH * HD; nx = 64; break;
        case 1:  W = Wo; Th = g_Wot_h; Tl = g_Wot_l; Kd = NH * HD; Nw = MODEL;   nx = 64; break;
        case 2:  W = Wk; Th = g_Wkt_h; Tl = g_Wkt_l; Kd = MODEL;   Nw = KVW;     nx = 16; break;
        default: W = Wv; Th = g_Wvt_h; Tl = g_Wvt_l; Kd = MODEL;   Nw = KVW;     nx = 16; break;
    }
    if ((int)blockIdx.x >= nx) return;
    int n0 = blockIdx.x * 32, k0 = blockIdx.y * 32;
    int tx = threadIdx.x & 31, ty = threadIdx.x >> 5;
    #pragma unroll
    for (int j = ty; j < 32; j += 8)
        tile[j][tx] = W[(size_t)(k0 + j) * Nw + n0 + tx];
    __syncthreads();
    #pragma unroll
    for (int j = ty; j < 32; j += 8) {
        float v = tile[tx][j];
        bf16 h = __float2bfloat16(v);
        Th[(size_t)(n0 + j) * Kd + k0 + tx] = h;
        Tl[(size_t)(n0 + j) * Kd + k0 + tx] = __float2bfloat16(v - __bfloat162float(h));
    }
}

// ---------------------------------------------------------------------------
// Split-bf16 tensor-core GEMM core — 128 threads, tile 64x128, 4 CTAs/SM.
// MODE 0: fp32 C.   MODE 1: rope+scale+split -> (Ch, Cl).
// MODE 2: V transpose+split -> [(b,kvh,d)][s].
// ---------------------------------------------------------------------------
#define GSTAGE 24576            // A 64x128B (8KB) + B 128x128B (16KB)
#define GEMM_SMEM (2 * GSTAGE)  // 49152

__device__ __forceinline__ void g_load_stage(uint32_t sbase,
                                             const bf16* Ah, const bf16* Al,
                                             const bf16* Bh, const bf16* Bl,
                                             int bm, int bn, int kb, int K, int tid) {
    #pragma unroll
    for (int it = 0; it < 4; it++) {          // A: 64 rows x 8 chunks = 512
        int idx = tid + it * 128;
        int r = idx >> 3, c = idx & 7;
        uint32_t dst = sbase + r * 128 + ((c ^ (r & 7)) << 4);
        const bf16* src = (c < 4 ? Ah : Al) + (size_t)(bm + r) * K + kb * 32 + (c & 3) * 8;
        cp16(dst, src);
    }
    #pragma unroll
    for (int it = 0; it < 8; it++) {          // B: 128 rows x 8 chunks = 1024
        int idx = tid + it * 128;
        int r = idx >> 3, c = idx & 7;
        uint32_t dst = sbase + 8192 + r * 128 + ((c ^ (r & 7)) << 4);
        const bf16* src = (c < 4 ? Bh : Bl) + (size_t)(bn + r) * K + kb * 32 + (c & 3) * 8;
        cp16(dst, src);
    }
}

template<int MODE>
__device__ __forceinline__
void gemm_mma_core(const bf16* __restrict__ Ah, const bf16* __restrict__ Al,
                   const bf16* __restrict__ Bh, const bf16* __restrict__ Bl,
                   float* __restrict__ C, bf16* __restrict__ Ch,
                   bf16* __restrict__ Cl, float rscale,
                   int Nt, int K, int bm, int bn) {
    extern __shared__ char smg[];
    const uint32_t sbase = smem_u32(smg);
    const int tid  = threadIdx.x;
    const int lane = tid & 31;
    const int warp = tid >> 5;            // 0..3
    const int wm   = (warp & 1) * 32;
    const int wn   = (warp >> 1) * 64;

    float acc[2][8][4];
    #pragma unroll
    for (int am = 0; am < 2; am++)
        #pragma unroll
        for (int an = 0; an < 8; an++)
            #pragma unroll
            for (int j = 0; j < 4; j++) acc[am][an][j] = 0.f;

    const int KB = K >> 5;
    g_load_stage(sbase,          Ah, Al, Bh, Bl, bm, bn, 0, K, tid); CP_COMMIT();
    g_load_stage(sbase + GSTAGE, Ah, Al, Bh, Bl, bm, bn, 1, K, tid); CP_COMMIT();

    const int a_row  = wm + (lane & 15);
    const int a_kh   = (lane >> 4) & 1;
    const int b_n    = wn + (lane & 7) + ((lane >> 4) << 3);
    const int b_kh   = (lane >> 3) & 1;

    for (int t = 0; t < KB; t++) {
        CP_WAIT1();
        __syncthreads();
        const uint32_t sA = sbase + (t & 1) * GSTAGE;
        const uint32_t sB = sA + 8192;

        #pragma unroll
        for (int h = 0; h < 2; h++) {
            uint32_t bh[4][4], bl[4][4];
            #pragma unroll
            for (int g = 0; g < 4; g++) {
                int n = b_n + g * 16;
                int ch = h * 2 + b_kh;
                ldsm4(bh[g], sB + n * 128 + (((ch)     ^ (n & 7)) << 4));
                ldsm4(bl[g], sB + n * 128 + (((ch + 4) ^ (n & 7)) << 4));
            }
            #pragma unroll
            for (int am = 0; am < 2; am++) {
                int r  = a_row + am * 16;
                int ch = h * 2 + a_kh;
                uint32_t ah[4], al[4];
                ldsm4(ah, sA + r * 128 + (((ch)     ^ (r & 7)) << 4));
                ldsm4(al, sA + r * 128 + (((ch + 4) ^ (r & 7)) << 4));
                #pragma unroll
                for (int g = 0; g < 4; g++) {
                    mma_bf16(acc[am][2 * g],     ah, &bh[g][0]);
                    mma_bf16(acc[am][2 * g + 1], ah, &bh[g][2]);
                }
                #pragma unroll
                for (int g = 0; g < 4; g++) {
                    mma_bf16(acc[am][2 * g],     al, &bh[g][0]);
                    mma_bf16(acc[am][2 * g + 1], al, &bh[g][2]);
                }
                #pragma unroll
                for (int g = 0; g < 4; g++) {
                    mma_bf16(acc[am][2 * g],     ah, &bl[g][0]);
                    mma_bf16(acc[am][2 * g + 1], ah, &bl[g][2]);
                }
            }
        }
        __syncthreads();
        if (t + 2 < KB) {
            g_load_stage(sA, Ah, Al, Bh, Bl, bm, bn, t + 2, K, tid);
        }
        CP_COMMIT();
    }

    if (MODE == 0) {
        #pragma unroll
        for (int am = 0; am < 2; am++) {
            int r0 = bm + wm + am * 16 + (lane >> 2);
            #pragma unroll
            for (int an = 0; an < 8; an++) {
                int col = bn + wn + an * 8 + (lane & 3) * 2;
                *(float2*)&C[(size_t)r0 * Nt + col]       = make_float2(acc[am][an][0], acc[am][an][1]);
                *(float2*)&C[(size_t)(r0 + 8) * Nt + col] = make_float2(acc[am][an][2], acc[am][an][3]);
            }
        }
    } else if (MODE == 1) {
        // rope + scale + split epilogue. d (col&31) pairs with d+32 = an+4.
        #pragma unroll
        for (int am = 0; am < 2; am++) {
            int r0 = bm + wm + am * 16 + (lane >> 2);
            #pragma unroll
            for (int rh = 0; rh < 2; rh++) {
                int row = r0 + rh * 8;
                int s   = row & (SEQ - 1);
                #pragma unroll
                for (int an = 0; an < 4; an++) {
                    int col = bn + wn + an * 8 + (lane & 3) * 2;
                    int d0  = col & 31;
                    float2 cs0 = *(const float2*)&g_cs[2 * (s * 32 + d0)];
                    float2 cs1 = *(const float2*)&g_cs[2 * (s * 32 + d0 + 1)];
                    float v0a = acc[am][an][rh * 2],     v0b = acc[am][an][rh * 2 + 1];
                    float v1a = acc[am][an + 4][rh * 2], v1b = acc[am][an + 4][rh * 2 + 1];
                    float loa = (v0a * cs0.x - v1a * cs0.y) * rscale;
                    float lob = (v0b * cs1.x - v1b * cs1.y) * rscale;
                    float hia = (v1a * cs0.x + v0a * cs0.y) * rscale;
                    float hib = (v1b * cs1.x + v0b * cs1.y) * rscale;
                    uint32_t hp, lp;
                    split2(loa, lob, hp, lp);
                    *(uint32_t*)&Ch[(size_t)row * Nt + col] = hp;
                    *(uint32_t*)&Cl[(size_t)row * Nt + col] = lp;
                    split2(hia, hib, hp, lp);
                    *(uint32_t*)&Ch[(size_t)row * Nt + col + 32] = hp;
                    *(uint32_t*)&Cl[(size_t)row * Nt + col + 32] = lp;
                }
            }
        }
    } else {
        // V transpose + split epilogue: out[(b*NKV + c>>6)*64 + (c&63)][s]
        #pragma unroll
        for (int am = 0; am < 2; am++) {
            int r0 = bm + wm + am * 16 + (lane >> 2);
            #pragma unroll
            for (int rh = 0; rh < 2; rh++) {
                int row = r0 + rh * 8;
                int bb  = row >> 11;
                int sl  = row & (SEQ - 1);
                #pragma unroll
                for (int an = 0; an < 8; an++) {
                    int col = bn + wn + an * 8 + (lane & 3) * 2;
                    float va = acc[am][an][rh * 2];
                    float vb = acc[am][an][rh * 2 + 1];
                    size_t o0 = ((size_t)(bb * NKV + (col >> 6)) * 64 + (col & 63)) * SEQ + sl;
                    size_t o1 = o0 + SEQ;
                    bf16 ha = __float2bfloat16(va);
                    Ch[o0] = ha;
                    Cl[o0] = __float2bfloat16(va - __bfloat162float(ha));
                    bf16 hb = __float2bfloat16(vb);
                    Ch[o1] = hb;
                    Cl[o1] = __float2bfloat16(vb - __bfloat162float(hb));
                }
            }
        }
    }
}

__global__ __launch_bounds__(128, 4)
void gemm_mma(const bf16* __restrict__ Ah, const bf16* __restrict__ Al,
              const bf16* __restrict__ Bh, const bf16* __restrict__ Bl,
              float* __restrict__ C, int Nt, int K) {
    gemm_mma_core<0>(Ah, Al, Bh, Bl, C, nullptr, nullptr, 0.f,
                     Nt, K, blockIdx.y * 64, blockIdx.x * 128);
}

__global__ __launch_bounds__(128, 4)
void gemm_mma_rope(const bf16* __restrict__ Ah, const bf16* __restrict__ Al,
                   const bf16* __restrict__ Bh, const bf16* __restrict__ Bl,
                   bf16* __restrict__ Ch, bf16* __restrict__ Cl,
                   float rscale, int Nt, int K) {
    gemm_mma_core<1>(Ah, Al, Bh, Bl, nullptr, Ch, Cl, rscale,
                     Nt, K, blockIdx.y * 64, blockIdx.x * 128);
}

// K (z=0, rope+split) and V (z=1, transpose+split) in one launch
__global__ __launch_bounds__(128, 4)
void gemm_mma_kv(const bf16* __restrict__ Ah, const bf16* __restrict__ Al,
                 const bf16* __restrict__ Bkh, const bf16* __restrict__ Bkl,
                 const bf16* __restrict__ Bvh, const bf16* __restrict__ Bvl,
                 bf16* __restrict__ Kh, bf16* __restrict__ Kl,
                 bf16* __restrict__ Vth, bf16* __restrict__ Vtl, int Nt, int K) {
    if (blockIdx.z == 0)
        gemm_mma_core<1>(Ah, Al, Bkh, Bkl, nullptr, Kh, Kl, 1.0f,
                         Nt, K, blockIdx.y * 64, blockIdx.x * 128);
    else
        gemm_mma_core<2>(Ah, Al, Bvh, Bvl, nullptr, Vth, Vtl, 0.f,
                         Nt, K, blockIdx.y * 64, blockIdx.x * 128);
}

// ---------------------------------------------------------------------------
// Tensor-core flash attention (unchanged)
// ---------------------------------------------------------------------------
#define QSTR 144
#define FA_STG_SZ 36864
#define FA_SQH 36864
#define FA_SQL 55296
#define FA_SMEM 73728

__device__ __forceinline__
void fa_load_kv(uint32_t sb, const bf16* __restrict__ Khp, const bf16* __restrict__ Klp,
                const bf16* __restrict__ Vhp, const bf16* __restrict__ Vlp,
                size_t krow0, int s0, int tid) {
    #pragma unroll
    for (int i = 0; i < 2; i++) {
        int idx = tid + i * 256;
        int r = idx >> 3, c = idx & 7;
        uint32_t so = r * QSTR + c * 16;
        cp16(sb + so,         Khp + (krow0 + r) * KVW + c * 8);
        cp16(sb + 9216 + so,  Klp + (krow0 + r) * KVW + c * 8);
        cp16(sb + 18432 + so, Vhp + (size_t)r * SEQ + s0 + c * 8);
        cp16(sb + 27648 + so, Vlp + (size_t)r * SEQ + s0 + c * 8);
    }
}

__global__ __launch_bounds__(256, 2)
void flashattn_mma(const bf16* __restrict__ Qh, const bf16* __restrict__ Ql,
                   const bf16* __restrict__ Kh, const bf16* __restrict__ Kl,
                   const bf16* __restrict__ Vth, const bf16* __restrict__ Vtl,
                   bf16* __restrict__ Yh, bf16* __restrict__ Yl) {
    extern __shared__ char sm[];
    const uint32_t base = smem_u32(sm);
    const int tid  = threadIdx.x;
    const int lane = tid & 31;
    const int warp = tid >> 5;
    const int qt   = gridDim.x - 1 - blockIdx.x;
    const int h    = blockIdx.y;
    const int b    = blockIdx.z;
    const int kvh  = h >> 2;
    const int wm   = warp * 16;

    const bf16* Khp = Kh + kvh * 64;
    const bf16* Klp = Kl + kvh * 64;
    const bf16* Vhp = Vth + (size_t)((b * NKV + kvh) * 64) * SEQ;
    const bf16* Vlp = Vtl + (size_t)((b * NKV + kvh) * 64) * SEQ;
    const int njt = 2 * qt + 2;

    // ---- Q cp.async into stage-1 footprint (group 0, waited first) ----
    {
        size_t qrow0 = (size_t)(b * SEQ + qt * 128);
        int hoff = h * HD;
        #pragma unroll
        for (int i = 0; i < 4; i++) {
            int idx = tid + i * 256;
            int r = idx >> 3, c = idx & 7;
            cp16(base + FA_SQH + r * QSTR + c * 16, Qh + (qrow0 + r) * (NH * HD) + hoff + c * 8);
            cp16(base + FA_SQL + r * QSTR + c * 16, Ql + (qrow0 + r) * (NH * HD) + hoff + c * 8);
        }
    }
    CP_COMMIT();

    fa_load_kv(base, Khp, Klp, Vhp, Vlp, (size_t)b * SEQ, 0, tid);
    CP_COMMIT();

    CP_WAIT1();
    __syncthreads();

    const int a_row = wm + (lane & 15);
    const int a_kh  = (lane >> 4) & 1;
    uint32_t qh[4][4], ql[4][4];
    #pragma unroll
    for (int kc = 0; kc < 4; kc++) {
        ldsm4(qh[kc], base + FA_SQH + a_row * QSTR + kc * 32 + a_kh * 16);
        ldsm4(ql[kc], base + FA_SQL + a_row * QSTR + kc * 32 + a_kh * 16);
    }

    const int b_n  = (lane & 7) + ((lane >> 4) << 3);
    const int b_kh = (lane >> 3) & 1;

    float m0 = -INFINITY, m1 = -INFINITY, l0 = 0.f, l1 = 0.f;
    float oa[8][4];
    #pragma unroll
    for (int f = 0; f < 8; f++)
        #pragma unroll
        for (int j = 0; j < 4; j++) oa[f][j] = 0.f;

    for (int jt = 0; jt < njt; jt++) {
        const uint32_t stg = base + (jt & 1) * FA_STG_SZ;

        __syncthreads();
        if (jt + 1 < njt) {
            fa_load_kv(base + ((jt + 1) & 1) * FA_STG_SZ,
                       Khp, Klp, Vhp, Vlp,
                       (size_t)b * SEQ + (jt + 1) * 64, (jt + 1) * 64, tid);
        }
        CP_COMMIT();
        CP_WAIT1();
        __syncthreads();

        float sa[8][4];
        #pragma unroll
        for (int f = 0; f < 8; f++)
            #pragma unroll
            for (int j = 0; j < 4; j++) sa[f][j] = 0.f;

        #pragma unroll
        for (int kc = 0; kc < 4; kc++) {
            #pragma unroll
            for (int g = 0; g < 4; g++) {
                uint32_t kh4[4], kl4[4];
                ldsm4(kh4, stg + (b_n + g * 16) * QSTR + kc * 32 + b_kh * 16);
                ldsm4(kl4, stg + 9216 + (b_n + g * 16) * QSTR + kc * 32 + b_kh * 16);
                mma_bf16(sa[2 * g],     qh[kc], &kh4[0]);
                mma_bf16(sa[2 * g + 1], qh[kc], &kh4[2]);
                mma_bf16(sa[2 * g],     ql[kc], &kh4[0]);
                mma_bf16(sa[2 * g + 1], ql[kc], &kh4[2]);
                mma_bf16(sa[2 * g],     qh[kc], &kl4[0]);
                mma_bf16(sa[2 * g + 1], qh[kc], &kl4[2]);
            }
        }

        if (jt * 64 + 63 > qt * 128) {
            int r0g = qt * 128 + wm + (lane >> 2);
            int r1g = r0g + 8;
            #pragma unroll
            for (int f = 0; f < 8; f++) {
                int c0 = jt * 64 + f * 8 + (lane & 3) * 2;
                if (c0 > r0g)     sa[f][0] = -INFINITY;
                if (c0 + 1 > r0g) sa[f][1] = -INFINITY;
                if (c0 > r1g)     sa[f][2] = -INFINITY;
                if (c0 + 1 > r1g) sa[f][3] = -INFINITY;
            }
        }

        float rm0 = -INFINITY, rm1 = -INFINITY;
        #pragma unroll
        for (int f = 0; f < 8; f++) {
            rm0 = fmaxf(rm0, fmaxf(sa[f][0], sa[f][1]));
            rm1 = fmaxf(rm1, fmaxf(sa[f][2], sa[f][3]));
        }
        rm0 = fmaxf(rm0, __shfl_xor_sync(0xffffffffu, rm0, 1));
        rm0 = fmaxf(rm0, __shfl_xor_sync(0xffffffffu, rm0, 2));
        rm1 = fmaxf(rm1, __shfl_xor_sync(0xffffffffu, rm1, 1));
        rm1 = fmaxf(rm1, __shfl_xor_sync(0xffffffffu, rm1, 2));

        float mn0 = fmaxf(m0, rm0), mn1 = fmaxf(m1, rm1);
        float f0 = exp2f(m0 - mn0), f1 = exp2f(m1 - mn1);
        float rs0 = 0.f, rs1 = 0.f;
        #pragma unroll
        for (int f = 0; f < 8; f++) {
            sa[f][0] = exp2f(sa[f][0] - mn0);
            sa[f][1] = exp2f(sa[f][1] - mn0);
            sa[f][2] = exp2f(sa[f][2] - mn1);
            sa[f][3] = exp2f(sa[f][3] - mn1);
            rs0 += sa[f][0] + sa[f][1];
            rs1 += sa[f][2] + sa[f][3];
        }
        rs0 += __shfl_xor_sync(0xffffffffu, rs0, 1);
        rs0 += __shfl_xor_sync(0xffffffffu, rs0, 2);
        rs1 += __shfl_xor_sync(0xffffffffu, rs1, 1);
        rs1 += __shfl_xor_sync(0xffffffffu, rs1, 2);

        l0 = l0 * f0 + rs0;  m0 = mn0;
        l1 = l1 * f1 + rs1;  m1 = mn1;
        #pragma unroll
        for (int f = 0; f < 8; f++) {
            oa[f][0] *= f0; oa[f][1] *= f0;
            oa[f][2] *= f1; oa[f][3] *= f1;
        }

        #pragma unroll
        for (int kc = 0; kc < 4; kc++) {
            uint32_t ah[4], al[4];
            split2(sa[2 * kc][0],     sa[2 * kc][1],     ah[0], al[0]);
            split2(sa[2 * kc][2],     sa[2 * kc][3],     ah[1], al[1]);
            split2(sa[2 * kc + 1][0], sa[2 * kc + 1][1], ah[2], al[2]);
            split2(sa[2 * kc + 1][2], sa[2 * kc + 1][3], ah[3], al[3]);
            #pragma unroll
            for (int g = 0; g < 4; g++) {
                uint32_t vh4[4], vl4[4];
                ldsm4(vh4, stg + 18432 + (b_n + g * 16) * QSTR + kc * 32 + b_kh * 16);
                ldsm4(vl4, stg + 27648 + (b_n + g * 16) * QSTR + kc * 32 + b_kh * 16);
                mma_bf16(oa[2 * g],     ah, &vh4[0]);
                mma_bf16(oa[2 * g + 1], ah, &vh4[2]);
                mma_bf16(oa[2 * g],     al, &vh4[0]);
                mma_bf16(oa[2 * g + 1], al, &vh4[2]);
                mma_bf16(oa[2 * g],     ah, &vl4[0]);
                mma_bf16(oa[2 * g + 1], ah, &vl4[2]);
            }
        }
    }

    float inv0 = 1.f / l0, inv1 = 1.f / l1;
    size_t row0 = (size_t)(b * SEQ + qt * 128 + wm + (lane >> 2));
    #pragma unroll
    for (int f = 0; f < 8; f++) {
        int col = h * HD + f * 8 + (lane & 3) * 2;
        uint32_t hp, lp;
        split2(oa[f][0] * inv0, oa[f][1] * inv0, hp, lp);
        *(uint32_t*)&Yh[row0 * (NH * HD) + col] = hp;
        *(uint32_t*)&Yl[row0 * (NH * HD) + col] = lp;
        split2(oa[f][2] * inv1, oa[f][3] * inv1, hp, lp);
        *(uint32_t*)&Yh[(row0 + 8) * (NH * HD) + col] = hp;
        *(uint32_t*)&Yl[(row0 + 8) * (NH * HD) + col] = lp;
    }
}

// ---------------------------------------------------------------------------
extern "C" void kernel_launch(void* const* d_in, const int* in_sizes, int n_in,
                              void* d_out, int out_size) {
    const float* x  = (const float*)d_in[0];
    const float* Wq = (const float*)d_in[1];
    const float* Wk = (const float*)d_in[2];
    const float* Wv = (const float*)d_in[3];
    const float* Wo = (const float*)d_in[4];
    float* out = (float*)d_out;

    bf16 *xh, *xl, *Qh, *Ql, *Kh, *Kl, *Vth, *Vtl, *Yh, *Yl;
    bf16 *Wqh, *Wql, *Wkh, *Wkl, *Wvh, *Wvl, *Woh, *Wol;
    cudaGetSymbolAddress((void**)&xh, g_xh);   cudaGetSymbolAddress((void**)&xl, g_xl);
    cudaGetSymbolAddress((void**)&Qh, g_Qh);   cudaGetSymbolAddress((void**)&Ql, g_Ql);
    cudaGetSymbolAddress((void**)&Kh, g_Kh);   cudaGetSymbolAddress((void**)&Kl, g_Kl);
    cudaGetSymbolAddress((void**)&Vth, g_Vth); cudaGetSymbolAddress((void**)&Vtl, g_Vtl);
    cudaGetSymbolAddress((void**)&Yh, g_Yh);   cudaGetSymbolAddress((void**)&Yl, g_Yl);
    cudaGetSymbolAddress((void**)&Wqh, g_Wqt_h); cudaGetSymbolAddress((void**)&Wql, g_Wqt_l);
    cudaGetSymbolAddress((void**)&Wkh, g_Wkt_h); cudaGetSymbolAddress((void**)&Wkl, g_Wkt_l);
    cudaGetSymbolAddress((void**)&Wvh, g_Wvt_h); cudaGetSymbolAddress((void**)&Wvl, g_Wvt_l);
    cudaGetSymbolAddress((void**)&Woh, g_Wot_h); cudaGetSymbolAddress((void**)&Wol, g_Wot_l);

    dim3 blk(256);
    dim3 gblk(128);
    const float QSC = 0.125f * 1.4426950408889634f;   // 1/sqrt(64) * log2(e)

    rope_table<<<(SEQ * 32 + 255) / 256, blk>>>();
    int totx = ROWS * MODEL;
    split_rows<<<(totx + 255) / 256, blk>>>(x, xh, xl, totx);
    ts_all<<<dim3(64, 64, 4), blk>>>(Wq, Wk, Wv, Wo);

    cudaFuncSetAttribute(gemm_mma, cudaFuncAttributeMaxDynamicSharedMemorySize, GEMM_SMEM);
    cudaFuncSetAttribute(gemm_mma_rope, cudaFuncAttributeMaxDynamicSharedMemorySize, GEMM_SMEM);
    cudaFuncSetAttribute(gemm_mma_kv, cudaFuncAttributeMaxDynamicSharedMemorySize, GEMM_SMEM);

    // Q projection with fused rope+scale+split epilogue (64x128 tiles)
    gemm_mma_rope<<<dim3((NH * HD) / 128, ROWS / 64), gblk, GEMM_SMEM>>>(
        xh, xl, Wqh, Wql, Qh, Ql, QSC, NH * HD, MODEL);
    // K (rope+split) and V (transpose+split)
    gemm_mma_kv<<<dim3(KVW / 128, ROWS / 64, 2), gblk, GEMM_SMEM>>>(
        xh, xl, Wkh, Wkl, Wvh, Wvl, Kh, Kl, Vth, Vtl, KVW, MODEL);

    // flash attention
    cudaFuncSetAttribute(flashattn_mma, cudaFuncAttributeMaxDynamicSharedMemorySize, FA_SMEM);
    flashattn_mma<<<dim3(SEQ / 128, NH, BATCH), blk, FA_SMEM>>>(
        Qh, Ql, Kh, Kl, Vth, Vtl, Yh, Yl);

    // output projection
    gemm_mma<<<dim3(MODEL / 128, ROWS / 64), gblk, GEMM_SMEM>>>(
        Yh, Yl, Woh, Wol, out, MODEL, MODEL);
}